// round 2
// baseline (speedup 1.0000x reference)
#include <cuda_runtime.h>
#include <math.h>
#include <stdint.h>

#define Bn 32
#define Sn 100
#define Tn 100
#define En 512
#define Hn 1024
#define Vn 32000
#define Gn 4096   // 4*H

// ---------------- scratch (device globals; no allocation allowed) ----------------
__device__ float g_XWenc[Bn*Sn*Gn];
__device__ float g_XWdec[Bn*Tn*Gn];
__device__ float g_enc_out[Bn*Sn*Hn];
__device__ float g_enc_proj[Bn*Sn*Hn];
__device__ float g_hidden[Bn*Tn*Hn];
__device__ float g_h [Bn*Hn];
__device__ float g_c [Bn*Hn];
__device__ float g_hd[Bn*Hn];
__device__ float g_cd[Bn*Hn];
__device__ float g_feed [Bn*Hn];
__device__ float g_atten[Bn*Hn];
__device__ float g_scores[Bn*Sn];
__device__ float g_part[16*Bn*Gn];
__device__ float g_fp  [16*Bn*Hn];

// ---------------- f32x2 packed helpers (sm_103a) ----------------
__device__ __forceinline__ void fma2(unsigned long long& d, unsigned long long a, unsigned long long b) {
    asm("fma.rn.f32x2 %0, %1, %2, %0;" : "+l"(d) : "l"(a), "l"(b));
}
__device__ __forceinline__ unsigned long long dup2(float x) {
    unsigned long long r; unsigned u = __float_as_uint(x);
    asm("mov.b64 %0, {%1, %1};" : "=l"(r) : "r"(u));
    return r;
}
__device__ __forceinline__ float lo2(unsigned long long v){ return __uint_as_float((unsigned)v); }
__device__ __forceinline__ float hi2(unsigned long long v){ return __uint_as_float((unsigned)(v>>32)); }
__device__ __forceinline__ float sigm(float x){ return 1.0f/(1.0f + expf(-x)); }

// ---------------- big GEMM: C[M,N] = gather(A)[M,K] @ B[K,N] + bias ----------------
__global__ void __launch_bounds__(256)
sgemm_big(const float* __restrict__ A, const int* __restrict__ gather,
          const float* __restrict__ Bw, const float* __restrict__ bias,
          float* __restrict__ C, int N, int K)
{
    __shared__ float As[8][128];
    __shared__ float Bs[8][128];
    const int t  = threadIdx.x;
    const int tx = t & 15, ty = t >> 4;
    const int m0 = blockIdx.y * 128, n0 = blockIdx.x * 128;

    const int ar = t >> 1, ac = (t & 1) * 4;
    const int arow = gather ? gather[m0 + ar] : (m0 + ar);
    const float* Ap = A + (size_t)arow * K + ac;
    const int bk = t >> 5, bn = (t & 31) * 4;
    const float* Bp = Bw + (size_t)bk * N + n0 + bn;

    unsigned long long acc[8][4];
    #pragma unroll
    for (int i = 0; i < 8; i++)
        #pragma unroll
        for (int j = 0; j < 4; j++) acc[i][j] = 0ull;

    const int nIter = K >> 3;
    float4 aR = *(const float4*)Ap;
    float4 bR = *(const float4*)Bp;
    for (int kt = 0; kt < nIter; kt++) {
        As[ac+0][ar] = aR.x; As[ac+1][ar] = aR.y;
        As[ac+2][ar] = aR.z; As[ac+3][ar] = aR.w;
        *(float4*)&Bs[bk][bn] = bR;
        __syncthreads();
        if (kt + 1 < nIter) {
            aR = *(const float4*)(Ap + (kt+1)*8);
            bR = *(const float4*)(Bp + (size_t)(kt+1)*8*N);
        }
        #pragma unroll
        for (int kk = 0; kk < 8; kk++) {
            unsigned long long bb[4];
            const unsigned long long* bp = (const unsigned long long*)&Bs[kk][tx*8];
            bb[0]=bp[0]; bb[1]=bp[1]; bb[2]=bp[2]; bb[3]=bp[3];
            float a[8];
            *(float4*)&a[0] = *(const float4*)&As[kk][ty*8];
            *(float4*)&a[4] = *(const float4*)&As[kk][ty*8+4];
            #pragma unroll
            for (int i = 0; i < 8; i++) {
                unsigned long long aa = dup2(a[i]);
                fma2(acc[i][0], aa, bb[0]);
                fma2(acc[i][1], aa, bb[1]);
                fma2(acc[i][2], aa, bb[2]);
                fma2(acc[i][3], aa, bb[3]);
            }
        }
        __syncthreads();
    }
    #pragma unroll
    for (int i = 0; i < 8; i++) {
        const int m = m0 + ty*8 + i;
        float* Cr = C + (size_t)m * N + n0 + tx*8;
        #pragma unroll
        for (int j = 0; j < 4; j++) {
            const int n = n0 + tx*8 + j*2;
            float2 v;
            v.x = lo2(acc[i][j]) + bias[n];
            v.y = hi2(acc[i][j]) + bias[n+1];
            *(float2*)(Cr + j*2) = v;
        }
    }
}

// ---------------- small-M (32-row) GEMM, K-split partials ----------------
__global__ void __launch_bounds__(256)
small_part(const float* __restrict__ xA, const float* __restrict__ WA,
           const float* __restrict__ xB, const float* __restrict__ WB,
           int nA, int N, float* __restrict__ part)
{
    __shared__ float hs[32][36];    // [kk][b]
    __shared__ float ws[32][128];   // [kk][n]
    const int t  = threadIdx.x;
    const int n4 = (t & 31) * 4;
    const int bq = t >> 5;
    const int n0 = blockIdx.x * 128;
    const int ky = blockIdx.y;
    const float* x; const float* W;
    if (ky < nA) { x = xA + ky*128;      W = WA + (size_t)(ky*128) * N; }
    else         { x = xB + (ky-nA)*128; W = WB + (size_t)((ky-nA)*128) * N; }

    float acc[4][4];
    #pragma unroll
    for (int i = 0; i < 4; i++)
        #pragma unroll
        for (int j = 0; j < 4; j++) acc[i][j] = 0.0f;

    for (int ks = 0; ks < 4; ks++) {
        #pragma unroll
        for (int i = 0; i < 4; i++) {
            int lin = t + i*256;
            int b = lin >> 5, kk = lin & 31;
            hs[kk][b] = x[b*Hn + ks*32 + kk];
        }
        #pragma unroll
        for (int i = 0; i < 4; i++) {
            int lin = t + i*256;
            int kk = lin >> 5, nq = (lin & 31) * 4;
            *(float4*)&ws[kk][nq] = *(const float4*)(W + (size_t)(ks*32+kk)*N + n0 + nq);
        }
        __syncthreads();
        #pragma unroll
        for (int kk = 0; kk < 32; kk++) {
            float4 a = *(const float4*)&hs[kk][bq*4];
            float4 w = *(const float4*)&ws[kk][n4];
            acc[0][0]+=a.x*w.x; acc[0][1]+=a.x*w.y; acc[0][2]+=a.x*w.z; acc[0][3]+=a.x*w.w;
            acc[1][0]+=a.y*w.x; acc[1][1]+=a.y*w.y; acc[1][2]+=a.y*w.z; acc[1][3]+=a.y*w.w;
            acc[2][0]+=a.z*w.x; acc[2][1]+=a.z*w.y; acc[2][2]+=a.z*w.z; acc[2][3]+=a.z*w.w;
            acc[3][0]+=a.w*w.x; acc[3][1]+=a.w*w.y; acc[3][2]+=a.w*w.z; acc[3][3]+=a.w*w.w;
        }
        __syncthreads();
    }
    #pragma unroll
    for (int i = 0; i < 4; i++) {
        float4 v = make_float4(acc[i][0], acc[i][1], acc[i][2], acc[i][3]);
        *(float4*)(part + ((size_t)ky*Bn + bq*4 + i) * N + n0 + n4) = v;
    }
}

// ---------------- state / cells / attention ----------------
__global__ void zero_state() {
    int i = blockIdx.x*256 + threadIdx.x;
    g_h[i] = 0.0f; g_c[i] = 0.0f;
}

__global__ void init_dec() {
    int i = blockIdx.x*256 + threadIdx.x;
    float h = g_h[i], c = g_c[i];
    g_hd[i] = h; g_cd[i] = c; g_feed[i] = h;
}

__global__ void enc_cell(int t) {
    int idx = blockIdx.x*256 + threadIdx.x;
    int b = idx >> 10, j = idx & 1023;
    size_t xb = ((size_t)(b*Sn + t)) * Gn;
    float gi = g_XWenc[xb + j];
    float gf = g_XWenc[xb + j + 1024];
    float gg = g_XWenc[xb + j + 2048];
    float go = g_XWenc[xb + j + 3072];
    #pragma unroll
    for (int p = 0; p < 8; p++) {
        size_t pb = ((size_t)(p*Bn + b)) * Gn;
        gi += g_part[pb + j];
        gf += g_part[pb + j + 1024];
        gg += g_part[pb + j + 2048];
        go += g_part[pb + j + 3072];
    }
    float c = sigm(gf) * g_c[idx] + sigm(gi) * tanhf(gg);
    float h = sigm(go) * tanhf(c);
    g_c[idx] = c; g_h[idx] = h;
    g_enc_out[((size_t)(b*Sn + t)) * Hn + j] = h;
}

__global__ void dec_cell(int t) {
    int idx = blockIdx.x*256 + threadIdx.x;
    int b = idx >> 10, j = idx & 1023;
    size_t xb = ((size_t)(b*Tn + t)) * Gn;
    float gi = g_XWdec[xb + j];
    float gf = g_XWdec[xb + j + 1024];
    float gg = g_XWdec[xb + j + 2048];
    float go = g_XWdec[xb + j + 3072];
    #pragma unroll
    for (int p = 0; p < 16; p++) {
        size_t pb = ((size_t)(p*Bn + b)) * Gn;
        gi += g_part[pb + j];
        gf += g_part[pb + j + 1024];
        gg += g_part[pb + j + 2048];
        go += g_part[pb + j + 3072];
    }
    float c = sigm(gf) * g_cd[idx] + sigm(gi) * tanhf(gg);
    float h = sigm(go) * tanhf(c);
    g_cd[idx] = c; g_hd[idx] = h;
}

__global__ void att_scores() {
    int pair = blockIdx.x * 8 + (threadIdx.x >> 5);
    int lane = threadIdx.x & 31;
    int b = pair / Sn;
    const float* ep = g_enc_proj + (size_t)pair * Hn;
    const float* hv = g_hd + b * Hn;
    float acc = 0.0f;
    #pragma unroll 4
    for (int k = lane; k < Hn; k += 32) acc += ep[k] * hv[k];
    #pragma unroll
    for (int o = 16; o; o >>= 1) acc += __shfl_xor_sync(0xffffffffu, acc, o);
    if (lane == 0) g_scores[pair] = acc;
}

__global__ void att_softmax() {
    int b = threadIdx.x >> 5, lane = threadIdx.x & 31;
    float v[4];
    float mx = -1e30f;
    #pragma unroll
    for (int i = 0; i < 4; i++) {
        int s = lane + 32*i;
        v[i] = (s < Sn) ? g_scores[b*Sn + s] : -1e30f;
        mx = fmaxf(mx, v[i]);
    }
    #pragma unroll
    for (int o = 16; o; o >>= 1) mx = fmaxf(mx, __shfl_xor_sync(0xffffffffu, mx, o));
    float sum = 0.0f;
    #pragma unroll
    for (int i = 0; i < 4; i++) {
        int s = lane + 32*i;
        v[i] = (s < Sn) ? expf(v[i] - mx) : 0.0f;
        sum += v[i];
    }
    #pragma unroll
    for (int o = 16; o; o >>= 1) sum += __shfl_xor_sync(0xffffffffu, sum, o);
    float inv = 1.0f / sum;
    #pragma unroll
    for (int i = 0; i < 4; i++) {
        int s = lane + 32*i;
        if (s < Sn) g_scores[b*Sn + s] = v[i] * inv;
    }
}

__global__ void att_apply() {
    int idx = blockIdx.x*256 + threadIdx.x;
    int b = idx >> 10, j = idx & 1023;
    const float* w = g_scores + b * Sn;
    const float* eo = g_enc_out + ((size_t)b * Sn) * Hn + j;
    float acc = 0.0f;
    #pragma unroll 4
    for (int s = 0; s < Sn; s++) acc += w[s] * eo[(size_t)s * Hn];
    g_atten[idx] = acc;
}

__global__ void feed_reduce(int t, const float* __restrict__ cls1_b) {
    int idx = blockIdx.x*256 + threadIdx.x;
    int b = idx >> 10, j = idx & 1023;
    float acc = cls1_b[j];
    #pragma unroll
    for (int p = 0; p < 16; p++) acc += g_fp[((size_t)(p*Bn + b)) * Hn + j];
    float f = tanhf(acc);
    g_feed[idx] = f;
    g_hidden[((size_t)(b*Tn + t)) * Hn + j] = f;
}

extern "C" void kernel_launch(void* const* d_in, const int* in_sizes, int n_in,
                              void* d_out, int out_size)
{
    const int*   source_data = (const int*)  d_in[0];
    const int*   target_data = (const int*)  d_in[1];
    const float* src_emb  = (const float*)d_in[2];
    const float* tgt_emb  = (const float*)d_in[3];
    const float* enc_Wih  = (const float*)d_in[4];
    const float* enc_Whh  = (const float*)d_in[5];
    const float* enc_b    = (const float*)d_in[6];
    const float* dec_Wih  = (const float*)d_in[7];
    const float* dec_Whh  = (const float*)d_in[8];
    const float* dec_b    = (const float*)d_in[9];
    const float* att1_W   = (const float*)d_in[10];
    const float* att1_b   = (const float*)d_in[11];
    const float* cls1_W   = (const float*)d_in[12];
    const float* cls1_b   = (const float*)d_in[13];
    const float* cls2_W   = (const float*)d_in[14];
    const float* cls2_b   = (const float*)d_in[15];
    float* out = (float*)d_out;

    float *XWenc, *XWdec, *enc_out, *enc_proj, *hidden;
    float *hptr, *hdptr, *feedptr, *attenptr, *partptr, *fpptr;
    cudaGetSymbolAddress((void**)&XWenc,   g_XWenc);
    cudaGetSymbolAddress((void**)&XWdec,   g_XWdec);
    cudaGetSymbolAddress((void**)&enc_out, g_enc_out);
    cudaGetSymbolAddress((void**)&enc_proj,g_enc_proj);
    cudaGetSymbolAddress((void**)&hidden,  g_hidden);
    cudaGetSymbolAddress((void**)&hptr,    g_h);
    cudaGetSymbolAddress((void**)&hdptr,   g_hd);
    cudaGetSymbolAddress((void**)&feedptr, g_feed);
    cudaGetSymbolAddress((void**)&attenptr,g_atten);
    cudaGetSymbolAddress((void**)&partptr, g_part);
    cudaGetSymbolAddress((void**)&fpptr,   g_fp);

    zero_state<<<128, 256>>>();
    sgemm_big<<<dim3(Gn/128, 25), 256>>>(src_emb, source_data, enc_Wih, enc_b, XWenc, Gn, En);
    sgemm_big<<<dim3(Gn/128, 25), 256>>>(tgt_emb, target_data, dec_Wih, dec_b, XWdec, Gn, En);

    for (int t = 0; t < Sn; t++) {
        small_part<<<dim3(Gn/128, 8), 256>>>(hptr, enc_Whh, hptr, enc_Whh, 8, Gn, partptr);
        enc_cell<<<128, 256>>>(t);
    }
    sgemm_big<<<dim3(Hn/128, 25), 256>>>(enc_out, nullptr, att1_W, att1_b, enc_proj, Hn, Hn);
    init_dec<<<128, 256>>>();

    for (int t = 0; t < Tn; t++) {
        small_part<<<dim3(Gn/128, 16), 256>>>(feedptr, dec_Wih + (size_t)En*Gn,
                                              hdptr, dec_Whh, 8, Gn, partptr);
        dec_cell<<<128, 256>>>(t);
        att_scores<<<400, 256>>>();
        att_softmax<<<1, 1024>>>();
        att_apply<<<128, 256>>>();
        small_part<<<dim3(Hn/128, 16), 256>>>(attenptr, cls1_W,
                                              hdptr, cls1_W + (size_t)Hn*Hn, 8, Hn, fpptr);
        feed_reduce<<<128, 256>>>(t, cls1_b);
    }

    sgemm_big<<<dim3(Vn/128, 25), 256>>>(hidden, nullptr, cls2_W, cls2_b, out, Vn, Hn);
}

// round 3
// speedup vs baseline: 1.0618x; 1.0618x over previous
#include <cuda_runtime.h>
#include <cuda_bf16.h>
#include <math.h>
#include <stdint.h>

#define Bn 32
#define Sn 100
#define Tn 100
#define En 512
#define Hn 1024
#define Vn 32000
#define Gn 4096   // 4*H
#define AST 24    // smem row stride in bf16 (16 data + 8 pad -> conflict-free)

// ---------------- scratch (device globals; no allocation allowed) ----------------
__device__ float g_XWenc[Bn*Sn*Gn];
__device__ float g_XWdec[Bn*Tn*Gn];
__device__ float g_enc_out[Bn*Sn*Hn];
__device__ float g_enc_proj[Bn*Sn*Hn];
__device__ float g_hidden[Bn*Tn*Hn];
__device__ float g_h [Bn*Hn];
__device__ float g_c [Bn*Hn];
__device__ float g_hd[Bn*Hn];
__device__ float g_cd[Bn*Hn];
__device__ float g_feed [Bn*Hn];
__device__ float g_atten[Bn*Hn];
__device__ float g_part[8*Bn*Gn];
__device__ float g_fp  [8*Bn*Hn];

// transposed bf16 hi/lo packed weights: Bq[n][k], word = hi | (lo<<16)
__device__ unsigned g_wih_e [4096u*512];
__device__ unsigned g_wih_d0[4096u*512];
__device__ unsigned g_whh_e [4096u*1024];
__device__ unsigned g_wih_dH[4096u*1024];
__device__ unsigned g_whh_d [4096u*1024];
__device__ unsigned g_att1q [1024u*1024];
__device__ unsigned g_cls1q [1024u*2048];
__device__ unsigned g_cls2q [32000u*1024];

__device__ __forceinline__ float sigm(float x){ return 1.0f/(1.0f + expf(-x)); }

// pack fp32 -> (hi bf16 | lo bf16<<16)
__device__ __forceinline__ unsigned pack_hl(float x) {
    __nv_bfloat16 h = __float2bfloat16(x);
    __nv_bfloat16 l = __float2bfloat16(x - __bfloat162float(h));
    return (unsigned)__bfloat16_as_ushort(h) | ((unsigned)__bfloat16_as_ushort(l) << 16);
}
// split two fp32 (k even, k odd) into hi-pair and lo-pair words
__device__ __forceinline__ void split2(float x, float y, unsigned& hp, unsigned& lp) {
    __nv_bfloat16 hx = __float2bfloat16(x), hy = __float2bfloat16(y);
    __nv_bfloat16 lx = __float2bfloat16(x - __bfloat162float(hx));
    __nv_bfloat16 ly = __float2bfloat16(y - __bfloat162float(hy));
    hp = (unsigned)__bfloat16_as_ushort(hx) | ((unsigned)__bfloat16_as_ushort(hy) << 16);
    lp = (unsigned)__bfloat16_as_ushort(lx) | ((unsigned)__bfloat16_as_ushort(ly) << 16);
}

__device__ __forceinline__ void mma16816(float* c, const unsigned* a, unsigned b0, unsigned b1) {
    asm volatile("mma.sync.aligned.m16n8k16.row.col.f32.bf16.bf16.f32 "
        "{%0,%1,%2,%3},{%4,%5,%6,%7},{%8,%9},{%0,%1,%2,%3};"
        : "+f"(c[0]), "+f"(c[1]), "+f"(c[2]), "+f"(c[3])
        : "r"(a[0]), "r"(a[1]), "r"(a[2]), "r"(a[3]), "r"(b0), "r"(b1));
}

// ---------------- weight convert + transpose: W[K][N] fp32 -> Bq[N][K] packed ----------------
__global__ void __launch_bounds__(256) conv_tp(const float* __restrict__ W,
                                               unsigned* __restrict__ Bq, int K, int N)
{
    __shared__ unsigned tile[32][33];
    int n0 = blockIdx.x * 32, k0 = blockIdx.y * 32;
    int tx = threadIdx.x & 31, ty = threadIdx.x >> 5;
    #pragma unroll
    for (int i = 0; i < 4; i++) {
        int kk = ty + i*8;
        tile[kk][tx] = pack_hl(W[(size_t)(k0+kk)*N + n0 + tx]);
    }
    __syncthreads();
    #pragma unroll
    for (int i = 0; i < 4; i++) {
        int nn = ty + i*8;
        Bq[(size_t)(n0+nn)*K + k0 + tx] = tile[tx][nn];
    }
}

// ---------------- big GEMM: C[M,N] = gather(A)[M,K] @ Bq^T + bias  (bf16x3 MMA) ----------------
// block tile 128x128, Bq is [N][K] packed. grid.x = M/128, grid.y = N/128.
__global__ void __launch_bounds__(256) gemm_big(
    const float* __restrict__ A, const int* __restrict__ gather,
    const unsigned* __restrict__ Bq, const float* __restrict__ bias,
    float* __restrict__ C, int N, int K)
{
    __shared__ __align__(16) __nv_bfloat16 Ah[128*AST], Al[128*AST];
    __shared__ __align__(16) __nv_bfloat16 Bh[128*AST], Bl[128*AST];
    const int t = threadIdx.x, lane = t & 31, wid = t >> 5;
    const int wr = wid & 3, wc = wid >> 2;      // 4 m-warps x 2 n-warps
    const int g = lane >> 2, tig = lane & 3;
    const int m0 = blockIdx.x * 128, n0 = blockIdx.y * 128;

    const int am = t >> 1, ak = (t & 1) * 8;
    const int arow = gather ? gather[m0 + am] : (m0 + am);
    const float* Ap = A + (size_t)arow * K + ak;
    const int bn = t >> 1, bk = (t & 1) * 8;
    const unsigned* Bp = Bq + (size_t)(n0 + bn) * K + bk;

    float acc[2][8][4];
    #pragma unroll
    for (int i = 0; i < 2; i++)
        #pragma unroll
        for (int j = 0; j < 8; j++)
            #pragma unroll
            for (int q = 0; q < 4; q++) acc[i][j][q] = 0.0f;

    const int iters = K >> 4;
    float4 a0R = *(const float4*)Ap;
    float4 a1R = *(const float4*)(Ap + 4);
    uint4  b0R = *(const uint4*)Bp;
    uint4  b1R = *(const uint4*)(Bp + 4);

    for (int kt = 0; kt < iters; kt++) {
        {
            unsigned h0,l0,h1,l1,h2,l2,h3,l3;
            split2(a0R.x, a0R.y, h0, l0); split2(a0R.z, a0R.w, h1, l1);
            split2(a1R.x, a1R.y, h2, l2); split2(a1R.z, a1R.w, h3, l3);
            *(uint4*)&Ah[am*AST + ak] = make_uint4(h0,h1,h2,h3);
            *(uint4*)&Al[am*AST + ak] = make_uint4(l0,l1,l2,l3);
            unsigned w[8] = {b0R.x,b0R.y,b0R.z,b0R.w,b1R.x,b1R.y,b1R.z,b1R.w};
            uint4 hh, ll;
            hh.x = (w[0]&0xffffu)|(w[1]<<16); ll.x = (w[0]>>16)|(w[1]&0xffff0000u);
            hh.y = (w[2]&0xffffu)|(w[3]<<16); ll.y = (w[2]>>16)|(w[3]&0xffff0000u);
            hh.z = (w[4]&0xffffu)|(w[5]<<16); ll.z = (w[4]>>16)|(w[5]&0xffff0000u);
            hh.w = (w[6]&0xffffu)|(w[7]<<16); ll.w = (w[6]>>16)|(w[7]&0xffff0000u);
            *(uint4*)&Bh[bn*AST + bk] = hh;
            *(uint4*)&Bl[bn*AST + bk] = ll;
        }
        __syncthreads();
        if (kt + 1 < iters) {
            a0R = *(const float4*)(Ap + (kt+1)*16);
            a1R = *(const float4*)(Ap + (kt+1)*16 + 4);
            b0R = *(const uint4*)(Bp + (kt+1)*16);
            b1R = *(const uint4*)(Bp + (kt+1)*16 + 4);
        }
        unsigned ah[2][4], al[2][4];
        #pragma unroll
        for (int mt = 0; mt < 2; mt++) {
            int r0 = wr*32 + mt*16 + g;
            ah[mt][0] = *(const unsigned*)&Ah[r0*AST + tig*2];
            ah[mt][1] = *(const unsigned*)&Ah[(r0+8)*AST + tig*2];
            ah[mt][2] = *(const unsigned*)&Ah[r0*AST + tig*2 + 8];
            ah[mt][3] = *(const unsigned*)&Ah[(r0+8)*AST + tig*2 + 8];
            al[mt][0] = *(const unsigned*)&Al[r0*AST + tig*2];
            al[mt][1] = *(const unsigned*)&Al[(r0+8)*AST + tig*2];
            al[mt][2] = *(const unsigned*)&Al[r0*AST + tig*2 + 8];
            al[mt][3] = *(const unsigned*)&Al[(r0+8)*AST + tig*2 + 8];
        }
        #pragma unroll
        for (int nt = 0; nt < 8; nt++) {
            int col = wc*64 + nt*8 + g;
            unsigned bh0 = *(const unsigned*)&Bh[col*AST + tig*2];
            unsigned bh1 = *(const unsigned*)&Bh[col*AST + tig*2 + 8];
            unsigned bl0 = *(const unsigned*)&Bl[col*AST + tig*2];
            unsigned bl1 = *(const unsigned*)&Bl[col*AST + tig*2 + 8];
            #pragma unroll
            for (int mt = 0; mt < 2; mt++) {
                mma16816(acc[mt][nt], ah[mt], bh0, bh1);
                mma16816(acc[mt][nt], ah[mt], bl0, bl1);
                mma16816(acc[mt][nt], al[mt], bh0, bh1);
            }
        }
        __syncthreads();
    }
    #pragma unroll
    for (int mt = 0; mt < 2; mt++) {
        #pragma unroll
        for (int nt = 0; nt < 8; nt++) {
            int m = m0 + wr*32 + mt*16 + g;
            int n = n0 + wc*64 + nt*8 + tig*2;
            float b0v = bias[n], b1v = bias[n+1];
            float* p = C + (size_t)m * N + n;
            *(float2*)p = make_float2(acc[mt][nt][0] + b0v, acc[mt][nt][1] + b1v);
            *(float2*)(p + (size_t)8*N) = make_float2(acc[mt][nt][2] + b0v, acc[mt][nt][3] + b1v);
        }
    }
}

// ---------------- small GEMM (M=32), K-split partials, bf16x3 MMA ----------------
// part[ky][32][N] = x_chunk[32, kc16*16] @ W_chunk^T. x row stride = Hn.
__global__ void __launch_bounds__(256) gemm_small(
    const float* __restrict__ xA, const unsigned* __restrict__ WA, int ldkA,
    const float* __restrict__ xB, const unsigned* __restrict__ WB, int ldkB,
    int nA, int kc16, int N, float* __restrict__ part)
{
    __shared__ __align__(16) __nv_bfloat16 Ah[32*AST], Al[32*AST];
    __shared__ __align__(16) __nv_bfloat16 Bh[128*AST], Bl[128*AST];
    const int t = threadIdx.x, lane = t & 31, wid = t >> 5;
    const int wm = wid & 1, wn = wid >> 1;    // 2 m-warps x 4 n-warps
    const int g = lane >> 2, tig = lane & 3;
    const int n0 = blockIdx.x * 128;
    const int ky = blockIdx.y;
    const float* x; const unsigned* W; int ldk;
    const int cky = (ky < nA) ? ky : ky - nA;
    if (ky < nA) { x = xA; W = WA; ldk = ldkA; } else { x = xB; W = WB; ldk = ldkB; }
    const int k0 = cky * (kc16 * 16);

    const int arow = t >> 2, akq = (t & 3) * 4;
    const float* Ap = x + (size_t)arow * Hn + k0 + akq;
    const int brow = t >> 1, bk = (t & 1) * 8;
    const unsigned* Bp = W + (size_t)(n0 + brow) * ldk + k0 + bk;

    float acc[4][4];
    #pragma unroll
    for (int i = 0; i < 4; i++)
        #pragma unroll
        for (int j = 0; j < 4; j++) acc[i][j] = 0.0f;

    float4 aR;
    if (t < 128) aR = *(const float4*)Ap;
    uint4 b0R = *(const uint4*)Bp;
    uint4 b1R = *(const uint4*)(Bp + 4);

    for (int kt = 0; kt < kc16; kt++) {
        if (t < 128) {
            unsigned h0,l0,h1,l1;
            split2(aR.x, aR.y, h0, l0); split2(aR.z, aR.w, h1, l1);
            *(uint2*)&Ah[arow*AST + akq] = make_uint2(h0, h1);
            *(uint2*)&Al[arow*AST + akq] = make_uint2(l0, l1);
        }
        {
            unsigned w[8] = {b0R.x,b0R.y,b0R.z,b0R.w,b1R.x,b1R.y,b1R.z,b1R.w};
            uint4 hh, ll;
            hh.x = (w[0]&0xffffu)|(w[1]<<16); ll.x = (w[0]>>16)|(w[1]&0xffff0000u);
            hh.y = (w[2]&0xffffu)|(w[3]<<16); ll.y = (w[2]>>16)|(w[3]&0xffff0000u);
            hh.z = (w[4]&0xffffu)|(w[5]<<16); ll.z = (w[4]>>16)|(w[5]&0xffff0000u);
            hh.w = (w[6]&0xffffu)|(w[7]<<16); ll.w = (w[6]>>16)|(w[7]&0xffff0000u);
            *(uint4*)&Bh[brow*AST + bk] = hh;
            *(uint4*)&Bl[brow*AST + bk] = ll;
        }
        __syncthreads();
        if (kt + 1 < kc16) {
            if (t < 128) aR = *(const float4*)(Ap + (kt+1)*16);
            b0R = *(const uint4*)(Bp + (kt+1)*16);
            b1R = *(const uint4*)(Bp + (kt+1)*16 + 4);
        }
        unsigned ah[4], al[4];
        {
            int r0 = wm*16 + g;
            ah[0] = *(const unsigned*)&Ah[r0*AST + tig*2];
            ah[1] = *(const unsigned*)&Ah[(r0+8)*AST + tig*2];
            ah[2] = *(const unsigned*)&Ah[r0*AST + tig*2 + 8];
            ah[3] = *(const unsigned*)&Ah[(r0+8)*AST + tig*2 + 8];
            al[0] = *(const unsigned*)&Al[r0*AST + tig*2];
            al[1] = *(const unsigned*)&Al[(r0+8)*AST + tig*2];
            al[2] = *(const unsigned*)&Al[r0*AST + tig*2 + 8];
            al[3] = *(const unsigned*)&Al[(r0+8)*AST + tig*2 + 8];
        }
        #pragma unroll
        for (int nt = 0; nt < 4; nt++) {
            int col = wn*32 + nt*8 + g;
            unsigned bh0 = *(const unsigned*)&Bh[col*AST + tig*2];
            unsigned bh1 = *(const unsigned*)&Bh[col*AST + tig*2 + 8];
            unsigned bl0 = *(const unsigned*)&Bl[col*AST + tig*2];
            unsigned bl1 = *(const unsigned*)&Bl[col*AST + tig*2 + 8];
            mma16816(acc[nt], ah, bh0, bh1);
            mma16816(acc[nt], ah, bl0, bl1);
            mma16816(acc[nt], al, bh0, bh1);
        }
        __syncthreads();
    }
    #pragma unroll
    for (int nt = 0; nt < 4; nt++) {
        int m = wm*16 + g;
        int n = n0 + wn*32 + nt*8 + tig*2;
        float* p = part + ((size_t)ky*Bn + m) * N + n;
        *(float2*)p = make_float2(acc[nt][0], acc[nt][1]);
        *(float2*)(p + (size_t)8*N) = make_float2(acc[nt][2], acc[nt][3]);
    }
}

// ---------------- state / cells ----------------
__global__ void zero_state() {
    int i = blockIdx.x*256 + threadIdx.x;
    g_h[i] = 0.0f; g_c[i] = 0.0f;
}
__global__ void init_dec() {
    int i = blockIdx.x*256 + threadIdx.x;
    float h = g_h[i], c = g_c[i];
    g_hd[i] = h; g_cd[i] = c; g_feed[i] = h;
}

__global__ void enc_cell(int t) {
    int idx = blockIdx.x*256 + threadIdx.x;
    int b = idx >> 10, j = idx & 1023;
    size_t xb = ((size_t)(b*Sn + t)) * Gn;
    float gi = g_XWenc[xb + j];
    float gf = g_XWenc[xb + j + 1024];
    float gg = g_XWenc[xb + j + 2048];
    float go = g_XWenc[xb + j + 3072];
    #pragma unroll
    for (int p = 0; p < 8; p++) {
        size_t pb = ((size_t)(p*Bn + b)) * Gn;
        gi += g_part[pb + j];
        gf += g_part[pb + j + 1024];
        gg += g_part[pb + j + 2048];
        go += g_part[pb + j + 3072];
    }
    float c = sigm(gf) * g_c[idx] + sigm(gi) * tanhf(gg);
    float h = sigm(go) * tanhf(c);
    g_c[idx] = c; g_h[idx] = h;
    g_enc_out[((size_t)(b*Sn + t)) * Hn + j] = h;
}

// fused decoder: LSTM cell + attention scores + softmax + context
__global__ void __launch_bounds__(256) dec_att(int t) {
    __shared__ float hsh[Hn];
    __shared__ float sc[128];
    __shared__ float red[32];
    const int b = blockIdx.x;
    const int tid = threadIdx.x, lane = tid & 31, wid = tid >> 5;

    // LSTM cell
    size_t xb = ((size_t)(b*Tn + t)) * Gn;
    #pragma unroll
    for (int jj = 0; jj < 4; jj++) {
        int j = tid + jj*256;
        float gi = g_XWdec[xb + j];
        float gf = g_XWdec[xb + j + 1024];
        float gg = g_XWdec[xb + j + 2048];
        float go = g_XWdec[xb + j + 3072];
        #pragma unroll
        for (int p = 0; p < 8; p++) {
            size_t pb = ((size_t)(p*Bn + b)) * Gn;
            gi += g_part[pb + j];
            gf += g_part[pb + j + 1024];
            gg += g_part[pb + j + 2048];
            go += g_part[pb + j + 3072];
        }
        int idx = b*Hn + j;
        float c = sigm(gf) * g_cd[idx] + sigm(gi) * tanhf(gg);
        float h = sigm(go) * tanhf(c);
        g_cd[idx] = c; g_hd[idx] = h;
        hsh[j] = h;
    }
    __syncthreads();

    // scores over S
    for (int s = wid; s < Sn; s += 8) {
        const float* ep = g_enc_proj + ((size_t)(b*Sn + s)) * Hn;
        float acc = 0.0f;
        #pragma unroll 4
        for (int k = lane; k < Hn; k += 32) acc += ep[k] * hsh[k];
        #pragma unroll
        for (int o = 16; o; o >>= 1) acc += __shfl_xor_sync(0xffffffffu, acc, o);
        if (lane == 0) sc[s] = acc;
    }
    __syncthreads();

    // softmax (unnormalized exp; scale folded into context)
    float v = (tid < Sn) ? sc[tid] : -1e30f;
    float m = v;
    #pragma unroll
    for (int o = 16; o; o >>= 1) m = fmaxf(m, __shfl_xor_sync(0xffffffffu, m, o));
    if (lane == 0) red[wid] = m;
    __syncthreads();
    if (tid == 0) {
        float mm = red[0];
        #pragma unroll
        for (int i = 1; i < 8; i++) mm = fmaxf(mm, red[i]);
        red[0] = mm;
    }
    __syncthreads();
    float mx = red[0];
    float e = (tid < Sn) ? expf(v - mx) : 0.0f;
    __syncthreads();
    if (tid < Sn) sc[tid] = e;
    float s0 = e;
    #pragma unroll
    for (int o = 16; o; o >>= 1) s0 += __shfl_xor_sync(0xffffffffu, s0, o);
    if (lane == 0) red[8 + wid] = s0;
    __syncthreads();
    if (tid == 0) {
        float ss = 0.0f;
        #pragma unroll
        for (int i = 0; i < 8; i++) ss += red[8 + i];
        red[16] = 1.0f / ss;
    }
    __syncthreads();
    float inv = red[16];

    // context
    #pragma unroll
    for (int jj = 0; jj < 4; jj++) {
        int j = tid + jj*256;
        const float* eo = g_enc_out + ((size_t)(b*Sn)) * Hn + j;
        float acc = 0.0f;
        #pragma unroll 4
        for (int s = 0; s < Sn; s++) acc += sc[s] * eo[(size_t)s * Hn];
        g_atten[b*Hn + j] = acc * inv;
    }
}

__global__ void feed_reduce(int t, const float* __restrict__ cls1_b) {
    int idx = blockIdx.x*256 + threadIdx.x;
    int b = idx >> 10, j = idx & 1023;
    float acc = cls1_b[j];
    #pragma unroll
    for (int p = 0; p < 8; p++) acc += g_fp[((size_t)(p*Bn + b)) * Hn + j];
    float f = tanhf(acc);
    g_feed[idx] = f;
    g_hidden[((size_t)(b*Tn + t)) * Hn + j] = f;
}

extern "C" void kernel_launch(void* const* d_in, const int* in_sizes, int n_in,
                              void* d_out, int out_size)
{
    const int*   source_data = (const int*)  d_in[0];
    const int*   target_data = (const int*)  d_in[1];
    const float* src_emb  = (const float*)d_in[2];
    const float* tgt_emb  = (const float*)d_in[3];
    const float* enc_Wih  = (const float*)d_in[4];
    const float* enc_Whh  = (const float*)d_in[5];
    const float* enc_b    = (const float*)d_in[6];
    const float* dec_Wih  = (const float*)d_in[7];
    const float* dec_Whh  = (const float*)d_in[8];
    const float* dec_b    = (const float*)d_in[9];
    const float* att1_W   = (const float*)d_in[10];
    const float* att1_b   = (const float*)d_in[11];
    const float* cls1_W   = (const float*)d_in[12];
    const float* cls1_b   = (const float*)d_in[13];
    const float* cls2_W   = (const float*)d_in[14];
    const float* cls2_b   = (const float*)d_in[15];
    float* out = (float*)d_out;

    float *XWenc, *XWdec, *enc_out, *enc_proj, *hidden;
    float *hptr, *hdptr, *feedptr, *attenptr, *partptr, *fpptr;
    unsigned *wih_e, *wih_d0, *whh_e, *wih_dH, *whh_d, *att1q, *cls1q, *cls2q;
    cudaGetSymbolAddress((void**)&XWenc,   g_XWenc);
    cudaGetSymbolAddress((void**)&XWdec,   g_XWdec);
    cudaGetSymbolAddress((void**)&enc_out, g_enc_out);
    cudaGetSymbolAddress((void**)&enc_proj,g_enc_proj);
    cudaGetSymbolAddress((void**)&hidden,  g_hidden);
    cudaGetSymbolAddress((void**)&hptr,    g_h);
    cudaGetSymbolAddress((void**)&hdptr,   g_hd);
    cudaGetSymbolAddress((void**)&feedptr, g_feed);
    cudaGetSymbolAddress((void**)&attenptr,g_atten);
    cudaGetSymbolAddress((void**)&partptr, g_part);
    cudaGetSymbolAddress((void**)&fpptr,   g_fp);
    cudaGetSymbolAddress((void**)&wih_e,   g_wih_e);
    cudaGetSymbolAddress((void**)&wih_d0,  g_wih_d0);
    cudaGetSymbolAddress((void**)&whh_e,   g_whh_e);
    cudaGetSymbolAddress((void**)&wih_dH,  g_wih_dH);
    cudaGetSymbolAddress((void**)&whh_d,   g_whh_d);
    cudaGetSymbolAddress((void**)&att1q,   g_att1q);
    cudaGetSymbolAddress((void**)&cls1q,   g_cls1q);
    cudaGetSymbolAddress((void**)&cls2q,   g_cls2q);

    // weight conversion (transpose + hi/lo bf16 pack)
    conv_tp<<<dim3(4096/32,  512/32), 256>>>(enc_Wih,                      wih_e,  512, 4096);
    conv_tp<<<dim3(4096/32,  512/32), 256>>>(dec_Wih,                      wih_d0, 512, 4096);
    conv_tp<<<dim3(4096/32, 1024/32), 256>>>(enc_Whh,                      whh_e, 1024, 4096);
    conv_tp<<<dim3(4096/32, 1024/32), 256>>>(dec_Wih + (size_t)512*4096,   wih_dH,1024, 4096);
    conv_tp<<<dim3(4096/32, 1024/32), 256>>>(dec_Whh,                      whh_d, 1024, 4096);
    conv_tp<<<dim3(1024/32, 1024/32), 256>>>(att1_W,                       att1q, 1024, 1024);
    conv_tp<<<dim3(1024/32, 2048/32), 256>>>(cls1_W,                       cls1q, 2048, 1024);
    conv_tp<<<dim3(32000/32,1024/32), 256>>>(cls2_W,                       cls2q, 1024, 32000);

    zero_state<<<128, 256>>>();
    // batched input projections (embedding gather fused)
    gemm_big<<<dim3(25, 32), 256>>>(src_emb, source_data, wih_e,  enc_b, XWenc, Gn, En);
    gemm_big<<<dim3(25, 32), 256>>>(tgt_emb, target_data, wih_d0, dec_b, XWdec, Gn, En);

    // encoder: h @ Whh split into 8 K-chunks of 128
    for (int t = 0; t < Sn; t++) {
        gemm_small<<<dim3(32, 8), 256>>>(hptr, whh_e, 1024, hptr, whh_e, 1024, 8, 8, Gn, partptr);
        enc_cell<<<128, 256>>>(t);
    }
    gemm_big<<<dim3(25, 8), 256>>>(enc_out, nullptr, att1q, att1_b, enc_proj, Hn, Hn);
    init_dec<<<128, 256>>>();

    // decoder: gates = feed@WihH (4 chunks of 256) + hd@Whh (4 chunks)
    for (int t = 0; t < Tn; t++) {
        gemm_small<<<dim3(32, 8), 256>>>(feedptr, wih_dH, 1024, hdptr, whh_d, 1024, 4, 16, Gn, partptr);
        dec_att<<<32, 256>>>(t);
        gemm_small<<<dim3(8, 8), 256>>>(attenptr, cls1q, 2048, hdptr, cls1q + 1024, 2048, 4, 16, Hn, fpptr);
        feed_reduce<<<128, 256>>>(t, cls1_b);
    }

    // classifier
    gemm_big<<<dim3(25, 250), 256>>>(hidden, nullptr, cls2q, cls2_b, out, Vn, Hn);
}

// round 4
// speedup vs baseline: 1.1766x; 1.1081x over previous
#include <cuda_runtime.h>
#include <cuda_bf16.h>
#include <math.h>
#include <stdint.h>

#define Bn 32
#define Sn 100
#define Tn 100
#define En 512
#define Hn 1024
#define Vn 32000
#define Gn 4096   // 4*H
#define AST 24    // smem row stride (bf16) for gemm_big
#define NBLK 128  // persistent grid size (<= SM count -> co-resident)

// ---------------- fp32 scratch ----------------
__device__ float g_XWenc[Bn*Sn*Gn];
__device__ float g_XWdec[Bn*Tn*Gn];
__device__ float g_enc_out[Bn*Sn*Hn];
__device__ float g_enc_proj[Bn*Sn*Hn];
__device__ float g_hidden[Bn*Tn*Hn];
__device__ float g_h[Bn*Hn];
__device__ float g_c[Bn*Hn];
__device__ float g_hdf[Bn*Hn];
__device__ float g_scores[Bn*Sn];

// ---------------- bf16 state buffers (double-buffered hi/lo) ----------------
__device__ __nv_bfloat16 g_eh_h[2][Bn*Hn], g_eh_l[2][Bn*Hn];
__device__ __nv_bfloat16 g_dh_h[2][Bn*Hn], g_dh_l[2][Bn*Hn];
__device__ __nv_bfloat16 g_fd_h[2][Bn*Hn], g_fd_l[2][Bn*Hn];
__device__ __nv_bfloat16 g_at_h[Bn*Hn],    g_at_l[Bn*Hn];

// ---------------- weights, transposed [n][k], bf16 hi/lo split ----------------
__device__ __nv_bfloat16 w_ihE_h [(size_t)Gn*En], w_ihE_l [(size_t)Gn*En];
__device__ __nv_bfloat16 w_ihD0_h[(size_t)Gn*En], w_ihD0_l[(size_t)Gn*En];
__device__ __nv_bfloat16 w_hhE_h [(size_t)Gn*Hn], w_hhE_l [(size_t)Gn*Hn];
__device__ __nv_bfloat16 w_ihDH_h[(size_t)Gn*Hn], w_ihDH_l[(size_t)Gn*Hn];
__device__ __nv_bfloat16 w_hhD_h [(size_t)Gn*Hn], w_hhD_l [(size_t)Gn*Hn];
__device__ __nv_bfloat16 w_att_h [(size_t)Hn*Hn], w_att_l [(size_t)Hn*Hn];
__device__ __nv_bfloat16 w_c1_h  [(size_t)Hn*2*Hn], w_c1_l [(size_t)Hn*2*Hn];
__device__ __nv_bfloat16 w_c2_h  [(size_t)Vn*Hn], w_c2_l  [(size_t)Vn*Hn];

// ---------------- grid barrier (sense-reversing) ----------------
__device__ unsigned g_cnt;
__device__ unsigned g_gen;

__device__ __forceinline__ void gbar() {
    __syncthreads();
    if (threadIdx.x == 0) {
        __threadfence();
        unsigned my = *((volatile unsigned*)&g_gen);
        unsigned a = atomicAdd(&g_cnt, 1u);
        if (a == NBLK - 1u) {
            g_cnt = 0u;
            __threadfence();
            *((volatile unsigned*)&g_gen) = my + 1u;
        } else {
            while (*((volatile unsigned*)&g_gen) == my) { __nanosleep(32); }
        }
        __threadfence();
    }
    __syncthreads();
}

__device__ __forceinline__ float sigm(float x){ return 1.0f/(1.0f + expf(-x)); }

__device__ __forceinline__ void split2(float x, float y, unsigned& hp, unsigned& lp) {
    __nv_bfloat16 hx = __float2bfloat16(x), hy = __float2bfloat16(y);
    __nv_bfloat16 lx = __float2bfloat16(x - __bfloat162float(hx));
    __nv_bfloat16 ly = __float2bfloat16(y - __bfloat162float(hy));
    hp = (unsigned)__bfloat16_as_ushort(hx) | ((unsigned)__bfloat16_as_ushort(hy) << 16);
    lp = (unsigned)__bfloat16_as_ushort(lx) | ((unsigned)__bfloat16_as_ushort(ly) << 16);
}

__device__ __forceinline__ void mma16816(float* c, const unsigned* a, unsigned b0, unsigned b1) {
    asm volatile("mma.sync.aligned.m16n8k16.row.col.f32.bf16.bf16.f32 "
        "{%0,%1,%2,%3},{%4,%5,%6,%7},{%8,%9},{%0,%1,%2,%3};"
        : "+f"(c[0]), "+f"(c[1]), "+f"(c[2]), "+f"(c[3])
        : "r"(a[0]), "r"(a[1]), "r"(a[2]), "r"(a[3]), "r"(b0), "r"(b1));
}

// load A-fragment (m16 x k16) hi or lo from bf16 matrix with row stride Hn
__device__ __forceinline__ void ldAfrag(unsigned* f, const __nv_bfloat16* base, int row, int kk) {
    f[0] = *(const unsigned*)(base + (size_t)row*Hn + kk);
    f[1] = *(const unsigned*)(base + (size_t)(row+8)*Hn + kk);
    f[2] = *(const unsigned*)(base + (size_t)row*Hn + kk + 8);
    f[3] = *(const unsigned*)(base + (size_t)(row+8)*Hn + kk + 8);
}

// ---------------- weight convert: W[K][N] fp32 -> Bh/Bl [N][K] bf16 ----------------
__global__ void __launch_bounds__(256) conv_tp(const float* __restrict__ W,
        __nv_bfloat16* __restrict__ Bh, __nv_bfloat16* __restrict__ Bl, int K, int N)
{
    __shared__ float tile[32][33];
    int n0 = blockIdx.x * 32, k0 = blockIdx.y * 32;
    int tx = threadIdx.x & 31, ty = threadIdx.x >> 5;
    #pragma unroll
    for (int i = 0; i < 4; i++)
        tile[ty + i*8][tx] = W[(size_t)(k0 + ty + i*8)*N + n0 + tx];
    __syncthreads();
    #pragma unroll
    for (int i = 0; i < 4; i++) {
        int nn = ty + i*8;
        float v = tile[tx][nn];
        __nv_bfloat16 h = __float2bfloat16(v);
        Bh[(size_t)(n0+nn)*K + k0 + tx] = h;
        Bl[(size_t)(n0+nn)*K + k0 + tx] = __float2bfloat16(v - __bfloat162float(h));
    }
}

// ---------------- big GEMM: C[M,N] = gather(A)[M,K] @ B^T + bias (bf16x3 MMA) ----------------
__global__ void __launch_bounds__(256) gemm_big(
    const float* __restrict__ A, const int* __restrict__ gather,
    const __nv_bfloat16* __restrict__ Bh, const __nv_bfloat16* __restrict__ Bl,
    const float* __restrict__ bias, float* __restrict__ C, int N, int K)
{
    __shared__ __align__(16) __nv_bfloat16 Ahs[128*AST], Als[128*AST];
    __shared__ __align__(16) __nv_bfloat16 Bhs[128*AST], Bls[128*AST];
    const int t = threadIdx.x, lane = t & 31, wid = t >> 5;
    const int wr = wid & 3, wc = wid >> 2;
    const int g = lane >> 2, tig = lane & 3;
    const int m0 = blockIdx.x * 128, n0 = blockIdx.y * 128;

    const int am = t >> 1, ak = (t & 1) * 8;
    const int arow = gather ? gather[m0 + am] : (m0 + am);
    const float* Ap = A + (size_t)arow * K + ak;
    const int bn = t >> 1, bkk = (t & 1) * 8;
    const __nv_bfloat16* Bph = Bh + (size_t)(n0 + bn) * K + bkk;
    const __nv_bfloat16* Bpl = Bl + (size_t)(n0 + bn) * K + bkk;

    float acc[2][8][4];
    #pragma unroll
    for (int i = 0; i < 2; i++)
        #pragma unroll
        for (int j = 0; j < 8; j++)
            #pragma unroll
            for (int q = 0; q < 4; q++) acc[i][j][q] = 0.0f;

    const int iters = K >> 4;
    float4 a0R = *(const float4*)Ap;
    float4 a1R = *(const float4*)(Ap + 4);
    uint4 bhR = *(const uint4*)Bph;
    uint4 blR = *(const uint4*)Bpl;

    for (int kt = 0; kt < iters; kt++) {
        {
            unsigned h0,l0,h1,l1,h2,l2,h3,l3;
            split2(a0R.x, a0R.y, h0, l0); split2(a0R.z, a0R.w, h1, l1);
            split2(a1R.x, a1R.y, h2, l2); split2(a1R.z, a1R.w, h3, l3);
            *(uint4*)&Ahs[am*AST + ak] = make_uint4(h0,h1,h2,h3);
            *(uint4*)&Als[am*AST + ak] = make_uint4(l0,l1,l2,l3);
            *(uint4*)&Bhs[bn*AST + bkk] = bhR;
            *(uint4*)&Bls[bn*AST + bkk] = blR;
        }
        __syncthreads();
        if (kt + 1 < iters) {
            a0R = *(const float4*)(Ap + (kt+1)*16);
            a1R = *(const float4*)(Ap + (kt+1)*16 + 4);
            bhR = *(const uint4*)(Bph + (kt+1)*16);
            blR = *(const uint4*)(Bpl + (kt+1)*16);
        }
        unsigned ah[2][4], al[2][4];
        #pragma unroll
        for (int mt = 0; mt < 2; mt++) {
            int r0 = wr*32 + mt*16 + g;
            ah[mt][0] = *(const unsigned*)&Ahs[r0*AST + tig*2];
            ah[mt][1] = *(const unsigned*)&Ahs[(r0+8)*AST + tig*2];
            ah[mt][2] = *(const unsigned*)&Ahs[r0*AST + tig*2 + 8];
            ah[mt][3] = *(const unsigned*)&Ahs[(r0+8)*AST + tig*2 + 8];
            al[mt][0] = *(const unsigned*)&Als[r0*AST + tig*2];
            al[mt][1] = *(const unsigned*)&Als[(r0+8)*AST + tig*2];
            al[mt][2] = *(const unsigned*)&Als[r0*AST + tig*2 + 8];
            al[mt][3] = *(const unsigned*)&Als[(r0+8)*AST + tig*2 + 8];
        }
        #pragma unroll
        for (int nt = 0; nt < 8; nt++) {
            int col = wc*64 + nt*8 + g;
            unsigned bh0 = *(const unsigned*)&Bhs[col*AST + tig*2];
            unsigned bh1 = *(const unsigned*)&Bhs[col*AST + tig*2 + 8];
            unsigned bl0 = *(const unsigned*)&Bls[col*AST + tig*2];
            unsigned bl1 = *(const unsigned*)&Bls[col*AST + tig*2 + 8];
            #pragma unroll
            for (int mt = 0; mt < 2; mt++) {
                mma16816(acc[mt][nt], ah[mt], bh0, bh1);
                mma16816(acc[mt][nt], ah[mt], bl0, bl1);
                mma16816(acc[mt][nt], al[mt], bh0, bh1);
            }
        }
        __syncthreads();
    }
    #pragma unroll
    for (int mt = 0; mt < 2; mt++) {
        #pragma unroll
        for (int nt = 0; nt < 8; nt++) {
            int m = m0 + wr*32 + mt*16 + g;
            int n = n0 + wc*64 + nt*8 + tig*2;
            float b0v = bias[n], b1v = bias[n+1];
            float* p = C + (size_t)m * N + n;
            *(float2*)p = make_float2(acc[mt][nt][0] + b0v, acc[mt][nt][1] + b1v);
            *(float2*)(p + (size_t)8*N) = make_float2(acc[mt][nt][2] + b0v, acc[mt][nt][3] + b1v);
        }
    }
}

// ---------------- persistent encoder: 100 LSTM steps in one kernel ----------------
__global__ void __launch_bounds__(256) enc_persist()
{
    const int bk = blockIdx.x, tid = threadIdx.x, lane = tid & 31, wid = tid >> 5;
    const int g = lane >> 2, tig = lane & 3;
    const int bb = tid >> 3, jl = tid & 7;
    const int j = bk*8 + jl;
    __shared__ float red[8][32*33];

    {   // zero h buffer 0 (t=0 reads zeros)
        int i = bk*256 + tid;
        g_eh_h[0][i] = __float2bfloat16(0.f);
        g_eh_l[0][i] = __float2bfloat16(0.f);
    }
    float cst = 0.0f;
    gbar();

    for (int t = 0; t < Sn; t++) {
        const int rp = t & 1, wp2 = rp ^ 1;
        const __nv_bfloat16* hh = g_eh_h[rp];
        const __nv_bfloat16* hl = g_eh_l[rp];
        float acc[2][4][4];
        #pragma unroll
        for (int a = 0; a < 2; a++)
            #pragma unroll
            for (int b = 0; b < 4; b++)
                #pragma unroll
                for (int q = 0; q < 4; q++) acc[a][b][q] = 0.0f;

        const int koff = wid * 128;
        for (int ks = 0; ks < 8; ks++) {
            const int kk = koff + ks*16 + tig*2;
            unsigned ah[2][4], al[2][4];
            #pragma unroll
            for (int mt = 0; mt < 2; mt++) {
                ldAfrag(ah[mt], hh, mt*16 + g, kk);
                ldAfrag(al[mt], hl, mt*16 + g, kk);
            }
            #pragma unroll
            for (int nt = 0; nt < 4; nt++) {
                const size_t nr = (size_t)(nt*Hn + bk*8 + g) * Hn + kk;
                unsigned b0h = *(const unsigned*)(w_hhE_h + nr);
                unsigned b1h = *(const unsigned*)(w_hhE_h + nr + 8);
                unsigned b0l = *(const unsigned*)(w_hhE_l + nr);
                unsigned b1l = *(const unsigned*)(w_hhE_l + nr + 8);
                #pragma unroll
                for (int mt = 0; mt < 2; mt++) {
                    mma16816(acc[mt][nt], ah[mt], b0h, b1h);
                    mma16816(acc[mt][nt], ah[mt], b0l, b1l);
                    mma16816(acc[mt][nt], al[mt], b0h, b1h);
                }
            }
        }
        #pragma unroll
        for (int mt = 0; mt < 2; mt++)
            #pragma unroll
            for (int nt = 0; nt < 4; nt++) {
                int r0 = mt*16 + g, c0 = nt*8 + tig*2;
                red[wid][r0*33 + c0]     = acc[mt][nt][0];
                red[wid][r0*33 + c0 + 1] = acc[mt][nt][1];
                red[wid][(r0+8)*33 + c0]     = acc[mt][nt][2];
                red[wid][(r0+8)*33 + c0 + 1] = acc[mt][nt][3];
            }
        __syncthreads();

        float gi = 0.f, gf = 0.f, gg = 0.f, go = 0.f;
        #pragma unroll
        for (int w = 0; w < 8; w++) {
            const float* rw = &red[w][bb*33];
            gi += rw[jl]; gf += rw[8+jl]; gg += rw[16+jl]; go += rw[24+jl];
        }
        const size_t xw = ((size_t)(bb*Sn + t))*Gn + bk*8 + jl;
        gi += g_XWenc[xw]; gf += g_XWenc[xw+1024]; gg += g_XWenc[xw+2048]; go += g_XWenc[xw+3072];
        cst = sigm(gf)*cst + sigm(gi)*tanhf(gg);
        float h = sigm(go)*tanhf(cst);
        __nv_bfloat16 hhv = __float2bfloat16(h);
        g_eh_h[wp2][bb*Hn + j] = hhv;
        g_eh_l[wp2][bb*Hn + j] = __float2bfloat16(h - __bfloat162float(hhv));
        g_enc_out[((size_t)(bb*Sn + t))*Hn + j] = h;
        if (t == Sn-1) { g_h[bb*Hn + j] = h; g_c[bb*Hn + j] = cst; }
        gbar();
    }
}

// ---------------- persistent decoder: 100 steps, 4 phases each ----------------
__global__ void __launch_bounds__(256) dec_persist(const float* __restrict__ cls1_b)
{
    const int bk = blockIdx.x, tid = threadIdx.x, lane = tid & 31, wid = tid >> 5;
    const int g = lane >> 2, tig = lane & 3;
    const int bb = tid >> 3, jl = tid & 7;
    const int j = bk*8 + jl;
    __shared__ float red[8][32*33];
    float* sc    = &red[0][0];      // 3200
    float* wsm   = sc + 3200;       // 3200
    float* stats = wsm + 3200;      // 64

    {   // init feed/hd buffers (parity 0) from encoder final h
        int i = bk*256 + tid;
        float h0 = g_h[i];
        __nv_bfloat16 hh = __float2bfloat16(h0);
        __nv_bfloat16 hl = __float2bfloat16(h0 - __bfloat162float(hh));
        g_dh_h[0][i] = hh; g_dh_l[0][i] = hl;
        g_fd_h[0][i] = hh; g_fd_l[0][i] = hl;
    }
    float cst = g_c[bb*Hn + j];
    gbar();

    for (int t = 0; t < Tn; t++) {
        const int rp = t & 1, wp2 = rp ^ 1;

        // ---- P1: gates = feed@WihH + hd@Whh + XWdec; LSTM cell ----
        {
            const __nv_bfloat16 *ah_p, *al_p, *bh_p, *bl_p;
            int koff;
            if (wid < 4) { ah_p = g_fd_h[rp]; al_p = g_fd_l[rp]; bh_p = w_ihDH_h; bl_p = w_ihDH_l; koff = wid*256; }
            else         { ah_p = g_dh_h[rp]; al_p = g_dh_l[rp]; bh_p = w_hhD_h;  bl_p = w_hhD_l;  koff = (wid-4)*256; }
            float acc[2][4][4];
            #pragma unroll
            for (int a = 0; a < 2; a++)
                #pragma unroll
                for (int b = 0; b < 4; b++)
                    #pragma unroll
                    for (int q = 0; q < 4; q++) acc[a][b][q] = 0.0f;

            for (int ks = 0; ks < 16; ks++) {
                const int kk = koff + ks*16 + tig*2;
                unsigned ah[2][4], al[2][4];
                #pragma unroll
                for (int mt = 0; mt < 2; mt++) {
                    ldAfrag(ah[mt], ah_p, mt*16 + g, kk);
                    ldAfrag(al[mt], al_p, mt*16 + g, kk);
                }
                #pragma unroll
                for (int nt = 0; nt < 4; nt++) {
                    const size_t nr = (size_t)(nt*Hn + bk*8 + g) * Hn + kk;
                    unsigned b0h = *(const unsigned*)(bh_p + nr);
                    unsigned b1h = *(const unsigned*)(bh_p + nr + 8);
                    unsigned b0l = *(const unsigned*)(bl_p + nr);
                    unsigned b1l = *(const unsigned*)(bl_p + nr + 8);
                    #pragma unroll
                    for (int mt = 0; mt < 2; mt++) {
                        mma16816(acc[mt][nt], ah[mt], b0h, b1h);
                        mma16816(acc[mt][nt], ah[mt], b0l, b1l);
                        mma16816(acc[mt][nt], al[mt], b0h, b1h);
                    }
                }
            }
            #pragma unroll
            for (int mt = 0; mt < 2; mt++)
                #pragma unroll
                for (int nt = 0; nt < 4; nt++) {
                    int r0 = mt*16 + g, c0 = nt*8 + tig*2;
                    red[wid][r0*33 + c0]     = acc[mt][nt][0];
                    red[wid][r0*33 + c0 + 1] = acc[mt][nt][1];
                    red[wid][(r0+8)*33 + c0]     = acc[mt][nt][2];
                    red[wid][(r0+8)*33 + c0 + 1] = acc[mt][nt][3];
                }
            __syncthreads();

            float gi = 0.f, gf = 0.f, gg = 0.f, go = 0.f;
            #pragma unroll
            for (int w = 0; w < 8; w++) {
                const float* rw = &red[w][bb*33];
                gi += rw[jl]; gf += rw[8+jl]; gg += rw[16+jl]; go += rw[24+jl];
            }
            const size_t xw = ((size_t)(bb*Tn + t))*Gn + bk*8 + jl;
            gi += g_XWdec[xw]; gf += g_XWdec[xw+1024]; gg += g_XWdec[xw+2048]; go += g_XWdec[xw+3072];
            cst = sigm(gf)*cst + sigm(gi)*tanhf(gg);
            float h = sigm(go)*tanhf(cst);
            __nv_bfloat16 hhv = __float2bfloat16(h);
            g_dh_h[wp2][bb*Hn + j] = hhv;
            g_dh_l[wp2][bb*Hn + j] = __float2bfloat16(h - __bfloat162float(hhv));
            g_hdf[bb*Hn + j] = h;
        }
        gbar();

        // ---- P2: attention scores ----
        #pragma unroll
        for (int r = 0; r < 4; r++) {
            int pair = bk*8 + wid + r*1024;
            if (pair < Bn*Sn) {
                int b = pair / Sn;
                const float* ep = g_enc_proj + (size_t)pair * Hn;
                const float* hv = g_hdf + b * Hn;
                float a = 0.f;
                #pragma unroll 4
                for (int k = lane; k < Hn; k += 32) a += ep[k] * hv[k];
                #pragma unroll
                for (int o = 16; o; o >>= 1) a += __shfl_xor_sync(0xffffffffu, a, o);
                if (lane == 0) g_scores[pair] = a;
            }
        }
        gbar();

        // ---- P3: softmax + context ----
        for (int i = tid; i < Bn*Sn; i += 256) sc[i] = g_scores[i];
        __syncthreads();
        #pragma unroll
        for (int q = 0; q < 4; q++) {
            int b = wid*4 + q;
            float m = -1e30f;
            for (int s = lane; s < Sn; s += 32) m = fmaxf(m, sc[b*Sn + s]);
            #pragma unroll
            for (int o = 16; o; o >>= 1) m = fmaxf(m, __shfl_xor_sync(0xffffffffu, m, o));
            float su = 0.f;
            for (int s = lane; s < Sn; s += 32) su += expf(sc[b*Sn + s] - m);
            #pragma unroll
            for (int o = 16; o; o >>= 1) su += __shfl_xor_sync(0xffffffffu, su, o);
            if (lane == 0) { stats[b] = m; stats[32 + b] = 1.0f / su; }
        }
        __syncthreads();
        for (int i = tid; i < Bn*Sn; i += 256) {
            int b = i / Sn;
            wsm[i] = expf(sc[i] - stats[b]) * stats[32 + b];
        }
        __syncthreads();
        {
            float a = 0.f;
            const float* eo = g_enc_out + ((size_t)bb*Sn) * Hn + j;
            const float* wv = wsm + bb*Sn;
            #pragma unroll 4
            for (int s = 0; s < Sn; s++) a += wv[s] * eo[(size_t)s * Hn];
            __nv_bfloat16 hh = __float2bfloat16(a);
            g_at_h[bb*Hn + j] = hh;
            g_at_l[bb*Hn + j] = __float2bfloat16(a - __bfloat162float(hh));
        }
        gbar();

        // ---- P4: feed = tanh([atten, hd] @ cls1 + b) ----
        {
            const __nv_bfloat16 *xa_h, *xa_l;
            int koff;
            if (wid < 4) { xa_h = g_at_h;      xa_l = g_at_l;      koff = wid*256; }
            else         { xa_h = g_dh_h[wp2]; xa_l = g_dh_l[wp2]; koff = (wid-4)*256; }
            const int kbase = (wid < 4) ? 0 : 1024;
            float fa[2][4];
            #pragma unroll
            for (int a = 0; a < 2; a++)
                #pragma unroll
                for (int q = 0; q < 4; q++) fa[a][q] = 0.0f;

            for (int ks = 0; ks < 16; ks++) {
                const int kk = koff + ks*16 + tig*2;
                const int kg = kbase + kk;
                unsigned ah[2][4], al[2][4];
                #pragma unroll
                for (int mt = 0; mt < 2; mt++) {
                    ldAfrag(ah[mt], xa_h, mt*16 + g, kk);
                    ldAfrag(al[mt], xa_l, mt*16 + g, kk);
                }
                const size_t nr = (size_t)(bk*8 + g) * (2*Hn) + kg;
                unsigned b0h = *(const unsigned*)(w_c1_h + nr);
                unsigned b1h = *(const unsigned*)(w_c1_h + nr + 8);
                unsigned b0l = *(const unsigned*)(w_c1_l + nr);
                unsigned b1l = *(const unsigned*)(w_c1_l + nr + 8);
                #pragma unroll
                for (int mt = 0; mt < 2; mt++) {
                    mma16816(fa[mt], ah[mt], b0h, b1h);
                    mma16816(fa[mt], ah[mt], b0l, b1l);
                    mma16816(fa[mt], al[mt], b0h, b1h);
                }
            }
            #pragma unroll
            for (int mt = 0; mt < 2; mt++) {
                int r0 = mt*16 + g, c0 = tig*2;
                red[wid][r0*33 + c0]     = fa[mt][0];
                red[wid][r0*33 + c0 + 1] = fa[mt][1];
                red[wid][(r0+8)*33 + c0]     = fa[mt][2];
                red[wid][(r0+8)*33 + c0 + 1] = fa[mt][3];
            }
            __syncthreads();
            float a = cls1_b[j];
            #pragma unroll
            for (int w = 0; w < 8; w++) a += red[w][bb*33 + jl];
            float f = tanhf(a);
            __nv_bfloat16 hh = __float2bfloat16(f);
            g_fd_h[wp2][bb*Hn + j] = hh;
            g_fd_l[wp2][bb*Hn + j] = __float2bfloat16(f - __bfloat162float(hh));
            g_hidden[((size_t)(bb*Tn + t))*Hn + j] = f;
        }
        gbar();
    }
}

extern "C" void kernel_launch(void* const* d_in, const int* in_sizes, int n_in,
                              void* d_out, int out_size)
{
    const int*   source_data = (const int*)  d_in[0];
    const int*   target_data = (const int*)  d_in[1];
    const float* src_emb  = (const float*)d_in[2];
    const float* tgt_emb  = (const float*)d_in[3];
    const float* enc_Wih  = (const float*)d_in[4];
    const float* enc_Whh  = (const float*)d_in[5];
    const float* enc_b    = (const float*)d_in[6];
    const float* dec_Wih  = (const float*)d_in[7];
    const float* dec_Whh  = (const float*)d_in[8];
    const float* dec_b    = (const float*)d_in[9];
    const float* att1_W   = (const float*)d_in[10];
    const float* att1_b   = (const float*)d_in[11];
    const float* cls1_W   = (const float*)d_in[12];
    const float* cls1_b   = (const float*)d_in[13];
    const float* cls2_W   = (const float*)d_in[14];
    const float* cls2_b   = (const float*)d_in[15];
    float* out = (float*)d_out;

    float *XWenc, *XWdec, *enc_out, *enc_proj, *hidden;
    __nv_bfloat16 *ihE_h,*ihE_l,*ihD0_h,*ihD0_l,*hhE_h,*hhE_l,*ihDH_h,*ihDH_l,*hhD_h,*hhD_l;
    __nv_bfloat16 *attq_h,*attq_l,*c1_h,*c1_l,*c2_h,*c2_l;
    cudaGetSymbolAddress((void**)&XWenc,   g_XWenc);
    cudaGetSymbolAddress((void**)&XWdec,   g_XWdec);
    cudaGetSymbolAddress((void**)&enc_out, g_enc_out);
    cudaGetSymbolAddress((void**)&enc_proj,g_enc_proj);
    cudaGetSymbolAddress((void**)&hidden,  g_hidden);
    cudaGetSymbolAddress((void**)&ihE_h,  w_ihE_h);  cudaGetSymbolAddress((void**)&ihE_l,  w_ihE_l);
    cudaGetSymbolAddress((void**)&ihD0_h, w_ihD0_h); cudaGetSymbolAddress((void**)&ihD0_l, w_ihD0_l);
    cudaGetSymbolAddress((void**)&hhE_h,  w_hhE_h);  cudaGetSymbolAddress((void**)&hhE_l,  w_hhE_l);
    cudaGetSymbolAddress((void**)&ihDH_h, w_ihDH_h); cudaGetSymbolAddress((void**)&ihDH_l, w_ihDH_l);
    cudaGetSymbolAddress((void**)&hhD_h,  w_hhD_h);  cudaGetSymbolAddress((void**)&hhD_l,  w_hhD_l);
    cudaGetSymbolAddress((void**)&attq_h, w_att_h);  cudaGetSymbolAddress((void**)&attq_l, w_att_l);
    cudaGetSymbolAddress((void**)&c1_h,   w_c1_h);   cudaGetSymbolAddress((void**)&c1_l,   w_c1_l);
    cudaGetSymbolAddress((void**)&c2_h,   w_c2_h);   cudaGetSymbolAddress((void**)&c2_l,   w_c2_l);

    // ---- weight conversion (transpose + bf16 hi/lo split) ----
    conv_tp<<<dim3(128, 16), 256>>>(enc_Wih,                    ihE_h,  ihE_l,   512, 4096);
    conv_tp<<<dim3(128, 16), 256>>>(dec_Wih,                    ihD0_h, ihD0_l,  512, 4096);
    conv_tp<<<dim3(128, 32), 256>>>(enc_Whh,                    hhE_h,  hhE_l,  1024, 4096);
    conv_tp<<<dim3(128, 32), 256>>>(dec_Wih + (size_t)512*4096, ihDH_h, ihDH_l, 1024, 4096);
    conv_tp<<<dim3(128, 32), 256>>>(dec_Whh,                    hhD_h,  hhD_l,  1024, 4096);
    conv_tp<<<dim3(32, 32),  256>>>(att1_W,                     attq_h, attq_l, 1024, 1024);
    conv_tp<<<dim3(32, 64),  256>>>(cls1_W,                     c1_h,   c1_l,   2048, 1024);
    conv_tp<<<dim3(1000,32), 256>>>(cls2_W,                     c2_h,   c2_l,   1024, 32000);

    // ---- batched input projections (embedding gather fused) ----
    gemm_big<<<dim3(25, 32), 256>>>(src_emb, source_data, ihE_h,  ihE_l,  enc_b, XWenc, Gn, En);
    gemm_big<<<dim3(25, 32), 256>>>(tgt_emb, target_data, ihD0_h, ihD0_l, dec_b, XWdec, Gn, En);

    // ---- persistent encoder ----
    enc_persist<<<NBLK, 256>>>();

    // ---- attention projection of encoder outputs ----
    gemm_big<<<dim3(25, 8), 256>>>(enc_out, nullptr, attq_h, attq_l, att1_b, enc_proj, Hn, Hn);

    // ---- persistent decoder ----
    dec_persist<<<NBLK, 256>>>(cls1_b);

    // ---- classifier ----
    gemm_big<<<dim3(25, 250), 256>>>(hidden, nullptr, c2_h, c2_l, cls2_b, out, Vn, Hn);
}

// round 5
// speedup vs baseline: 1.2276x; 1.0433x over previous
#include <cuda_runtime.h>
#include <cuda_bf16.h>
#include <math.h>
#include <stdint.h>

#define Bn 32
#define Sn 100
#define Tn 100
#define En 512
#define Hn 1024
#define Vn 32000
#define Gn 4096   // 4*H
#define AST 24    // smem row stride (bf16) for gemm_big
#define NBLK 128  // persistent grid size (<= SM count -> co-resident)

// ---------------- fp32 scratch ----------------
__device__ float g_XWenc[Bn*Sn*Gn];
__device__ float g_XWdec[Bn*Tn*Gn];
__device__ float g_enc_out[Bn*Sn*Hn];
__device__ float g_enc_proj[Bn*Sn*Hn];
__device__ float g_hidden[Bn*Tn*Hn];
__device__ float g_h[Bn*Hn];
__device__ float g_c[Bn*Hn];
__device__ float g_hdf[Bn*Hn];
__device__ float g_scores[Bn*Sn];

// ---------------- bf16 state buffers (double-buffered hi/lo) ----------------
__device__ __nv_bfloat16 g_eh_h[2][Bn*Hn], g_eh_l[2][Bn*Hn];
__device__ __nv_bfloat16 g_dh_h[2][Bn*Hn], g_dh_l[2][Bn*Hn];
__device__ __nv_bfloat16 g_fd_h[2][Bn*Hn], g_fd_l[2][Bn*Hn];
__device__ __nv_bfloat16 g_at_h[Bn*Hn],    g_at_l[Bn*Hn];

// ---------------- weights, transposed [n][k], bf16 hi/lo split ----------------
__device__ __nv_bfloat16 w_ihE_h [(size_t)Gn*En], w_ihE_l [(size_t)Gn*En];
__device__ __nv_bfloat16 w_ihD0_h[(size_t)Gn*En], w_ihD0_l[(size_t)Gn*En];
__device__ __nv_bfloat16 w_hhE_h [(size_t)Gn*Hn], w_hhE_l [(size_t)Gn*Hn];
__device__ __nv_bfloat16 w_ihDH_h[(size_t)Gn*Hn], w_ihDH_l[(size_t)Gn*Hn];
__device__ __nv_bfloat16 w_hhD_h [(size_t)Gn*Hn], w_hhD_l [(size_t)Gn*Hn];
__device__ __nv_bfloat16 w_att_h [(size_t)Hn*Hn], w_att_l [(size_t)Hn*Hn];
__device__ __nv_bfloat16 w_c1_h  [(size_t)Hn*2*Hn], w_c1_l [(size_t)Hn*2*Hn];
__device__ __nv_bfloat16 w_c2_h  [(size_t)Vn*Hn], w_c2_l  [(size_t)Vn*Hn];

// ---------------- grid barrier (sense-reversing) ----------------
__device__ unsigned g_cnt;
__device__ unsigned g_gen;

__device__ __forceinline__ void gbar() {
    __syncthreads();
    if (threadIdx.x == 0) {
        __threadfence();
        unsigned my = *((volatile unsigned*)&g_gen);
        unsigned a = atomicAdd(&g_cnt, 1u);
        if (a == NBLK - 1u) {
            g_cnt = 0u;
            __threadfence();
            *((volatile unsigned*)&g_gen) = my + 1u;
        } else {
            while (*((volatile unsigned*)&g_gen) == my) { __nanosleep(32); }
        }
        __threadfence();
    }
    __syncthreads();
}

__device__ __forceinline__ float sigm(float x){ return 1.0f/(1.0f + expf(-x)); }

__device__ __forceinline__ void split2(float x, float y, unsigned& hp, unsigned& lp) {
    __nv_bfloat16 hx = __float2bfloat16(x), hy = __float2bfloat16(y);
    __nv_bfloat16 lx = __float2bfloat16(x - __bfloat162float(hx));
    __nv_bfloat16 ly = __float2bfloat16(y - __bfloat162float(hy));
    hp = (unsigned)__bfloat16_as_ushort(hx) | ((unsigned)__bfloat16_as_ushort(hy) << 16);
    lp = (unsigned)__bfloat16_as_ushort(lx) | ((unsigned)__bfloat16_as_ushort(ly) << 16);
}

__device__ __forceinline__ void mma16816(float* c, const unsigned* a, unsigned b0, unsigned b1) {
    asm volatile("mma.sync.aligned.m16n8k16.row.col.f32.bf16.bf16.f32 "
        "{%0,%1,%2,%3},{%4,%5,%6,%7},{%8,%9},{%0,%1,%2,%3};"
        : "+f"(c[0]), "+f"(c[1]), "+f"(c[2]), "+f"(c[3])
        : "r"(a[0]), "r"(a[1]), "r"(a[2]), "r"(a[3]), "r"(b0), "r"(b1));
}

// load A-fragment (m16 x k16) hi or lo from bf16 matrix with row stride Hn
__device__ __forceinline__ void ldAfrag(unsigned* f, const __nv_bfloat16* base, int row, int kk) {
    f[0] = *(const unsigned*)(base + (size_t)row*Hn + kk);
    f[1] = *(const unsigned*)(base + (size_t)(row+8)*Hn + kk);
    f[2] = *(const unsigned*)(base + (size_t)row*Hn + kk + 8);
    f[3] = *(const unsigned*)(base + (size_t)(row+8)*Hn + kk + 8);
}

// ---------------- weight convert: W[K][N] fp32 -> Bh/Bl [N][K] bf16 ----------------
__global__ void __launch_bounds__(256) conv_tp(const float* __restrict__ W,
        __nv_bfloat16* __restrict__ Bh, __nv_bfloat16* __restrict__ Bl, int K, int N)
{
    __shared__ float tile[32][33];
    int n0 = blockIdx.x * 32, k0 = blockIdx.y * 32;
    int tx = threadIdx.x & 31, ty = threadIdx.x >> 5;
    #pragma unroll
    for (int i = 0; i < 4; i++)
        tile[ty + i*8][tx] = W[(size_t)(k0 + ty + i*8)*N + n0 + tx];
    __syncthreads();
    #pragma unroll
    for (int i = 0; i < 4; i++) {
        int nn = ty + i*8;
        float v = tile[tx][nn];
        __nv_bfloat16 h = __float2bfloat16(v);
        Bh[(size_t)(n0+nn)*K + k0 + tx] = h;
        Bl[(size_t)(n0+nn)*K + k0 + tx] = __float2bfloat16(v - __bfloat162float(h));
    }
}

// ---------------- big GEMM: C[M,N] = gather(A)[M,K] @ B^T + bias (bf16x3 MMA) ----------------
__global__ void __launch_bounds__(256) gemm_big(
    const float* __restrict__ A, const int* __restrict__ gather,
    const __nv_bfloat16* __restrict__ Bh, const __nv_bfloat16* __restrict__ Bl,
    const float* __restrict__ bias, float* __restrict__ C, int N, int K)
{
    __shared__ __align__(16) __nv_bfloat16 Ahs[128*AST], Als[128*AST];
    __shared__ __align__(16) __nv_bfloat16 Bhs[128*AST], Bls[128*AST];
    const int t = threadIdx.x, lane = t & 31, wid = t >> 5;
    const int wr = wid & 3, wc = wid >> 2;
    const int g = lane >> 2, tig = lane & 3;
    const int m0 = blockIdx.x * 128, n0 = blockIdx.y * 128;

    const int am = t >> 1, ak = (t & 1) * 8;
    const int arow = gather ? gather[m0 + am] : (m0 + am);
    const float* Ap = A + (size_t)arow * K + ak;
    const int bn = t >> 1, bkk = (t & 1) * 8;
    const __nv_bfloat16* Bph = Bh + (size_t)(n0 + bn) * K + bkk;
    const __nv_bfloat16* Bpl = Bl + (size_t)(n0 + bn) * K + bkk;

    float acc[2][8][4];
    #pragma unroll
    for (int i = 0; i < 2; i++)
        #pragma unroll
        for (int j = 0; j < 8; j++)
            #pragma unroll
            for (int q = 0; q < 4; q++) acc[i][j][q] = 0.0f;

    const int iters = K >> 4;
    float4 a0R = *(const float4*)Ap;
    float4 a1R = *(const float4*)(Ap + 4);
    uint4 bhR = *(const uint4*)Bph;
    uint4 blR = *(const uint4*)Bpl;

    for (int kt = 0; kt < iters; kt++) {
        {
            unsigned h0,l0,h1,l1,h2,l2,h3,l3;
            split2(a0R.x, a0R.y, h0, l0); split2(a0R.z, a0R.w, h1, l1);
            split2(a1R.x, a1R.y, h2, l2); split2(a1R.z, a1R.w, h3, l3);
            *(uint4*)&Ahs[am*AST + ak] = make_uint4(h0,h1,h2,h3);
            *(uint4*)&Als[am*AST + ak] = make_uint4(l0,l1,l2,l3);
            *(uint4*)&Bhs[bn*AST + bkk] = bhR;
            *(uint4*)&Bls[bn*AST + bkk] = blR;
        }
        __syncthreads();
        if (kt + 1 < iters) {
            a0R = *(const float4*)(Ap + (kt+1)*16);
            a1R = *(const float4*)(Ap + (kt+1)*16 + 4);
            bhR = *(const uint4*)(Bph + (kt+1)*16);
            blR = *(const uint4*)(Bpl + (kt+1)*16);
        }
        unsigned ah[2][4], al[2][4];
        #pragma unroll
        for (int mt = 0; mt < 2; mt++) {
            int r0 = wr*32 + mt*16 + g;
            ah[mt][0] = *(const unsigned*)&Ahs[r0*AST + tig*2];
            ah[mt][1] = *(const unsigned*)&Ahs[(r0+8)*AST + tig*2];
            ah[mt][2] = *(const unsigned*)&Ahs[r0*AST + tig*2 + 8];
            ah[mt][3] = *(const unsigned*)&Ahs[(r0+8)*AST + tig*2 + 8];
            al[mt][0] = *(const unsigned*)&Als[r0*AST + tig*2];
            al[mt][1] = *(const unsigned*)&Als[(r0+8)*AST + tig*2];
            al[mt][2] = *(const unsigned*)&Als[r0*AST + tig*2 + 8];
            al[mt][3] = *(const unsigned*)&Als[(r0+8)*AST + tig*2 + 8];
        }
        #pragma unroll
        for (int nt = 0; nt < 8; nt++) {
            int col = wc*64 + nt*8 + g;
            unsigned bh0 = *(const unsigned*)&Bhs[col*AST + tig*2];
            unsigned bh1 = *(const unsigned*)&Bhs[col*AST + tig*2 + 8];
            unsigned bl0 = *(const unsigned*)&Bls[col*AST + tig*2];
            unsigned bl1 = *(const unsigned*)&Bls[col*AST + tig*2 + 8];
            #pragma unroll
            for (int mt = 0; mt < 2; mt++) {
                mma16816(acc[mt][nt], ah[mt], bh0, bh1);
                mma16816(acc[mt][nt], ah[mt], bl0, bl1);
                mma16816(acc[mt][nt], al[mt], bh0, bh1);
            }
        }
        __syncthreads();
    }
    #pragma unroll
    for (int mt = 0; mt < 2; mt++) {
        #pragma unroll
        for (int nt = 0; nt < 8; nt++) {
            int m = m0 + wr*32 + mt*16 + g;
            int n = n0 + wc*64 + nt*8 + tig*2;
            float b0v = bias[n], b1v = bias[n+1];
            float* p = C + (size_t)m * N + n;
            *(float2*)p = make_float2(acc[mt][nt][0] + b0v, acc[mt][nt][1] + b1v);
            *(float2*)(p + (size_t)8*N) = make_float2(acc[mt][nt][2] + b0v, acc[mt][nt][3] + b1v);
        }
    }
}

// ---------------- persistent encoder: 100 LSTM steps in one kernel ----------------
__global__ void __launch_bounds__(256) enc_persist()
{
    const int bk = blockIdx.x, tid = threadIdx.x, lane = tid & 31, wid = tid >> 5;
    const int g = lane >> 2, tig = lane & 3;
    const int bb = tid >> 3, jl = tid & 7;
    const int j = bk*8 + jl;
    __shared__ float red[8][32*33];

    {   // zero h buffer 0 (t=0 reads zeros)
        int i = bk*256 + tid;
        g_eh_h[0][i] = __float2bfloat16(0.f);
        g_eh_l[0][i] = __float2bfloat16(0.f);
    }
    float cst = 0.0f;
    gbar();

    for (int t = 0; t < Sn; t++) {
        const int rp = t & 1, wp2 = rp ^ 1;
        const __nv_bfloat16* hh = g_eh_h[rp];
        const __nv_bfloat16* hl = g_eh_l[rp];
        float acc[2][4][4];
        #pragma unroll
        for (int a = 0; a < 2; a++)
            #pragma unroll
            for (int b = 0; b < 4; b++)
                #pragma unroll
                for (int q = 0; q < 4; q++) acc[a][b][q] = 0.0f;

        const int koff = wid * 128;
        for (int ks = 0; ks < 8; ks++) {
            const int kk = koff + ks*16 + tig*2;
            unsigned ah[2][4], al[2][4];
            #pragma unroll
            for (int mt = 0; mt < 2; mt++) {
                ldAfrag(ah[mt], hh, mt*16 + g, kk);
                ldAfrag(al[mt], hl, mt*16 + g, kk);
            }
            #pragma unroll
            for (int nt = 0; nt < 4; nt++) {
                const size_t nr = (size_t)(nt*Hn + bk*8 + g) * Hn + kk;
                unsigned b0h = *(const unsigned*)(w_hhE_h + nr);
                unsigned b1h = *(const unsigned*)(w_hhE_h + nr + 8);
                unsigned b0l = *(const unsigned*)(w_hhE_l + nr);
                unsigned b1l = *(const unsigned*)(w_hhE_l + nr + 8);
                #pragma unroll
                for (int mt = 0; mt < 2; mt++) {
                    mma16816(acc[mt][nt], ah[mt], b0h, b1h);
                    mma16816(acc[mt][nt], ah[mt], b0l, b1l);
                    mma16816(acc[mt][nt], al[mt], b0h, b1h);
                }
            }
        }
        #pragma unroll
        for (int mt = 0; mt < 2; mt++)
            #pragma unroll
            for (int nt = 0; nt < 4; nt++) {
                int r0 = mt*16 + g, c0 = nt*8 + tig*2;
                red[wid][r0*33 + c0]     = acc[mt][nt][0];
                red[wid][r0*33 + c0 + 1] = acc[mt][nt][1];
                red[wid][(r0+8)*33 + c0]     = acc[mt][nt][2];
                red[wid][(r0+8)*33 + c0 + 1] = acc[mt][nt][3];
            }
        __syncthreads();

        float gi = 0.f, gf = 0.f, gg = 0.f, go = 0.f;
        #pragma unroll
        for (int w = 0; w < 8; w++) {
            const float* rw = &red[w][bb*33];
            gi += rw[jl]; gf += rw[8+jl]; gg += rw[16+jl]; go += rw[24+jl];
        }
        const size_t xw = ((size_t)(bb*Sn + t))*Gn + bk*8 + jl;
        gi += g_XWenc[xw]; gf += g_XWenc[xw+1024]; gg += g_XWenc[xw+2048]; go += g_XWenc[xw+3072];
        cst = sigm(gf)*cst + sigm(gi)*tanhf(gg);
        float h = sigm(go)*tanhf(cst);
        __nv_bfloat16 hhv = __float2bfloat16(h);
        g_eh_h[wp2][bb*Hn + j] = hhv;
        g_eh_l[wp2][bb*Hn + j] = __float2bfloat16(h - __bfloat162float(hhv));
        g_enc_out[((size_t)(bb*Sn + t))*Hn + j] = h;
        if (t == Sn-1) { g_h[bb*Hn + j] = h; g_c[bb*Hn + j] = cst; }
        gbar();
    }
}

// ---------------- persistent decoder: 100 steps, 4 phases each ----------------
__global__ void __launch_bounds__(256) dec_persist(const float* __restrict__ cls1_b)
{
    const int bk = blockIdx.x, tid = threadIdx.x, lane = tid & 31, wid = tid >> 5;
    const int g = lane >> 2, tig = lane & 3;
    const int bb = tid >> 3, jl = tid & 7;
    const int j = bk*8 + jl;
    __shared__ float red[8][32*33];
    float* sc    = &red[0][0];      // 3200
    float* wsm   = sc + 3200;       // 3200
    float* stats = wsm + 3200;      // 64

    {   // init feed/hd buffers (parity 0) from encoder final h
        int i = bk*256 + tid;
        float h0 = g_h[i];
        __nv_bfloat16 hh = __float2bfloat16(h0);
        __nv_bfloat16 hl = __float2bfloat16(h0 - __bfloat162float(hh));
        g_dh_h[0][i] = hh; g_dh_l[0][i] = hl;
        g_fd_h[0][i] = hh; g_fd_l[0][i] = hl;
    }
    float cst = g_c[bb*Hn + j];
    gbar();

    for (int t = 0; t < Tn; t++) {
        const int rp = t & 1, wp2 = rp ^ 1;

        // ---- P1: gates = feed@WihH + hd@Whh + XWdec; LSTM cell ----
        {
            const __nv_bfloat16 *ah_p, *al_p, *bh_p, *bl_p;
            int koff;
            if (wid < 4) { ah_p = g_fd_h[rp]; al_p = g_fd_l[rp]; bh_p = w_ihDH_h; bl_p = w_ihDH_l; koff = wid*256; }
            else         { ah_p = g_dh_h[rp]; al_p = g_dh_l[rp]; bh_p = w_hhD_h;  bl_p = w_hhD_l;  koff = (wid-4)*256; }
            float acc[2][4][4];
            #pragma unroll
            for (int a = 0; a < 2; a++)
                #pragma unroll
                for (int b = 0; b < 4; b++)
                    #pragma unroll
                    for (int q = 0; q < 4; q++) acc[a][b][q] = 0.0f;

            for (int ks = 0; ks < 16; ks++) {
                const int kk = koff + ks*16 + tig*2;
                unsigned ah[2][4], al[2][4];
                #pragma unroll
                for (int mt = 0; mt < 2; mt++) {
                    ldAfrag(ah[mt], ah_p, mt*16 + g, kk);
                    ldAfrag(al[mt], al_p, mt*16 + g, kk);
                }
                #pragma unroll
                for (int nt = 0; nt < 4; nt++) {
                    const size_t nr = (size_t)(nt*Hn + bk*8 + g) * Hn + kk;
                    unsigned b0h = *(const unsigned*)(bh_p + nr);
                    unsigned b1h = *(const unsigned*)(bh_p + nr + 8);
                    unsigned b0l = *(const unsigned*)(bl_p + nr);
                    unsigned b1l = *(const unsigned*)(bl_p + nr + 8);
                    #pragma unroll
                    for (int mt = 0; mt < 2; mt++) {
                        mma16816(acc[mt][nt], ah[mt], b0h, b1h);
                        mma16816(acc[mt][nt], ah[mt], b0l, b1l);
                        mma16816(acc[mt][nt], al[mt], b0h, b1h);
                    }
                }
            }
            #pragma unroll
            for (int mt = 0; mt < 2; mt++)
                #pragma unroll
                for (int nt = 0; nt < 4; nt++) {
                    int r0 = mt*16 + g, c0 = nt*8 + tig*2;
                    red[wid][r0*33 + c0]     = acc[mt][nt][0];
                    red[wid][r0*33 + c0 + 1] = acc[mt][nt][1];
                    red[wid][(r0+8)*33 + c0]     = acc[mt][nt][2];
                    red[wid][(r0+8)*33 + c0 + 1] = acc[mt][nt][3];
                }
            __syncthreads();

            float gi = 0.f, gf = 0.f, gg = 0.f, go = 0.f;
            #pragma unroll
            for (int w = 0; w < 8; w++) {
                const float* rw = &red[w][bb*33];
                gi += rw[jl]; gf += rw[8+jl]; gg += rw[16+jl]; go += rw[24+jl];
            }
            const size_t xw = ((size_t)(bb*Tn + t))*Gn + bk*8 + jl;
            gi += g_XWdec[xw]; gf += g_XWdec[xw+1024]; gg += g_XWdec[xw+2048]; go += g_XWdec[xw+3072];
            cst = sigm(gf)*cst + sigm(gi)*tanhf(gg);
            float h = sigm(go)*tanhf(cst);
            __nv_bfloat16 hhv = __float2bfloat16(h);
            g_dh_h[wp2][bb*Hn + j] = hhv;
            g_dh_l[wp2][bb*Hn + j] = __float2bfloat16(h - __bfloat162float(hhv));
            g_hdf[bb*Hn + j] = h;
        }
        gbar();

        // ---- P2: attention scores ----
        #pragma unroll
        for (int r = 0; r < 4; r++) {
            int pair = bk*8 + wid + r*1024;
            if (pair < Bn*Sn) {
                int b = pair / Sn;
                const float* ep = g_enc_proj + (size_t)pair * Hn;
                const float* hv = g_hdf + b * Hn;
                float a = 0.f;
                #pragma unroll 4
                for (int k = lane; k < Hn; k += 32) a += ep[k] * hv[k];
                #pragma unroll
                for (int o = 16; o; o >>= 1) a += __shfl_xor_sync(0xffffffffu, a, o);
                if (lane == 0) g_scores[pair] = a;
            }
        }
        gbar();

        // ---- P3: softmax + context ----
        for (int i = tid; i < Bn*Sn; i += 256) sc[i] = g_scores[i];
        __syncthreads();
        #pragma unroll
        for (int q = 0; q < 4; q++) {
            int b = wid*4 + q;
            float m = -1e30f;
            for (int s = lane; s < Sn; s += 32) m = fmaxf(m, sc[b*Sn + s]);
            #pragma unroll
            for (int o = 16; o; o >>= 1) m = fmaxf(m, __shfl_xor_sync(0xffffffffu, m, o));
            float su = 0.f;
            for (int s = lane; s < Sn; s += 32) su += expf(sc[b*Sn + s] - m);
            #pragma unroll
            for (int o = 16; o; o >>= 1) su += __shfl_xor_sync(0xffffffffu, su, o);
            if (lane == 0) { stats[b] = m; stats[32 + b] = 1.0f / su; }
        }
        __syncthreads();
        for (int i = tid; i < Bn*Sn; i += 256) {
            int b = i / Sn;
            wsm[i] = expf(sc[i] - stats[b]) * stats[32 + b];
        }
        __syncthreads();
        {
            float a = 0.f;
            const float* eo = g_enc_out + ((size_t)bb*Sn) * Hn + j;
            const float* wv = wsm + bb*Sn;
            #pragma unroll 4
            for (int s = 0; s < Sn; s++) a += wv[s] * eo[(size_t)s * Hn];
            __nv_bfloat16 hh = __float2bfloat16(a);
            g_at_h[bb*Hn + j] = hh;
            g_at_l[bb*Hn + j] = __float2bfloat16(a - __bfloat162float(hh));
        }
        gbar();

        // ---- P4: feed = tanh([atten, hd] @ cls1 + b) ----
        {
            const __nv_bfloat16 *xa_h, *xa_l;
            int koff;
            if (wid < 4) { xa_h = g_at_h;      xa_l = g_at_l;      koff = wid*256; }
            else         { xa_h = g_dh_h[wp2]; xa_l = g_dh_l[wp2]; koff = (wid-4)*256; }
            const int kbase = (wid < 4) ? 0 : 1024;
            float fa[2][4];
            #pragma unroll
            for (int a = 0; a < 2; a++)
                #pragma unroll
                for (int q = 0; q < 4; q++) fa[a][q] = 0.0f;

            for (int ks = 0; ks < 16; ks++) {
                const int kk = koff + ks*16 + tig*2;
                const int kg = kbase + kk;
                unsigned ah[2][4], al[2][4];
                #pragma unroll
                for (int mt = 0; mt < 2; mt++) {
                    ldAfrag(ah[mt], xa_h, mt*16 + g, kk);
                    ldAfrag(al[mt], xa_l, mt*16 + g, kk);
                }
                const size_t nr = (size_t)(bk*8 + g) * (2*Hn) + kg;
                unsigned b0h = *(const unsigned*)(w_c1_h + nr);
                unsigned b1h = *(const unsigned*)(w_c1_h + nr + 8);
                unsigned b0l = *(const unsigned*)(w_c1_l + nr);
                unsigned b1l = *(const unsigned*)(w_c1_l + nr + 8);
                #pragma unroll
                for (int mt = 0; mt < 2; mt++) {
                    mma16816(fa[mt], ah[mt], b0h, b1h);
                    mma16816(fa[mt], ah[mt], b0l, b1l);
                    mma16816(fa[mt], al[mt], b0h, b1h);
                }
            }
            #pragma unroll
            for (int mt = 0; mt < 2; mt++) {
                int r0 = mt*16 + g, c0 = tig*2;
                red[wid][r0*33 + c0]     = fa[mt][0];
                red[wid][r0*33 + c0 + 1] = fa[mt][1];
                red[wid][(r0+8)*33 + c0]     = fa[mt][2];
                red[wid][(r0+8)*33 + c0 + 1] = fa[mt][3];
            }
            __syncthreads();
            float a = cls1_b[j];
            #pragma unroll
            for (int w = 0; w < 8; w++) a += red[w][bb*33 + jl];
            float f = tanhf(a);
            __nv_bfloat16 hh = __float2bfloat16(f);
            g_fd_h[wp2][bb*Hn + j] = hh;
            g_fd_l[wp2][bb*Hn + j] = __float2bfloat16(f - __bfloat162float(hh));
            g_hidden[((size_t)(bb*Tn + t))*Hn + j] = f;
        }
        gbar();
    }
}

extern "C" void kernel_launch(void* const* d_in, const int* in_sizes, int n_in,
                              void* d_out, int out_size)
{
    const int*   source_data = (const int*)  d_in[0];
    const int*   target_data = (const int*)  d_in[1];
    const float* src_emb  = (const float*)d_in[2];
    const float* tgt_emb  = (const float*)d_in[3];
    const float* enc_Wih  = (const float*)d_in[4];
    const float* enc_Whh  = (const float*)d_in[5];
    const float* enc_b    = (const float*)d_in[6];
    const float* dec_Wih  = (const float*)d_in[7];
    const float* dec_Whh  = (const float*)d_in[8];
    const float* dec_b    = (const float*)d_in[9];
    const float* att1_W   = (const float*)d_in[10];
    const float* att1_b   = (const float*)d_in[11];
    const float* cls1_W   = (const float*)d_in[12];
    const float* cls1_b   = (const float*)d_in[13];
    const float* cls2_W   = (const float*)d_in[14];
    const float* cls2_b   = (const float*)d_in[15];
    float* out = (float*)d_out;

    float *XWenc, *XWdec, *enc_out, *enc_proj, *hidden;
    __nv_bfloat16 *ihE_h,*ihE_l,*ihD0_h,*ihD0_l,*hhE_h,*hhE_l,*ihDH_h,*ihDH_l,*hhD_h,*hhD_l;
    __nv_bfloat16 *attq_h,*attq_l,*c1_h,*c1_l,*c2_h,*c2_l;
    cudaGetSymbolAddress((void**)&XWenc,   g_XWenc);
    cudaGetSymbolAddress((void**)&XWdec,   g_XWdec);
    cudaGetSymbolAddress((void**)&enc_out, g_enc_out);
    cudaGetSymbolAddress((void**)&enc_proj,g_enc_proj);
    cudaGetSymbolAddress((void**)&hidden,  g_hidden);
    cudaGetSymbolAddress((void**)&ihE_h,  w_ihE_h);  cudaGetSymbolAddress((void**)&ihE_l,  w_ihE_l);
    cudaGetSymbolAddress((void**)&ihD0_h, w_ihD0_h); cudaGetSymbolAddress((void**)&ihD0_l, w_ihD0_l);
    cudaGetSymbolAddress((void**)&hhE_h,  w_hhE_h);  cudaGetSymbolAddress((void**)&hhE_l,  w_hhE_l);
    cudaGetSymbolAddress((void**)&ihDH_h, w_ihDH_h); cudaGetSymbolAddress((void**)&ihDH_l, w_ihDH_l);
    cudaGetSymbolAddress((void**)&hhD_h,  w_hhD_h);  cudaGetSymbolAddress((void**)&hhD_l,  w_hhD_l);
    cudaGetSymbolAddress((void**)&attq_h, w_att_h);  cudaGetSymbolAddress((void**)&attq_l, w_att_l);
    cudaGetSymbolAddress((void**)&c1_h,   w_c1_h);   cudaGetSymbolAddress((void**)&c1_l,   w_c1_l);
    cudaGetSymbolAddress((void**)&c2_h,   w_c2_h);   cudaGetSymbolAddress((void**)&c2_l,   w_c2_l);

    // ---- weight conversion (transpose + bf16 hi/lo split) ----
    conv_tp<<<dim3(128, 16), 256>>>(enc_Wih,                    ihE_h,  ihE_l,   512, 4096);
    conv_tp<<<dim3(128, 16), 256>>>(dec_Wih,                    ihD0_h, ihD0_l,  512, 4096);
    conv_tp<<<dim3(128, 32), 256>>>(enc_Whh,                    hhE_h,  hhE_l,  1024, 4096);
    conv_tp<<<dim3(128, 32), 256>>>(dec_Wih + (size_t)512*4096, ihDH_h, ihDH_l, 1024, 4096);
    conv_tp<<<dim3(128, 32), 256>>>(dec_Whh,                    hhD_h,  hhD_l,  1024, 4096);
    conv_tp<<<dim3(32, 32),  256>>>(att1_W,                     attq_h, attq_l, 1024, 1024);
    conv_tp<<<dim3(32, 64),  256>>>(cls1_W,                     c1_h,   c1_l,   2048, 1024);
    conv_tp<<<dim3(1000,32), 256>>>(cls2_W,                     c2_h,   c2_l,   1024, 32000);

    // ---- batched input projections (embedding gather fused) ----
    gemm_big<<<dim3(25, 32), 256>>>(src_emb, source_data, ihE_h,  ihE_l,  enc_b, XWenc, Gn, En);
    gemm_big<<<dim3(25, 32), 256>>>(tgt_emb, target_data, ihD0_h, ihD0_l, dec_b, XWdec, Gn, En);

    // ---- persistent encoder ----
    enc_persist<<<NBLK, 256>>>();

    // ---- attention projection of encoder outputs ----
    gemm_big<<<dim3(25, 8), 256>>>(enc_out, nullptr, attq_h, attq_l, att1_b, enc_proj, Hn, Hn);

    // ---- persistent decoder ----
    dec_persist<<<NBLK, 256>>>(cls1_b);

    // ---- classifier ----
    gemm_big<<<dim3(25, 250), 256>>>(hidden, nullptr, c2_h, c2_l, cls2_b, out, Vn, Hn);
}

// round 6
// speedup vs baseline: 1.6034x; 1.3061x over previous
#include <cuda_runtime.h>
#include <cuda_bf16.h>
#include <math.h>
#include <stdint.h>

typedef unsigned short u16;
typedef unsigned int   u32;

#define Bn 32
#define Sn 100
#define Tn 100
#define En 512
#define Hn 1024
#define Vn 32000
#define Gn 4096
#define NBLK 128

// fp32 scratch
__device__ float g_XWenc[Bn*Sn*Gn];
__device__ float g_XWdec[Bn*Tn*Gn];
__device__ float g_enc_out[Bn*Sn*Hn];
__device__ float g_enc_proj[Bn*Sn*Hn];
__device__ float g_hidden[Bn*Tn*Hn];
__device__ float g_h[Bn*Hn];
__device__ float g_c[Bn*Hn];
__device__ float g_hdf[Bn*Hn];
__device__ float g_scores[Bn*Sn];

// fragment-major state: uint4 idx = (chunk*2+mt)*32+lane, chunk=k16 (64 per K=1024)
__device__ uint4 g_ehf[2][2][4096];  // [parity][hi/lo]
__device__ uint4 g_dhf[2][2][4096];
__device__ uint4 g_fdf[2][2][4096];
__device__ uint4 g_atf[2][4096];

// plain transposed [n][k] bf16 weights (for gemm_big)
__device__ u16 w_ihE_h [(size_t)Gn*En],  w_ihE_l [(size_t)Gn*En];
__device__ u16 w_ihD0_h[(size_t)Gn*En],  w_ihD0_l[(size_t)Gn*En];
__device__ u16 w_att_h [(size_t)Hn*Hn],  w_att_l [(size_t)Hn*Hn];
__device__ u16 w_c2_h  [(size_t)Vn*Hn],  w_c2_l  [(size_t)Vn*Hn];

// fragment-major weights: uint4 {b0h,b1h,b0l,b1l}, idx = (ng*nch + c)*32 + lane
__device__ uint4 w_hhE_f [512*64*32];
__device__ uint4 w_ihDH_f[512*64*32];
__device__ uint4 w_hhD_f [512*64*32];
__device__ uint4 w_c1_f  [128*128*32];

__device__ unsigned g_cnt, g_gen;
__device__ __forceinline__ void gbar() {
    __syncthreads();
    if (threadIdx.x == 0) {
        __threadfence();
        unsigned my = *((volatile unsigned*)&g_gen);
        unsigned a = atomicAdd(&g_cnt, 1u);
        if (a == NBLK - 1u) { g_cnt = 0u; __threadfence(); *((volatile unsigned*)&g_gen) = my + 1u; }
        else { while (*((volatile unsigned*)&g_gen) == my) {} }
        __threadfence();
    }
    __syncthreads();
}

__device__ __forceinline__ float sigm(float x){ return 1.0f/(1.0f + expf(-x)); }
__device__ __forceinline__ u16 bhi(float v){ return __bfloat16_as_ushort(__float2bfloat16(v)); }
__device__ __forceinline__ u16 blo(float v){
    __nv_bfloat16 h = __float2bfloat16(v);
    return __bfloat16_as_ushort(__float2bfloat16(v - __bfloat162float(h)));
}
__device__ __forceinline__ u32 pack2(u16 a, u16 b){ return (u32)a | ((u32)b << 16); }
__device__ __forceinline__ void split2(float x, float y, u32& hp, u32& lp) {
    hp = pack2(bhi(x), bhi(y)); lp = pack2(blo(x), blo(y));
}
__device__ __forceinline__ void mma16816(float* c, const u32* a, u32 b0, u32 b1) {
    asm volatile("mma.sync.aligned.m16n8k16.row.col.f32.bf16.bf16.f32 "
        "{%0,%1,%2,%3},{%4,%5,%6,%7},{%8,%9},{%0,%1,%2,%3};"
        : "+f"(c[0]), "+f"(c[1]), "+f"(c[2]), "+f"(c[3])
        : "r"(a[0]), "r"(a[1]), "r"(a[2]), "r"(a[3]), "r"(b0), "r"(b1));
}
__device__ __forceinline__ void ldsm4(u32* r, u32 addr) {
    asm volatile("ldmatrix.sync.aligned.m8n8.x4.shared.b16 {%0,%1,%2,%3}, [%4];"
        : "=r"(r[0]), "=r"(r[1]), "=r"(r[2]), "=r"(r[3]) : "r"(addr));
}
// scatter one state element into fragment-major hi/lo
__device__ __forceinline__ void frag_store(u16* Fh, u16* Fl, int row, int col, float v){
    int ch = col >> 4, kc = col & 15, mt = row >> 4, rg = row & 15;
    int lane = (rg & 7)*4 + ((kc >> 1) & 3);
    int w = ((kc >> 3) << 1) + (rg >> 3);
    size_t idx = ((size_t)(((ch*2 + mt)*32) + lane) << 3) + (w << 1) + (kc & 1);
    __nv_bfloat16 h = __float2bfloat16(v);
    Fh[idx] = __bfloat16_as_ushort(h);
    Fl[idx] = __bfloat16_as_ushort(__float2bfloat16(v - __bfloat162float(h)));
}

// ---------- merged conversion ----------
struct CJ { const float* W; void* Oh; void* Ol; int K, N, mode, boff; };
struct CJobs { CJ j[8]; };

__global__ void __launch_bounds__(256) conv_all(CJobs jb)
{
    __shared__ float tile[32][33];
    int blk = blockIdx.x, ji = 0;
    #pragma unroll
    for (int i = 7; i >= 0; i--) if (blk >= jb.j[i].boff) { ji = i; break; }
    const CJ& J = jb.j[ji];
    int local = blk - J.boff;
    const int tid = threadIdx.x, lane = tid & 31;
    if (J.mode == 0) {
        int ntl = J.N >> 5;
        int tk = local / ntl, tn = local % ntl;
        int n0 = tn*32, k0 = tk*32;
        int tx = lane, ty = tid >> 5;
        #pragma unroll
        for (int i = 0; i < 4; i++)
            tile[ty + i*8][tx] = J.W[(size_t)(k0 + ty + i*8)*J.N + n0 + tx];
        __syncthreads();
        u16* Oh = (u16*)J.Oh; u16* Ol = (u16*)J.Ol;
        #pragma unroll
        for (int i = 0; i < 4; i++) {
            int nn = ty + i*8;
            float v = tile[tx][nn];
            Oh[(size_t)(n0+nn)*J.K + k0 + tx] = bhi(v);
            Ol[(size_t)(n0+nn)*J.K + k0 + tx] = blo(v);
        }
    } else {
        int nch = J.K >> 4;
        int pair = local*8 + (tid >> 5);
        int ng = pair / nch, c = pair % nch;
        int n = ng*8 + (lane >> 2), k = c*16 + (lane & 3)*2;
        const float* W = J.W;
        float v0 = W[(size_t)k*J.N + n],     v1 = W[(size_t)(k+1)*J.N + n];
        float v2 = W[(size_t)(k+8)*J.N + n], v3 = W[(size_t)(k+9)*J.N + n];
        ((uint4*)J.Oh)[(size_t)pair*32 + lane] =
            make_uint4(pack2(bhi(v0),bhi(v1)), pack2(bhi(v2),bhi(v3)),
                       pack2(blo(v0),blo(v1)), pack2(blo(v2),blo(v3)));
    }
}

// ---------- big GEMM with ldmatrix ----------
__global__ void __launch_bounds__(256) gemm_big(
    const float* __restrict__ A, const int* __restrict__ gather,
    const u16* __restrict__ Bh, const u16* __restrict__ Bl,
    const float* __restrict__ bias, float* __restrict__ C, int N, int K)
{
    __shared__ __align__(16) u16 Ahs[128*24], Als[128*24], Bhs[128*24], Bls[128*24];
    const int t = threadIdx.x, lane = t & 31, wid = t >> 5;
    const int wr = wid & 3, wc = wid >> 2;
    const int g = lane >> 2, tg = lane & 3;
    const int m0 = blockIdx.x * 128, n0 = blockIdx.y * 128;

    const int srow = t >> 1, sseg = (t & 1) * 8;
    const int arow = gather ? gather[m0 + srow] : (m0 + srow);
    const float* Ap = A + (size_t)arow * K + sseg;
    const u16* Bph = Bh + (size_t)(n0 + srow) * K + sseg;
    const u16* Bpl = Bl + (size_t)(n0 + srow) * K + sseg;

    const int a_r = ((lane>>3)&1)*8 + (lane&7), a_c = (lane>>4)*8;
    const int b_r = (lane>>4)*8 + (lane&7),     b_c = ((lane>>3)&1)*8;
    const u32 bAh = (u32)__cvta_generic_to_shared(Ahs);
    const u32 bAl = (u32)__cvta_generic_to_shared(Als);
    const u32 bBh = (u32)__cvta_generic_to_shared(Bhs);
    const u32 bBl = (u32)__cvta_generic_to_shared(Bls);

    float acc[2][8][4];
    #pragma unroll
    for (int i = 0; i < 2; i++)
        #pragma unroll
        for (int j = 0; j < 8; j++)
            #pragma unroll
            for (int q = 0; q < 4; q++) acc[i][j][q] = 0.0f;

    const int iters = K >> 4;
    float4 a0R = *(const float4*)Ap, a1R = *(const float4*)(Ap + 4);
    uint4 bhR = *(const uint4*)Bph, blR = *(const uint4*)Bpl;

    for (int kt = 0; kt < iters; kt++) {
        u32 h0,l0,h1,l1,h2,l2,h3,l3;
        split2(a0R.x,a0R.y,h0,l0); split2(a0R.z,a0R.w,h1,l1);
        split2(a1R.x,a1R.y,h2,l2); split2(a1R.z,a1R.w,h3,l3);
        *(uint4*)&Ahs[srow*24 + sseg] = make_uint4(h0,h1,h2,h3);
        *(uint4*)&Als[srow*24 + sseg] = make_uint4(l0,l1,l2,l3);
        *(uint4*)&Bhs[srow*24 + sseg] = bhR;
        *(uint4*)&Bls[srow*24 + sseg] = blR;
        __syncthreads();
        if (kt + 1 < iters) {
            a0R = *(const float4*)(Ap + (kt+1)*16);
            a1R = *(const float4*)(Ap + (kt+1)*16 + 4);
            bhR = *(const uint4*)(Bph + (kt+1)*16);
            blR = *(const uint4*)(Bpl + (kt+1)*16);
        }
        u32 ah[2][4], al[2][4];
        #pragma unroll
        for (int mt = 0; mt < 2; mt++) {
            u32 off = (u32)(((wr*32 + mt*16 + a_r)*24 + a_c) * 2);
            ldsm4(ah[mt], bAh + off);
            ldsm4(al[mt], bAl + off);
        }
        #pragma unroll
        for (int ntp = 0; ntp < 4; ntp++) {
            u32 off = (u32)(((wc*64 + ntp*16 + b_r)*24 + b_c) * 2);
            u32 bh4[4], bl4[4];
            ldsm4(bh4, bBh + off);
            ldsm4(bl4, bBl + off);
            #pragma unroll
            for (int e = 0; e < 2; e++) {
                int nt = ntp*2 + e;
                #pragma unroll
                for (int mt = 0; mt < 2; mt++) {
                    mma16816(acc[mt][nt], ah[mt], bh4[e*2], bh4[e*2+1]);
                    mma16816(acc[mt][nt], ah[mt], bl4[e*2], bl4[e*2+1]);
                    mma16816(acc[mt][nt], al[mt], bh4[e*2], bh4[e*2+1]);
                }
            }
        }
        __syncthreads();
    }
    #pragma unroll
    for (int mt = 0; mt < 2; mt++)
        #pragma unroll
        for (int nt = 0; nt < 8; nt++) {
            int m = m0 + wr*32 + mt*16 + g;
            int n = n0 + wc*64 + nt*8 + tg*2;
            float b0v = bias[n], b1v = bias[n+1];
            float* p = C + (size_t)m * N + n;
            *(float2*)p = make_float2(acc[mt][nt][0] + b0v, acc[mt][nt][1] + b1v);
            *(float2*)(p + (size_t)8*N) = make_float2(acc[mt][nt][2] + b0v, acc[mt][nt][3] + b1v);
        }
}

// ---------- persistent encoder ----------
__global__ void __launch_bounds__(256) enc_persist()
{
    const int bk = blockIdx.x, tid = threadIdx.x, lane = tid & 31, wid = tid >> 5;
    const int g = lane >> 2, tg = lane & 3;
    const int bb = tid >> 3, jl = tid & 7;
    const int j = bk*8 + jl;
    __shared__ float red[8][32*33];

    { int i = bk*256 + tid;
      if (i < 16384) { ((u32*)g_ehf[0][0])[i] = 0u; ((u32*)g_ehf[0][1])[i] = 0u; } }
    float cst = 0.0f;
    gbar();

    for (int t = 0; t < Sn; t++) {
        const int rp = t & 1, wp2 = rp ^ 1;
        const uint4* Ah = g_ehf[rp][0];
        const uint4* Al = g_ehf[rp][1];
        float acc[2][4][4];
        #pragma unroll
        for (int a = 0; a < 2; a++)
            #pragma unroll
            for (int b = 0; b < 4; b++)
                #pragma unroll
                for (int q = 0; q < 4; q++) acc[a][b][q] = 0.0f;

        #pragma unroll
        for (int ks = 0; ks < 8; ks++) {
            const int c = wid*8 + ks;
            uint4 fh0 = Ah[(c*2)*32 + lane],   fh1 = Ah[(c*2+1)*32 + lane];
            uint4 fl0 = Al[(c*2)*32 + lane],   fl1 = Al[(c*2+1)*32 + lane];
            #pragma unroll
            for (int nt = 0; nt < 4; nt++) {
                uint4 wq = w_hhE_f[((size_t)(nt*128 + bk)*64 + c)*32 + lane];
                mma16816(acc[0][nt], (u32*)&fh0, wq.x, wq.y);
                mma16816(acc[0][nt], (u32*)&fh0, wq.z, wq.w);
                mma16816(acc[0][nt], (u32*)&fl0, wq.x, wq.y);
                mma16816(acc[1][nt], (u32*)&fh1, wq.x, wq.y);
                mma16816(acc[1][nt], (u32*)&fh1, wq.z, wq.w);
                mma16816(acc[1][nt], (u32*)&fl1, wq.x, wq.y);
            }
        }
        #pragma unroll
        for (int mt = 0; mt < 2; mt++)
            #pragma unroll
            for (int nt = 0; nt < 4; nt++) {
                int r0 = mt*16 + g, c0 = nt*8 + tg*2;
                red[wid][r0*33 + c0]       = acc[mt][nt][0];
                red[wid][r0*33 + c0 + 1]   = acc[mt][nt][1];
                red[wid][(r0+8)*33 + c0]   = acc[mt][nt][2];
                red[wid][(r0+8)*33 + c0+1] = acc[mt][nt][3];
            }
        __syncthreads();

        float gi = 0.f, gf = 0.f, gg = 0.f, go = 0.f;
        #pragma unroll
        for (int w = 0; w < 8; w++) {
            const float* rw = &red[w][bb*33];
            gi += rw[jl]; gf += rw[8+jl]; gg += rw[16+jl]; go += rw[24+jl];
        }
        const size_t xw = ((size_t)(bb*Sn + t))*Gn + bk*8 + jl;
        gi += g_XWenc[xw]; gf += g_XWenc[xw+1024]; gg += g_XWenc[xw+2048]; go += g_XWenc[xw+3072];
        cst = sigm(gf)*cst + sigm(gi)*tanhf(gg);
        float h = sigm(go)*tanhf(cst);
        g_enc_out[((size_t)(bb*Sn + t))*Hn + j] = h;
        frag_store((u16*)g_ehf[wp2][0], (u16*)g_ehf[wp2][1], bb, j, h);
        if (t == Sn-1) { g_h[bb*Hn + j] = h; g_c[bb*Hn + j] = cst; }
        gbar();
    }
}

// ---------- persistent decoder ----------
__global__ void __launch_bounds__(256) dec_persist(const float* __restrict__ cls1_b)
{
    const int bk = blockIdx.x, tid = threadIdx.x, lane = tid & 31, wid = tid >> 5;
    const int g = lane >> 2, tg = lane & 3;
    const int bb = tid >> 3, jl = tid & 7;
    const int j = bk*8 + jl;
    __shared__ float red[8][32*33];
    float* sc    = &red[0][0];
    float* wsm   = sc + 3200;
    float* stats = wsm + 3200;

    { int i = bk*256 + tid;
      float h0 = g_h[i];
      int row = i >> 10, col = i & 1023;
      frag_store((u16*)g_dhf[0][0], (u16*)g_dhf[0][1], row, col, h0);
      frag_store((u16*)g_fdf[0][0], (u16*)g_fdf[0][1], row, col, h0); }
    float cst = g_c[bb*Hn + j];
    gbar();

    for (int t = 0; t < Tn; t++) {
        const int rp = t & 1, wp2 = rp ^ 1;

        // P1: gates + cell
        {
            const uint4 *Ah, *Al, *Wf;
            int cb;
            if (wid < 4) { Ah = g_fdf[rp][0]; Al = g_fdf[rp][1]; Wf = w_ihDH_f; cb = wid*16; }
            else         { Ah = g_dhf[rp][0]; Al = g_dhf[rp][1]; Wf = w_hhD_f;  cb = (wid-4)*16; }
            float acc[2][4][4];
            #pragma unroll
            for (int a = 0; a < 2; a++)
                #pragma unroll
                for (int b = 0; b < 4; b++)
                    #pragma unroll
                    for (int q = 0; q < 4; q++) acc[a][b][q] = 0.0f;
            #pragma unroll
            for (int ks = 0; ks < 16; ks++) {
                const int c = cb + ks;
                uint4 fh0 = Ah[(c*2)*32 + lane],   fh1 = Ah[(c*2+1)*32 + lane];
                uint4 fl0 = Al[(c*2)*32 + lane],   fl1 = Al[(c*2+1)*32 + lane];
                #pragma unroll
                for (int nt = 0; nt < 4; nt++) {
                    uint4 wq = Wf[((size_t)(nt*128 + bk)*64 + c)*32 + lane];
                    mma16816(acc[0][nt], (u32*)&fh0, wq.x, wq.y);
                    mma16816(acc[0][nt], (u32*)&fh0, wq.z, wq.w);
                    mma16816(acc[0][nt], (u32*)&fl0, wq.x, wq.y);
                    mma16816(acc[1][nt], (u32*)&fh1, wq.x, wq.y);
                    mma16816(acc[1][nt], (u32*)&fh1, wq.z, wq.w);
                    mma16816(acc[1][nt], (u32*)&fl1, wq.x, wq.y);
                }
            }
            #pragma unroll
            for (int mt = 0; mt < 2; mt++)
                #pragma unroll
                for (int nt = 0; nt < 4; nt++) {
                    int r0 = mt*16 + g, c0 = nt*8 + tg*2;
                    red[wid][r0*33 + c0]       = acc[mt][nt][0];
                    red[wid][r0*33 + c0 + 1]   = acc[mt][nt][1];
                    red[wid][(r0+8)*33 + c0]   = acc[mt][nt][2];
                    red[wid][(r0+8)*33 + c0+1] = acc[mt][nt][3];
                }
            __syncthreads();
            float gi = 0.f, gf = 0.f, gg = 0.f, go = 0.f;
            #pragma unroll
            for (int w = 0; w < 8; w++) {
                const float* rw = &red[w][bb*33];
                gi += rw[jl]; gf += rw[8+jl]; gg += rw[16+jl]; go += rw[24+jl];
            }
            const size_t xw = ((size_t)(bb*Tn + t))*Gn + bk*8 + jl;
            gi += g_XWdec[xw]; gf += g_XWdec[xw+1024]; gg += g_XWdec[xw+2048]; go += g_XWdec[xw+3072];
            cst = sigm(gf)*cst + sigm(gi)*tanhf(gg);
            float h = sigm(go)*tanhf(cst);
            g_hdf[bb*Hn + j] = h;
            frag_store((u16*)g_dhf[wp2][0], (u16*)g_dhf[wp2][1], bb, j, h);
        }
        gbar();

        // P2: scores
        #pragma unroll
        for (int r = 0; r < 4; r++) {
            int pair = bk*8 + wid + r*1024;
            if (pair < Bn*Sn) {
                int b = pair / Sn;
                const float* ep = g_enc_proj + (size_t)pair * Hn;
                const float* hv = g_hdf + b * Hn;
                float a = 0.f;
                #pragma unroll 4
                for (int k = lane; k < Hn; k += 32) a += ep[k] * hv[k];
                #pragma unroll
                for (int o = 16; o; o >>= 1) a += __shfl_xor_sync(0xffffffffu, a, o);
                if (lane == 0) g_scores[pair] = a;
            }
        }
        gbar();

        // P3: softmax + context
        for (int i = tid; i < Bn*Sn; i += 256) sc[i] = g_scores[i];
        __syncthreads();
        #pragma unroll
        for (int q = 0; q < 4; q++) {
            int b = wid*4 + q;
            float m = -1e30f;
            for (int s = lane; s < Sn; s += 32) m = fmaxf(m, sc[b*Sn + s]);
            #pragma unroll
            for (int o = 16; o; o >>= 1) m = fmaxf(m, __shfl_xor_sync(0xffffffffu, m, o));
            float su = 0.f;
            for (int s = lane; s < Sn; s += 32) su += expf(sc[b*Sn + s] - m);
            #pragma unroll
            for (int o = 16; o; o >>= 1) su += __shfl_xor_sync(0xffffffffu, su, o);
            if (lane == 0) { stats[b] = m; stats[32 + b] = 1.0f / su; }
        }
        __syncthreads();
        for (int i = tid; i < Bn*Sn; i += 256) {
            int b = i / Sn;
            wsm[i] = expf(sc[i] - stats[b]) * stats[32 + b];
        }
        __syncthreads();
        {
            float a = 0.f;
            const float* eo = g_enc_out + ((size_t)bb*Sn) * Hn + j;
            const float* wv = wsm + bb*Sn;
            #pragma unroll 4
            for (int s = 0; s < Sn; s++) a += wv[s] * eo[(size_t)s * Hn];
            frag_store((u16*)g_atf[0], (u16*)g_atf[1], bb, j, a);
        }
        gbar();

        // P4: feed = tanh([atten, hd] @ cls1 + b)
        {
            const uint4 *Ah, *Al;
            int cb, cw;
            if (wid < 4) { Ah = g_atf[0];      Al = g_atf[1];      cb = wid*16;     cw = 0; }
            else         { Ah = g_dhf[wp2][0]; Al = g_dhf[wp2][1]; cb = (wid-4)*16; cw = 64; }
            float fa[2][4];
            #pragma unroll
            for (int a = 0; a < 2; a++)
                #pragma unroll
                for (int q = 0; q < 4; q++) fa[a][q] = 0.0f;
            #pragma unroll
            for (int ks = 0; ks < 16; ks++) {
                const int c = cb + ks;
                uint4 fh0 = Ah[(c*2)*32 + lane],   fh1 = Ah[(c*2+1)*32 + lane];
                uint4 fl0 = Al[(c*2)*32 + lane],   fl1 = Al[(c*2+1)*32 + lane];
                uint4 wq = w_c1_f[((size_t)bk*128 + cw + c)*32 + lane];
                mma16816(fa[0], (u32*)&fh0, wq.x, wq.y);
                mma16816(fa[0], (u32*)&fh0, wq.z, wq.w);
                mma16816(fa[0], (u32*)&fl0, wq.x, wq.y);
                mma16816(fa[1], (u32*)&fh1, wq.x, wq.y);
                mma16816(fa[1], (u32*)&fh1, wq.z, wq.w);
                mma16816(fa[1], (u32*)&fl1, wq.x, wq.y);
            }
            #pragma unroll
            for (int mt = 0; mt < 2; mt++) {
                int r0 = mt*16 + g, c0 = tg*2;
                red[wid][r0*33 + c0]       = fa[mt][0];
                red[wid][r0*33 + c0 + 1]   = fa[mt][1];
                red[wid][(r0+8)*33 + c0]   = fa[mt][2];
                red[wid][(r0+8)*33 + c0+1] = fa[mt][3];
            }
            __syncthreads();
            float a = cls1_b[j];
            #pragma unroll
            for (int w = 0; w < 8; w++) a += red[w][bb*33 + jl];
            float f = tanhf(a);
            frag_store((u16*)g_fdf[wp2][0], (u16*)g_fdf[wp2][1], bb, j, f);
            g_hidden[((size_t)(bb*Tn + t))*Hn + j] = f;
        }
        gbar();
    }
}

extern "C" void kernel_launch(void* const* d_in, const int* in_sizes, int n_in,
                              void* d_out, int out_size)
{
    const int*   source_data = (const int*)  d_in[0];
    const int*   target_data = (const int*)  d_in[1];
    const float* src_emb  = (const float*)d_in[2];
    const float* tgt_emb  = (const float*)d_in[3];
    const float* enc_Wih  = (const float*)d_in[4];
    const float* enc_Whh  = (const float*)d_in[5];
    const float* enc_b    = (const float*)d_in[6];
    const float* dec_Wih  = (const float*)d_in[7];
    const float* dec_Whh  = (const float*)d_in[8];
    const float* dec_b    = (const float*)d_in[9];
    const float* att1_W   = (const float*)d_in[10];
    const float* att1_b   = (const float*)d_in[11];
    const float* cls1_W   = (const float*)d_in[12];
    const float* cls1_b   = (const float*)d_in[13];
    const float* cls2_W   = (const float*)d_in[14];
    const float* cls2_b   = (const float*)d_in[15];
    float* out = (float*)d_out;

    float *XWenc, *XWdec, *enc_out, *enc_proj, *hidden;
    void *ihE_h,*ihE_l,*ihD0_h,*ihD0_l,*att_h,*att_l,*c2_h,*c2_l;
    void *hhE_f,*ihDH_f,*hhD_f,*c1_f;
    cudaGetSymbolAddress((void**)&XWenc,   g_XWenc);
    cudaGetSymbolAddress((void**)&XWdec,   g_XWdec);
    cudaGetSymbolAddress((void**)&enc_out, g_enc_out);
    cudaGetSymbolAddress((void**)&enc_proj,g_enc_proj);
    cudaGetSymbolAddress((void**)&hidden,  g_hidden);
    cudaGetSymbolAddress(&ihE_h,  w_ihE_h);  cudaGetSymbolAddress(&ihE_l,  w_ihE_l);
    cudaGetSymbolAddress(&ihD0_h, w_ihD0_h); cudaGetSymbolAddress(&ihD0_l, w_ihD0_l);
    cudaGetSymbolAddress(&att_h,  w_att_h);  cudaGetSymbolAddress(&att_l,  w_att_l);
    cudaGetSymbolAddress(&c2_h,   w_c2_h);   cudaGetSymbolAddress(&c2_l,   w_c2_l);
    cudaGetSymbolAddress(&hhE_f,  w_hhE_f);  cudaGetSymbolAddress(&ihDH_f, w_ihDH_f);
    cudaGetSymbolAddress(&hhD_f,  w_hhD_f);  cudaGetSymbolAddress(&c1_f,   w_c1_f);

    CJobs jb;
    jb.j[0] = { enc_Wih,                    ihE_h,  ihE_l,   512, 4096, 0, 0     };
    jb.j[1] = { dec_Wih,                    ihD0_h, ihD0_l,  512, 4096, 0, 2048  };
    jb.j[2] = { att1_W,                     att_h,  att_l,  1024, 1024, 0, 4096  };
    jb.j[3] = { cls2_W,                     c2_h,   c2_l,   1024, Vn,   0, 5120  };
    jb.j[4] = { enc_Whh,                    hhE_f,  nullptr,1024, 4096, 1, 37120 };
    jb.j[5] = { dec_Wih + (size_t)512*4096, ihDH_f, nullptr,1024, 4096, 1, 41216 };
    jb.j[6] = { dec_Whh,                    hhD_f,  nullptr,1024, 4096, 1, 45312 };
    jb.j[7] = { cls1_W,                     c1_f,   nullptr,2048, 1024, 1, 49408 };
    conv_all<<<51456, 256>>>(jb);                                              // 1

    gemm_big<<<dim3(25, 32), 256>>>(src_emb, source_data,
        (u16*)ihE_h, (u16*)ihE_l, enc_b, XWenc, Gn, En);                       // 2
    gemm_big<<<dim3(25, 32), 256>>>(tgt_emb, target_data,
        (u16*)ihD0_h, (u16*)ihD0_l, dec_b, XWdec, Gn, En);                     // 3
    enc_persist<<<NBLK, 256>>>();                                              // 4
    gemm_big<<<dim3(25, 8), 256>>>(enc_out, nullptr,
        (u16*)att_h, (u16*)att_l, att1_b, enc_proj, Hn, Hn);                   // 5
    dec_persist<<<NBLK, 256>>>(cls1_b);                                        // 6  <- ncu
    gemm_big<<<dim3(25, 250), 256>>>(hidden, nullptr,
        (u16*)c2_h, (u16*)c2_l, cls2_b, out, Vn, Hn);                          // 7
}

// round 7
// speedup vs baseline: 2.0129x; 1.2554x over previous
#include <cuda_runtime.h>
#include <cuda_bf16.h>
#include <math.h>
#include <stdint.h>

typedef unsigned short u16;
typedef unsigned int   u32;

#define Bn 32
#define Sn 100
#define Tn 100
#define En 512
#define Hn 1024
#define Vn 32000
#define Gn 4096
#define NBLK 128
#define RED_F (16*1056)   // dynamic smem floats for persistent kernels

// fp32 scratch
__device__ float g_XWenc[Bn*Sn*Gn];
__device__ float g_XWdec[Bn*Tn*Gn];
__device__ float g_enc_out[Bn*Sn*Hn];
__device__ float g_enc_proj[Bn*Sn*Hn];
__device__ float g_hidden[Bn*Tn*Hn];
__device__ float g_h[Bn*Hn];
__device__ float g_c[Bn*Hn];
__device__ float g_hdf[Bn*Hn];
__device__ float g_scores[Bn*Sn];

// fragment-major state: uint4 idx = (chunk*2+mt)*32+lane, chunk=k16
__device__ uint4 g_ehf[2][2][4096];
__device__ uint4 g_dhf[2][2][4096];
__device__ uint4 g_fdf[2][2][4096];
__device__ uint4 g_atf[2][4096];

// plain transposed [n][k] bf16 weights (for gemm_big)
__device__ u16 w_ihE_h [(size_t)Gn*En],  w_ihE_l [(size_t)Gn*En];
__device__ u16 w_ihD0_h[(size_t)Gn*En],  w_ihD0_l[(size_t)Gn*En];
__device__ u16 w_att_h [(size_t)Hn*Hn],  w_att_l [(size_t)Hn*Hn];
__device__ u16 w_c2_h  [(size_t)Vn*Hn],  w_c2_l  [(size_t)Vn*Hn];

// fragment-major weights: uint4 {b0h,b1h,b0l,b1l}, idx = (ng*nch + c)*32 + lane
__device__ uint4 w_hhE_f [512*64*32];
__device__ uint4 w_ihDH_f[512*64*32];
__device__ uint4 w_hhD_f [512*64*32];
__device__ uint4 w_c1_f  [128*128*32];

__device__ unsigned g_cnt, g_gen;
__device__ __forceinline__ void gbar() {
    __syncthreads();
    if (threadIdx.x == 0) {
        __threadfence();
        unsigned my = *((volatile unsigned*)&g_gen);
        unsigned a = atomicAdd(&g_cnt, 1u);
        if (a == NBLK - 1u) { g_cnt = 0u; __threadfence(); *((volatile unsigned*)&g_gen) = my + 1u; }
        else { while (*((volatile unsigned*)&g_gen) == my) {} }
        __threadfence();
    }
    __syncthreads();
}

__device__ __forceinline__ float sigm(float x){ return 1.0f/(1.0f + expf(-x)); }
__device__ __forceinline__ u16 bhi(float v){ return __bfloat16_as_ushort(__float2bfloat16(v)); }
__device__ __forceinline__ u16 blo(float v){
    __nv_bfloat16 h = __float2bfloat16(v);
    return __bfloat16_as_ushort(__float2bfloat16(v - __bfloat162float(h)));
}
__device__ __forceinline__ u32 pack2(u16 a, u16 b){ return (u32)a | ((u32)b << 16); }
__device__ __forceinline__ void split2(float x, float y, u32& hp, u32& lp) {
    hp = pack2(bhi(x), bhi(y)); lp = pack2(blo(x), blo(y));
}
__device__ __forceinline__ void mma16816(float* c, const u32* a, u32 b0, u32 b1) {
    asm volatile("mma.sync.aligned.m16n8k16.row.col.f32.bf16.bf16.f32 "
        "{%0,%1,%2,%3},{%4,%5,%6,%7},{%8,%9},{%0,%1,%2,%3};"
        : "+f"(c[0]), "+f"(c[1]), "+f"(c[2]), "+f"(c[3])
        : "r"(a[0]), "r"(a[1]), "r"(a[2]), "r"(a[3]), "r"(b0), "r"(b1));
}
__device__ __forceinline__ void ldsm4(u32* r, u32 addr) {
    asm volatile("ldmatrix.sync.aligned.m8n8.x4.shared.b16 {%0,%1,%2,%3}, [%4];"
        : "=r"(r[0]), "=r"(r[1]), "=r"(r[2]), "=r"(r[3]) : "r"(addr));
}
__device__ __forceinline__ void frag_store(u16* Fh, u16* Fl, int row, int col, float v){
    int ch = col >> 4, kc = col & 15, mt = row >> 4, rg = row & 15;
    int lane = (rg & 7)*4 + ((kc >> 1) & 3);
    int w = ((kc >> 3) << 1) + (rg >> 3);
    size_t idx = ((size_t)(((ch*2 + mt)*32) + lane) << 3) + (w << 1) + (kc & 1);
    __nv_bfloat16 h = __float2bfloat16(v);
    Fh[idx] = __bfloat16_as_ushort(h);
    Fl[idx] = __bfloat16_as_ushort(__float2bfloat16(v - __bfloat162float(h)));
}

// ---------- merged conversion ----------
struct CJ { const float* W; void* Oh; void* Ol; int K, N, mode, boff; };
struct CJobs { CJ j[8]; };

__global__ void __launch_bounds__(256) conv_all(CJobs jb)
{
    __shared__ float tile[32][33];
    int blk = blockIdx.x, ji = 0;
    #pragma unroll
    for (int i = 7; i >= 0; i--) if (blk >= jb.j[i].boff) { ji = i; break; }
    const CJ& J = jb.j[ji];
    int local = blk - J.boff;
    const int tid = threadIdx.x, lane = tid & 31;
    if (J.mode == 0) {
        int ntl = J.N >> 5;
        int tk = local / ntl, tn = local % ntl;
        int n0 = tn*32, k0 = tk*32;
        int tx = lane, ty = tid >> 5;
        #pragma unroll
        for (int i = 0; i < 4; i++)
            tile[ty + i*8][tx] = J.W[(size_t)(k0 + ty + i*8)*J.N + n0 + tx];
        __syncthreads();
        u16* Oh = (u16*)J.Oh; u16* Ol = (u16*)J.Ol;
        #pragma unroll
        for (int i = 0; i < 4; i++) {
            int nn = ty + i*8;
            float v = tile[tx][nn];
            Oh[(size_t)(n0+nn)*J.K + k0 + tx] = bhi(v);
            Ol[(size_t)(n0+nn)*J.K + k0 + tx] = blo(v);
        }
    } else {
        int nch = J.K >> 4;
        int pair = local*8 + (tid >> 5);
        int ng = pair / nch, c = pair % nch;
        int n = ng*8 + (lane >> 2), k = c*16 + (lane & 3)*2;
        const float* W = J.W;
        float v0 = W[(size_t)k*J.N + n],     v1 = W[(size_t)(k+1)*J.N + n];
        float v2 = W[(size_t)(k+8)*J.N + n], v3 = W[(size_t)(k+9)*J.N + n];
        ((uint4*)J.Oh)[(size_t)pair*32 + lane] =
            make_uint4(pack2(bhi(v0),bhi(v1)), pack2(bhi(v2),bhi(v3)),
                       pack2(blo(v0),blo(v1)), pack2(blo(v2),blo(v3)));
    }
}

// ---------- big GEMM with ldmatrix (unchanged from R6) ----------
__global__ void __launch_bounds__(256) gemm_big(
    const float* __restrict__ A, const int* __restrict__ gather,
    const u16* __restrict__ Bh, const u16* __restrict__ Bl,
    const float* __restrict__ bias, float* __restrict__ C, int N, int K)
{
    __shared__ __align__(16) u16 Ahs[128*24], Als[128*24], Bhs[128*24], Bls[128*24];
    const int t = threadIdx.x, lane = t & 31, wid = t >> 5;
    const int wr = wid & 3, wc = wid >> 2;
    const int g = lane >> 2, tg = lane & 3;
    const int m0 = blockIdx.x * 128, n0 = blockIdx.y * 128;

    const int srow = t >> 1, sseg = (t & 1) * 8;
    const int arow = gather ? gather[m0 + srow] : (m0 + srow);
    const float* Ap = A + (size_t)arow * K + sseg;
    const u16* Bph = Bh + (size_t)(n0 + srow) * K + sseg;
    const u16* Bpl = Bl + (size_t)(n0 + srow) * K + sseg;

    const int a_r = ((lane>>3)&1)*8 + (lane&7), a_c = (lane>>4)*8;
    const int b_r = (lane>>4)*8 + (lane&7),     b_c = ((lane>>3)&1)*8;
    const u32 bAh = (u32)__cvta_generic_to_shared(Ahs);
    const u32 bAl = (u32)__cvta_generic_to_shared(Als);
    const u32 bBh = (u32)__cvta_generic_to_shared(Bhs);
    const u32 bBl = (u32)__cvta_generic_to_shared(Bls);

    float acc[2][8][4];
    #pragma unroll
    for (int i = 0; i < 2; i++)
        #pragma unroll
        for (int j = 0; j < 8; j++)
            #pragma unroll
            for (int q = 0; q < 4; q++) acc[i][j][q] = 0.0f;

    const int iters = K >> 4;
    float4 a0R = *(const float4*)Ap, a1R = *(const float4*)(Ap + 4);
    uint4 bhR = *(const uint4*)Bph, blR = *(const uint4*)Bpl;

    for (int kt = 0; kt < iters; kt++) {
        u32 h0,l0,h1,l1,h2,l2,h3,l3;
        split2(a0R.x,a0R.y,h0,l0); split2(a0R.z,a0R.w,h1,l1);
        split2(a1R.x,a1R.y,h2,l2); split2(a1R.z,a1R.w,h3,l3);
        *(uint4*)&Ahs[srow*24 + sseg] = make_uint4(h0,h1,h2,h3);
        *(uint4*)&Als[srow*24 + sseg] = make_uint4(l0,l1,l2,l3);
        *(uint4*)&Bhs[srow*24 + sseg] = bhR;
        *(uint4*)&Bls[srow*24 + sseg] = blR;
        __syncthreads();
        if (kt + 1 < iters) {
            a0R = *(const float4*)(Ap + (kt+1)*16);
            a1R = *(const float4*)(Ap + (kt+1)*16 + 4);
            bhR = *(const uint4*)(Bph + (kt+1)*16);
            blR = *(const uint4*)(Bpl + (kt+1)*16);
        }
        u32 ah[2][4], al[2][4];
        #pragma unroll
        for (int mt = 0; mt < 2; mt++) {
            u32 off = (u32)(((wr*32 + mt*16 + a_r)*24 + a_c) * 2);
            ldsm4(ah[mt], bAh + off);
            ldsm4(al[mt], bAl + off);
        }
        #pragma unroll
        for (int ntp = 0; ntp < 4; ntp++) {
            u32 off = (u32)(((wc*64 + ntp*16 + b_r)*24 + b_c) * 2);
            u32 bh4[4], bl4[4];
            ldsm4(bh4, bBh + off);
            ldsm4(bl4, bBl + off);
            #pragma unroll
            for (int e = 0; e < 2; e++) {
                int nt = ntp*2 + e;
                #pragma unroll
                for (int mt = 0; mt < 2; mt++) {
                    mma16816(acc[mt][nt], ah[mt], bh4[e*2], bh4[e*2+1]);
                    mma16816(acc[mt][nt], ah[mt], bl4[e*2], bl4[e*2+1]);
                    mma16816(acc[mt][nt], al[mt], bh4[e*2], bh4[e*2+1]);
                }
            }
        }
        __syncthreads();
    }
    #pragma unroll
    for (int mt = 0; mt < 2; mt++)
        #pragma unroll
        for (int nt = 0; nt < 8; nt++) {
            int m = m0 + wr*32 + mt*16 + g;
            int n = n0 + wc*64 + nt*8 + tg*2;
            float b0v = bias[n], b1v = bias[n+1];
            float* p = C + (size_t)m * N + n;
            *(float2*)p = make_float2(acc[mt][nt][0] + b0v, acc[mt][nt][1] + b1v);
            *(float2*)(p + (size_t)8*N) = make_float2(acc[mt][nt][2] + b0v, acc[mt][nt][3] + b1v);
        }
}

// ---------- persistent encoder: 512 threads, 16 warps ----------
__global__ void __launch_bounds__(512) enc_persist()
{
    extern __shared__ float red_[];
    const int bk = blockIdx.x, tid = threadIdx.x, lane = tid & 31, wid = tid >> 5;
    const int g = lane >> 2, tg = lane & 3;

    { int i = bk*512 + tid;
      if (i < 16384) { ((u32*)g_ehf[0][0])[i] = 0u; ((u32*)g_ehf[0][1])[i] = 0u; } }
    float cst = 0.0f;
    gbar();

    for (int t = 0; t < Sn; t++) {
        const int rp = t & 1, wp2 = rp ^ 1;
        const uint4* Ah = g_ehf[rp][0];
        const uint4* Al = g_ehf[rp][1];
        float acc[2][4][4];
        #pragma unroll
        for (int a = 0; a < 2; a++)
            #pragma unroll
            for (int b = 0; b < 4; b++)
                #pragma unroll
                for (int q = 0; q < 4; q++) acc[a][b][q] = 0.0f;

        #pragma unroll
        for (int ks = 0; ks < 4; ks++) {
            const int c = wid*4 + ks;
            uint4 fh0 = Ah[(c*2)*32 + lane],   fh1 = Ah[(c*2+1)*32 + lane];
            uint4 fl0 = Al[(c*2)*32 + lane],   fl1 = Al[(c*2+1)*32 + lane];
            #pragma unroll
            for (int nt = 0; nt < 4; nt++) {
                uint4 wq = w_hhE_f[((size_t)(nt*128 + bk)*64 + c)*32 + lane];
                mma16816(acc[0][nt], (u32*)&fh0, wq.x, wq.y);
                mma16816(acc[0][nt], (u32*)&fh0, wq.z, wq.w);
                mma16816(acc[0][nt], (u32*)&fl0, wq.x, wq.y);
                mma16816(acc[1][nt], (u32*)&fh1, wq.x, wq.y);
                mma16816(acc[1][nt], (u32*)&fh1, wq.z, wq.w);
                mma16816(acc[1][nt], (u32*)&fl1, wq.x, wq.y);
            }
        }
        float* rw0 = &red_[wid*1056];
        #pragma unroll
        for (int mt = 0; mt < 2; mt++)
            #pragma unroll
            for (int nt = 0; nt < 4; nt++) {
                int r0 = mt*16 + g, c0 = nt*8 + tg*2;
                rw0[r0*33 + c0]       = acc[mt][nt][0];
                rw0[r0*33 + c0 + 1]   = acc[mt][nt][1];
                rw0[(r0+8)*33 + c0]   = acc[mt][nt][2];
                rw0[(r0+8)*33 + c0+1] = acc[mt][nt][3];
            }
        __syncthreads();

        if (tid < 256) {
            const int bb = tid >> 3, jl = tid & 7, j = bk*8 + jl;
            float gi = 0.f, gf = 0.f, gg = 0.f, go = 0.f;
            #pragma unroll
            for (int w = 0; w < 16; w++) {
                const float* rw = &red_[w*1056 + bb*33];
                gi += rw[jl]; gf += rw[8+jl]; gg += rw[16+jl]; go += rw[24+jl];
            }
            const size_t xw = ((size_t)(bb*Sn + t))*Gn + bk*8 + jl;
            gi += g_XWenc[xw]; gf += g_XWenc[xw+1024]; gg += g_XWenc[xw+2048]; go += g_XWenc[xw+3072];
            cst = sigm(gf)*cst + sigm(gi)*tanhf(gg);
            float h = sigm(go)*tanhf(cst);
            g_enc_out[((size_t)(bb*Sn + t))*Hn + j] = h;
            frag_store((u16*)g_ehf[wp2][0], (u16*)g_ehf[wp2][1], bb, j, h);
            if (t == Sn-1) { g_h[bb*Hn + j] = h; g_c[bb*Hn + j] = cst; }
        }
        gbar();
    }
}

// ---------- persistent decoder: 512 threads, 16 warps ----------
__global__ void __launch_bounds__(512) dec_persist(const float* __restrict__ cls1_b)
{
    extern __shared__ float red_[];
    const int bk = blockIdx.x, tid = threadIdx.x, lane = tid & 31, wid = tid >> 5;
    const int g = lane >> 2, tg = lane & 3;
    float* sc    = red_;
    float* wsm   = sc + 3200;
    float* stats = wsm + 3200;
    float* ctx   = stats + 64;

    { int i = bk*512 + tid;
      if (i < Bn*Hn) {
          float h0 = g_h[i];
          int row = i >> 10, col = i & 1023;
          frag_store((u16*)g_dhf[0][0], (u16*)g_dhf[0][1], row, col, h0);
          frag_store((u16*)g_fdf[0][0], (u16*)g_fdf[0][1], row, col, h0);
      } }
    float cst = (tid < 256) ? g_c[(tid>>3)*Hn + bk*8 + (tid&7)] : 0.0f;
    gbar();

    for (int t = 0; t < Tn; t++) {
        const int rp = t & 1, wp2 = rp ^ 1;

        // P1: gates + cell
        {
            const uint4 *Ah, *Al, *Wf;
            int cb;
            if (wid < 8) { Ah = g_fdf[rp][0]; Al = g_fdf[rp][1]; Wf = w_ihDH_f; cb = wid*8; }
            else         { Ah = g_dhf[rp][0]; Al = g_dhf[rp][1]; Wf = w_hhD_f;  cb = (wid-8)*8; }
            float acc[2][4][4];
            #pragma unroll
            for (int a = 0; a < 2; a++)
                #pragma unroll
                for (int b = 0; b < 4; b++)
                    #pragma unroll
                    for (int q = 0; q < 4; q++) acc[a][b][q] = 0.0f;
            #pragma unroll
            for (int ks = 0; ks < 8; ks++) {
                const int c = cb + ks;
                uint4 fh0 = Ah[(c*2)*32 + lane],   fh1 = Ah[(c*2+1)*32 + lane];
                uint4 fl0 = Al[(c*2)*32 + lane],   fl1 = Al[(c*2+1)*32 + lane];
                #pragma unroll
                for (int nt = 0; nt < 4; nt++) {
                    uint4 wq = Wf[((size_t)(nt*128 + bk)*64 + c)*32 + lane];
                    mma16816(acc[0][nt], (u32*)&fh0, wq.x, wq.y);
                    mma16816(acc[0][nt], (u32*)&fh0, wq.z, wq.w);
                    mma16816(acc[0][nt], (u32*)&fl0, wq.x, wq.y);
                    mma16816(acc[1][nt], (u32*)&fh1, wq.x, wq.y);
                    mma16816(acc[1][nt], (u32*)&fh1, wq.z, wq.w);
                    mma16816(acc[1][nt], (u32*)&fl1, wq.x, wq.y);
                }
            }
            float* rw0 = &red_[wid*1056];
            #pragma unroll
            for (int mt = 0; mt < 2; mt++)
                #pragma unroll
                for (int nt = 0; nt < 4; nt++) {
                    int r0 = mt*16 + g, c0 = nt*8 + tg*2;
                    rw0[r0*33 + c0]       = acc[mt][nt][0];
                    rw0[r0*33 + c0 + 1]   = acc[mt][nt][1];
                    rw0[(r0+8)*33 + c0]   = acc[mt][nt][2];
                    rw0[(r0+8)*33 + c0+1] = acc[mt][nt][3];
                }
            __syncthreads();
            if (tid < 256) {
                const int bb = tid >> 3, jl = tid & 7, j = bk*8 + jl;
                float gi = 0.f, gf = 0.f, gg = 0.f, go = 0.f;
                #pragma unroll
                for (int w = 0; w < 16; w++) {
                    const float* rw = &red_[w*1056 + bb*33];
                    gi += rw[jl]; gf += rw[8+jl]; gg += rw[16+jl]; go += rw[24+jl];
                }
                const size_t xw = ((size_t)(bb*Tn + t))*Gn + bk*8 + jl;
                gi += g_XWdec[xw]; gf += g_XWdec[xw+1024]; gg += g_XWdec[xw+2048]; go += g_XWdec[xw+3072];
                cst = sigm(gf)*cst + sigm(gi)*tanhf(gg);
                float h = sigm(go)*tanhf(cst);
                g_hdf[bb*Hn + j] = h;
                frag_store((u16*)g_dhf[wp2][0], (u16*)g_dhf[wp2][1], bb, j, h);
            }
        }
        gbar();

        // P2: scores (one warp per (b,s) pair)
        #pragma unroll
        for (int r = 0; r < 2; r++) {
            int pair = bk*16 + wid + r*2048;
            if (pair < Bn*Sn) {
                int b = pair / Sn;
                const float* ep = g_enc_proj + (size_t)pair * Hn;
                const float* hv = g_hdf + b * Hn;
                float a = 0.f;
                #pragma unroll 4
                for (int k = lane; k < Hn; k += 32) a += ep[k] * hv[k];
                #pragma unroll
                for (int o = 16; o; o >>= 1) a += __shfl_xor_sync(0xffffffffu, a, o);
                if (lane == 0) g_scores[pair] = a;
            }
        }
        gbar();

        // P3: softmax + context
        for (int i = tid; i < Bn*Sn; i += 512) sc[i] = g_scores[i];
        __syncthreads();
        #pragma unroll
        for (int q = 0; q < 2; q++) {
            int b = wid*2 + q;
            float m = -1e30f;
            for (int s = lane; s < Sn; s += 32) m = fmaxf(m, sc[b*Sn + s]);
            #pragma unroll
            for (int o = 16; o; o >>= 1) m = fmaxf(m, __shfl_xor_sync(0xffffffffu, m, o));
            float su = 0.f;
            for (int s = lane; s < Sn; s += 32) su += expf(sc[b*Sn + s] - m);
            #pragma unroll
            for (int o = 16; o; o >>= 1) su += __shfl_xor_sync(0xffffffffu, su, o);
            if (lane == 0) { stats[b] = m; stats[32 + b] = 1.0f / su; }
        }
        __syncthreads();
        for (int i = tid; i < Bn*Sn; i += 512) {
            int b = i / Sn;
            wsm[i] = expf(sc[i] - stats[b]) * stats[32 + b];
        }
        __syncthreads();
        {
            const int half = tid >> 8, ct = tid & 255;
            const int bb = ct >> 3, jl = ct & 7, j = bk*8 + jl;
            float a = 0.f;
            const float* eo = g_enc_out + ((size_t)bb*Sn) * Hn + j;
            const float* wv = wsm + bb*Sn;
            const int s0 = half*50;
            #pragma unroll 5
            for (int s = s0; s < s0 + 50; s++) a += wv[s] * eo[(size_t)s * Hn];
            ctx[tid] = a;
        }
        __syncthreads();
        if (tid < 256) {
            const int bb = tid >> 3, jl = tid & 7, j = bk*8 + jl;
            float a = ctx[tid] + ctx[256 + tid];
            frag_store((u16*)g_atf[0], (u16*)g_atf[1], bb, j, a);
        }
        gbar();

        // P4: feed = tanh([atten, hd] @ cls1 + b)
        {
            const uint4 *Ah, *Al;
            int cb, cw;
            if (wid < 8) { Ah = g_atf[0];      Al = g_atf[1];      cb = wid*8;     cw = 0; }
            else         { Ah = g_dhf[wp2][0]; Al = g_dhf[wp2][1]; cb = (wid-8)*8; cw = 64; }
            float fa[2][4];
            #pragma unroll
            for (int a = 0; a < 2; a++)
                #pragma unroll
                for (int q = 0; q < 4; q++) fa[a][q] = 0.0f;
            #pragma unroll
            for (int ks = 0; ks < 8; ks++) {
                const int c = cb + ks;
                uint4 fh0 = Ah[(c*2)*32 + lane],   fh1 = Ah[(c*2+1)*32 + lane];
                uint4 fl0 = Al[(c*2)*32 + lane],   fl1 = Al[(c*2+1)*32 + lane];
                uint4 wq = w_c1_f[((size_t)bk*128 + cw + c)*32 + lane];
                mma16816(fa[0], (u32*)&fh0, wq.x, wq.y);
                mma16816(fa[0], (u32*)&fh0, wq.z, wq.w);
                mma16816(fa[0], (u32*)&fl0, wq.x, wq.y);
                mma16816(fa[1], (u32*)&fh1, wq.x, wq.y);
                mma16816(fa[1], (u32*)&fh1, wq.z, wq.w);
                mma16816(fa[1], (u32*)&fl1, wq.x, wq.y);
            }
            float* rw0 = &red_[wid*1056];
            #pragma unroll
            for (int mt = 0; mt < 2; mt++) {
                int r0 = mt*16 + g, c0 = tg*2;
                rw0[r0*33 + c0]       = fa[mt][0];
                rw0[r0*33 + c0 + 1]   = fa[mt][1];
                rw0[(r0+8)*33 + c0]   = fa[mt][2];
                rw0[(r0+8)*33 + c0+1] = fa[mt][3];
            }
            __syncthreads();
            if (tid < 256) {
                const int bb = tid >> 3, jl = tid & 7, j = bk*8 + jl;
                float a = cls1_b[j];
                #pragma unroll
                for (int w = 0; w < 16; w++) a += red_[w*1056 + bb*33 + jl];
                float f = tanhf(a);
                frag_store((u16*)g_fdf[wp2][0], (u16*)g_fdf[wp2][1], bb, j, f);
                g_hidden[((size_t)(bb*Tn + t))*Hn + j] = f;
            }
        }
        gbar();
    }
}

extern "C" void kernel_launch(void* const* d_in, const int* in_sizes, int n_in,
                              void* d_out, int out_size)
{
    const int*   source_data = (const int*)  d_in[0];
    const int*   target_data = (const int*)  d_in[1];
    const float* src_emb  = (const float*)d_in[2];
    const float* tgt_emb  = (const float*)d_in[3];
    const float* enc_Wih  = (const float*)d_in[4];
    const float* enc_Whh  = (const float*)d_in[5];
    const float* enc_b    = (const float*)d_in[6];
    const float* dec_Wih  = (const float*)d_in[7];
    const float* dec_Whh  = (const float*)d_in[8];
    const float* dec_b    = (const float*)d_in[9];
    const float* att1_W   = (const float*)d_in[10];
    const float* att1_b   = (const float*)d_in[11];
    const float* cls1_W   = (const float*)d_in[12];
    const float* cls1_b   = (const float*)d_in[13];
    const float* cls2_W   = (const float*)d_in[14];
    const float* cls2_b   = (const float*)d_in[15];
    float* out = (float*)d_out;

    float *XWenc, *XWdec, *enc_out, *enc_proj, *hidden;
    void *ihE_h,*ihE_l,*ihD0_h,*ihD0_l,*att_h,*att_l,*c2_h,*c2_l;
    void *hhE_f,*ihDH_f,*hhD_f,*c1_f;
    cudaGetSymbolAddress((void**)&XWenc,   g_XWenc);
    cudaGetSymbolAddress((void**)&XWdec,   g_XWdec);
    cudaGetSymbolAddress((void**)&enc_out, g_enc_out);
    cudaGetSymbolAddress((void**)&enc_proj,g_enc_proj);
    cudaGetSymbolAddress((void**)&hidden,  g_hidden);
    cudaGetSymbolAddress(&ihE_h,  w_ihE_h);  cudaGetSymbolAddress(&ihE_l,  w_ihE_l);
    cudaGetSymbolAddress(&ihD0_h, w_ihD0_h); cudaGetSymbolAddress(&ihD0_l, w_ihD0_l);
    cudaGetSymbolAddress(&att_h,  w_att_h);  cudaGetSymbolAddress(&att_l,  w_att_l);
    cudaGetSymbolAddress(&c2_h,   w_c2_h);   cudaGetSymbolAddress(&c2_l,   w_c2_l);
    cudaGetSymbolAddress(&hhE_f,  w_hhE_f);  cudaGetSymbolAddress(&ihDH_f, w_ihDH_f);
    cudaGetSymbolAddress(&hhD_f,  w_hhD_f);  cudaGetSymbolAddress(&c1_f,   w_c1_f);

    static int attr_done = 0;
    if (!attr_done) {
        cudaFuncSetAttribute(enc_persist, cudaFuncAttributeMaxDynamicSharedMemorySize, RED_F*4);
        cudaFuncSetAttribute(dec_persist, cudaFuncAttributeMaxDynamicSharedMemorySize, RED_F*4);
        attr_done = 1;
    }

    CJobs jb;
    jb.j[0] = { enc_Wih,                    ihE_h,  ihE_l,   512, 4096, 0, 0     };
    jb.j[1] = { dec_Wih,                    ihD0_h, ihD0_l,  512, 4096, 0, 2048  };
    jb.j[2] = { att1_W,                     att_h,  att_l,  1024, 1024, 0, 4096  };
    jb.j[3] = { cls2_W,                     c2_h,   c2_l,   1024, Vn,   0, 5120  };
    jb.j[4] = { enc_Whh,                    hhE_f,  nullptr,1024, 4096, 1, 37120 };
    jb.j[5] = { dec_Wih + (size_t)512*4096, ihDH_f, nullptr,1024, 4096, 1, 41216 };
    jb.j[6] = { dec_Whh,                    hhD_f,  nullptr,1024, 4096, 1, 45312 };
    jb.j[7] = { cls1_W,                     c1_f,   nullptr,2048, 1024, 1, 49408 };
    conv_all<<<51456, 256>>>(jb);                                              // 1

    gemm_big<<<dim3(25, 32), 256>>>(src_emb, source_data,
        (u16*)ihE_h, (u16*)ihE_l, enc_b, XWenc, Gn, En);                       // 2
    gemm_big<<<dim3(25, 32), 256>>>(tgt_emb, target_data,
        (u16*)ihD0_h, (u16*)ihD0_l, dec_b, XWdec, Gn, En);                     // 3
    enc_persist<<<NBLK, 512, RED_F*4>>>();                                     // 4
    gemm_big<<<dim3(25, 8), 256>>>(enc_out, nullptr,
        (u16*)att_h, (u16*)att_l, att1_b, enc_proj, Hn, Hn);                   // 5
    dec_persist<<<NBLK, 512, RED_F*4>>>(cls1_b);                               // 6  <- ncu
    gemm_big<<<dim3(25, 250), 256>>>(hidden, nullptr,
        (u16*)c2_h, (u16*)c2_l, cls2_b, out, Vn, Hn);                          // 7
}

// round 9
// speedup vs baseline: 2.1083x; 1.0474x over previous
#include <cuda_runtime.h>
#include <cuda_bf16.h>
#include <math.h>
#include <stdint.h>

typedef unsigned short u16;
typedef unsigned int   u32;

#define Bn 32
#define Sn 100
#define Tn 100
#define En 512
#define Hn 1024
#define Vn 32000
#define Gn 4096
#define NBLK 128
#define RED_F (16*1056)   // dynamic smem floats for persistent kernels

// fp32 scratch
__device__ float g_XWenc[Bn*Sn*Gn];
__device__ float g_XWdec[Bn*Tn*Gn];
__device__ float g_enc_out[Bn*Sn*Hn];
__device__ float g_enc_proj[Bn*Sn*Hn];
__device__ float g_hidden[Bn*Tn*Hn];
__device__ float g_h[Bn*Hn];
__device__ float g_c[Bn*Hn];
__device__ float g_hdf[Bn*Hn];
__device__ float g_scores[Bn*Sn];

// fragment-major state: uint4 idx = (chunk*2+mt)*32+lane, chunk=k16
__device__ uint4 g_ehf[2][2][4096];
__device__ uint4 g_dhf[2][2][4096];
__device__ uint4 g_fdf[2][2][4096];
__device__ uint4 g_atf[2][4096];

// plain transposed [n][k] bf16 weights (for gemm_big)
__device__ u16 w_ihE_h [(size_t)Gn*En],  w_ihE_l [(size_t)Gn*En];
__device__ u16 w_ihD0_h[(size_t)Gn*En],  w_ihD0_l[(size_t)Gn*En];
__device__ u16 w_att_h [(size_t)Hn*Hn],  w_att_l [(size_t)Hn*Hn];
__device__ u16 w_c2_h  [(size_t)Vn*Hn],  w_c2_l  [(size_t)Vn*Hn];

// fragment-major weights: uint4 {b0h,b1h,b0l,b1l}, idx = (ng*nch + c)*32 + lane
__device__ uint4 w_hhE_f [512*64*32];
__device__ uint4 w_ihDH_f[512*64*32];
__device__ uint4 w_hhD_f [512*64*32];
__device__ uint4 w_c1_f  [128*128*32];

__device__ unsigned g_cnt, g_gen;
__device__ __forceinline__ void gbar() {
    __syncthreads();
    if (threadIdx.x == 0) {
        __threadfence();
        unsigned my = *((volatile unsigned*)&g_gen);
        unsigned a = atomicAdd(&g_cnt, 1u);
        if (a == NBLK - 1u) { g_cnt = 0u; __threadfence(); *((volatile unsigned*)&g_gen) = my + 1u; }
        else { while (*((volatile unsigned*)&g_gen) == my) {} }
        __threadfence();
    }
    __syncthreads();
}

__device__ __forceinline__ float sigm(float x){ return 1.0f/(1.0f + expf(-x)); }
__device__ __forceinline__ u16 bhi(float v){ return __bfloat16_as_ushort(__float2bfloat16(v)); }
__device__ __forceinline__ u16 blo(float v){
    __nv_bfloat16 h = __float2bfloat16(v);
    return __bfloat16_as_ushort(__float2bfloat16(v - __bfloat162float(h)));
}
__device__ __forceinline__ u32 pack2(u16 a, u16 b){ return (u32)a | ((u32)b << 16); }
__device__ __forceinline__ void split2(float x, float y, u32& hp, u32& lp) {
    hp = pack2(bhi(x), bhi(y)); lp = pack2(blo(x), blo(y));
}
__device__ __forceinline__ void mma16816(float* c, const u32* a, u32 b0, u32 b1) {
    asm volatile("mma.sync.aligned.m16n8k16.row.col.f32.bf16.bf16.f32 "
        "{%0,%1,%2,%3},{%4,%5,%6,%7},{%8,%9},{%0,%1,%2,%3};"
        : "+f"(c[0]), "+f"(c[1]), "+f"(c[2]), "+f"(c[3])
        : "r"(a[0]), "r"(a[1]), "r"(a[2]), "r"(a[3]), "r"(b0), "r"(b1));
}
__device__ __forceinline__ void ldsm4(u32* r, u32 addr) {
    asm volatile("ldmatrix.sync.aligned.m8n8.x4.shared.b16 {%0,%1,%2,%3}, [%4];"
        : "=r"(r[0]), "=r"(r[1]), "=r"(r[2]), "=r"(r[3]) : "r"(addr));
}
__device__ __forceinline__ void frag_store(u16* Fh, u16* Fl, int row, int col, float v){
    int ch = col >> 4, kc = col & 15, mt = row >> 4, rg = row & 15;
    int lane = (rg & 7)*4 + ((kc >> 1) & 3);
    int w = ((kc >> 3) << 1) + (rg >> 3);
    size_t idx = ((size_t)(((ch*2 + mt)*32) + lane) << 3) + (w << 1) + (kc & 1);
    __nv_bfloat16 h = __float2bfloat16(v);
    Fh[idx] = __bfloat16_as_ushort(h);
    Fl[idx] = __bfloat16_as_ushort(__float2bfloat16(v - __bfloat162float(h)));
}

// ---------- merged conversion ----------
struct CJ { const float* W; void* Oh; void* Ol; int K, N, mode, boff; };
struct CJobs { CJ j[8]; };

__global__ void __launch_bounds__(256) conv_all(CJobs jb)
{
    __shared__ float tile[32][33];
    int blk = blockIdx.x, ji = 0;
    #pragma unroll
    for (int i = 7; i >= 0; i--) if (blk >= jb.j[i].boff) { ji = i; break; }
    const CJ& J = jb.j[ji];
    int local = blk - J.boff;
    const int tid = threadIdx.x, lane = tid & 31;
    if (J.mode == 0) {
        int ntl = J.N >> 5;
        int tk = local / ntl, tn = local % ntl;
        int n0 = tn*32, k0 = tk*32;
        int tx = lane, ty = tid >> 5;
        #pragma unroll
        for (int i = 0; i < 4; i++)
            tile[ty + i*8][tx] = J.W[(size_t)(k0 + ty + i*8)*J.N + n0 + tx];
        __syncthreads();
        u16* Oh = (u16*)J.Oh; u16* Ol = (u16*)J.Ol;
        #pragma unroll
        for (int i = 0; i < 4; i++) {
            int nn = ty + i*8;
            float v = tile[tx][nn];
            Oh[(size_t)(n0+nn)*J.K + k0 + tx] = bhi(v);
            Ol[(size_t)(n0+nn)*J.K + k0 + tx] = blo(v);
        }
    } else {
        int nch = J.K >> 4;
        int pair = local*8 + (tid >> 5);
        int ng = pair / nch, c = pair % nch;
        int n = ng*8 + (lane >> 2), k = c*16 + (lane & 3)*2;
        const float* W = J.W;
        float v0 = W[(size_t)k*J.N + n],     v1 = W[(size_t)(k+1)*J.N + n];
        float v2 = W[(size_t)(k+8)*J.N + n], v3 = W[(size_t)(k+9)*J.N + n];
        ((uint4*)J.Oh)[(size_t)pair*32 + lane] =
            make_uint4(pack2(bhi(v0),bhi(v1)), pack2(bhi(v2),bhi(v3)),
                       pack2(blo(v0),blo(v1)), pack2(blo(v2),blo(v3)));
    }
}

// ---------- big GEMM with ldmatrix, DOUBLE-BUFFERED smem ----------
__global__ void __launch_bounds__(256) gemm_big(
    const float* __restrict__ A, const int* __restrict__ gather,
    const u16* __restrict__ Bh, const u16* __restrict__ Bl,
    const float* __restrict__ bias, float* __restrict__ C, int N, int K)
{
    __shared__ __align__(16) u16 Ahs[2][128*24], Als[2][128*24];
    __shared__ __align__(16) u16 Bhs[2][128*24], Bls[2][128*24];
    const int t = threadIdx.x, lane = t & 31, wid = t >> 5;
    const int wr = wid & 3, wc = wid >> 2;
    const int g = lane >> 2, tg = lane & 3;
    const int m0 = blockIdx.x * 128, n0 = blockIdx.y * 128;

    const int srow = t >> 1, sseg = (t & 1) * 8;
    const int arow = gather ? gather[m0 + srow] : (m0 + srow);
    const float* Ap = A + (size_t)arow * K + sseg;
    const u16* Bph = Bh + (size_t)(n0 + srow) * K + sseg;
    const u16* Bpl = Bl + (size_t)(n0 + srow) * K + sseg;

    const int a_r = ((lane>>3)&1)*8 + (lane&7), a_c = (lane>>4)*8;
    const int b_r = (lane>>4)*8 + (lane&7),     b_c = ((lane>>3)&1)*8;
    u32 bAh[2], bAl[2], bBh[2], bBl[2];
    #pragma unroll
    for (int p = 0; p < 2; p++) {
        bAh[p] = (u32)__cvta_generic_to_shared(&Ahs[p][0]);
        bAl[p] = (u32)__cvta_generic_to_shared(&Als[p][0]);
        bBh[p] = (u32)__cvta_generic_to_shared(&Bhs[p][0]);
        bBl[p] = (u32)__cvta_generic_to_shared(&Bls[p][0]);
    }

    float acc[2][8][4];
    #pragma unroll
    for (int i = 0; i < 2; i++)
        #pragma unroll
        for (int j = 0; j < 8; j++)
            #pragma unroll
            for (int q = 0; q < 4; q++) acc[i][j][q] = 0.0f;

    const int iters = K >> 4;
    float4 a0R = *(const float4*)Ap, a1R = *(const float4*)(Ap + 4);
    uint4 bhR = *(const uint4*)Bph, blR = *(const uint4*)Bpl;

    // stage chunk 0 -> buf 0
    {
        u32 h0,l0,h1,l1,h2,l2,h3,l3;
        split2(a0R.x,a0R.y,h0,l0); split2(a0R.z,a0R.w,h1,l1);
        split2(a1R.x,a1R.y,h2,l2); split2(a1R.z,a1R.w,h3,l3);
        *(uint4*)&Ahs[0][srow*24 + sseg] = make_uint4(h0,h1,h2,h3);
        *(uint4*)&Als[0][srow*24 + sseg] = make_uint4(l0,l1,l2,l3);
        *(uint4*)&Bhs[0][srow*24 + sseg] = bhR;
        *(uint4*)&Bls[0][srow*24 + sseg] = blR;
    }
    __syncthreads();

    for (int kt = 0; kt < iters; kt++) {
        const int p = kt & 1;
        if (kt + 1 < iters) {                 // issue global loads early
            a0R = *(const float4*)(Ap + (kt+1)*16);
            a1R = *(const float4*)(Ap + (kt+1)*16 + 4);
            bhR = *(const uint4*)(Bph + (kt+1)*16);
            blR = *(const uint4*)(Bpl + (kt+1)*16);
        }
        u32 ah[2][4], al[2][4];
        #pragma unroll
        for (int mt = 0; mt < 2; mt++) {
            u32 off = (u32)(((wr*32 + mt*16 + a_r)*24 + a_c) * 2);
            ldsm4(ah[mt], bAh[p] + off);
            ldsm4(al[mt], bAl[p] + off);
        }
        #pragma unroll
        for (int ntp = 0; ntp < 4; ntp++) {
            u32 off = (u32)(((wc*64 + ntp*16 + b_r)*24 + b_c) * 2);
            u32 bh4[4], bl4[4];
            ldsm4(bh4, bBh[p] + off);
            ldsm4(bl4, bBl[p] + off);
            #pragma unroll
            for (int e = 0; e < 2; e++) {
                int nt = ntp*2 + e;
                #pragma unroll
                for (int mt = 0; mt < 2; mt++) {
                    mma16816(acc[mt][nt], ah[mt], bh4[e*2], bh4[e*2+1]);
                    mma16816(acc[mt][nt], ah[mt], bl4[e*2], bl4[e*2+1]);
                    mma16816(acc[mt][nt], al[mt], bh4[e*2], bh4[e*2+1]);
                }
            }
        }
        if (kt + 1 < iters) {                 // stage next chunk into other buf
            const int q = p ^ 1;
            u32 h0,l0,h1,l1,h2,l2,h3,l3;
            split2(a0R.x,a0R.y,h0,l0); split2(a0R.z,a0R.w,h1,l1);
            split2(a1R.x,a1R.y,h2,l2); split2(a1R.z,a1R.w,h3,l3);
            *(uint4*)&Ahs[q][srow*24 + sseg] = make_uint4(h0,h1,h2,h3);
            *(uint4*)&Als[q][srow*24 + sseg] = make_uint4(l0,l1,l2,l3);
            *(uint4*)&Bhs[q][srow*24 + sseg] = bhR;
            *(uint4*)&Bls[q][srow*24 + sseg] = blR;
        }
        __syncthreads();
    }
    #pragma unroll
    for (int mt = 0; mt < 2; mt++)
        #pragma unroll
        for (int nt = 0; nt < 8; nt++) {
            int m = m0 + wr*32 + mt*16 + g;
            int n = n0 + wc*64 + nt*8 + tg*2;
            float b0v = bias[n], b1v = bias[n+1];
            float* p2 = C + (size_t)m * N + n;
            *(float2*)p2 = make_float2(acc[mt][nt][0] + b0v, acc[mt][nt][1] + b1v);
            *(float2*)(p2 + (size_t)8*N) = make_float2(acc[mt][nt][2] + b0v, acc[mt][nt][3] + b1v);
        }
}

// ---------- persistent encoder: 512 threads, prefetched ----------
__global__ void __launch_bounds__(512) enc_persist()
{
    extern __shared__ float red_[];
    const int bk = blockIdx.x, tid = threadIdx.x, lane = tid & 31, wid = tid >> 5;
    const int g = lane >> 2, tg = lane & 3;

    { int i = bk*512 + tid;
      if (i < 16384) { ((u32*)g_ehf[0][0])[i] = 0u; ((u32*)g_ehf[0][1])[i] = 0u; } }
    float cst = 0.0f;
    gbar();

    for (int t = 0; t < Sn; t++) {
        const int rp = t & 1, wp2 = rp ^ 1;
        const uint4* Ah = g_ehf[rp][0];
        const uint4* Al = g_ehf[rp][1];

        // hoist XW gate loads (long-latency, independent of MMA)
        float xg0, xg1, xg2, xg3;
        if (tid < 256) {
            const int bb = tid >> 3, jl = tid & 7;
            const size_t xw = ((size_t)(bb*Sn + t))*Gn + bk*8 + jl;
            xg0 = g_XWenc[xw]; xg1 = g_XWenc[xw+1024];
            xg2 = g_XWenc[xw+2048]; xg3 = g_XWenc[xw+3072];
        }

        float acc[2][4][4];
        #pragma unroll
        for (int a = 0; a < 2; a++)
            #pragma unroll
            for (int b = 0; b < 4; b++)
                #pragma unroll
                for (int q = 0; q < 4; q++) acc[a][b][q] = 0.0f;

        const int cb = wid*4;
        uint4 pfh0 = Ah[(cb*2)*32 + lane],   pfh1 = Ah[(cb*2+1)*32 + lane];
        uint4 pfl0 = Al[(cb*2)*32 + lane],   pfl1 = Al[(cb*2+1)*32 + lane];
        #pragma unroll
        for (int ks = 0; ks < 4; ks++) {
            const int c = cb + ks;
            uint4 fh0 = pfh0, fh1 = pfh1, fl0 = pfl0, fl1 = pfl1;
            if (ks < 3) {
                const int c2 = c + 1;
                pfh0 = Ah[(c2*2)*32 + lane]; pfh1 = Ah[(c2*2+1)*32 + lane];
                pfl0 = Al[(c2*2)*32 + lane]; pfl1 = Al[(c2*2+1)*32 + lane];
            }
            #pragma unroll
            for (int nt = 0; nt < 4; nt++) {
                uint4 wq = w_hhE_f[((size_t)(nt*128 + bk)*64 + c)*32 + lane];
                mma16816(acc[0][nt], (u32*)&fh0, wq.x, wq.y);
                mma16816(acc[0][nt], (u32*)&fh0, wq.z, wq.w);
                mma16816(acc[0][nt], (u32*)&fl0, wq.x, wq.y);
                mma16816(acc[1][nt], (u32*)&fh1, wq.x, wq.y);
                mma16816(acc[1][nt], (u32*)&fh1, wq.z, wq.w);
                mma16816(acc[1][nt], (u32*)&fl1, wq.x, wq.y);
            }
        }
        float* rw0 = &red_[wid*1056];
        #pragma unroll
        for (int mt = 0; mt < 2; mt++)
            #pragma unroll
            for (int nt = 0; nt < 4; nt++) {
                int r0 = mt*16 + g, c0 = nt*8 + tg*2;
                rw0[r0*33 + c0]       = acc[mt][nt][0];
                rw0[r0*33 + c0 + 1]   = acc[mt][nt][1];
                rw0[(r0+8)*33 + c0]   = acc[mt][nt][2];
                rw0[(r0+8)*33 + c0+1] = acc[mt][nt][3];
            }
        __syncthreads();

        if (tid < 256) {
            const int bb = tid >> 3, jl = tid & 7, j = bk*8 + jl;
            float gi = xg0, gf = xg1, gg = xg2, go = xg3;
            #pragma unroll
            for (int w = 0; w < 16; w++) {
                const float* rw = &red_[w*1056 + bb*33];
                gi += rw[jl]; gf += rw[8+jl]; gg += rw[16+jl]; go += rw[24+jl];
            }
            cst = sigm(gf)*cst + sigm(gi)*tanhf(gg);
            float h = sigm(go)*tanhf(cst);
            g_enc_out[((size_t)(bb*Sn + t))*Hn + j] = h;
            frag_store((u16*)g_ehf[wp2][0], (u16*)g_ehf[wp2][1], bb, j, h);
            if (t == Sn-1) { g_h[bb*Hn + j] = h; g_c[bb*Hn + j] = cst; }
        }
        gbar();
    }
}

// ---------- persistent decoder: 512 threads, prefetched ----------
__global__ void __launch_bounds__(512) dec_persist(const float* __restrict__ cls1_b)
{
    extern __shared__ float red_[];
    const int bk = blockIdx.x, tid = threadIdx.x, lane = tid & 31, wid = tid >> 5;
    const int g = lane >> 2, tg = lane & 3;
    float* sc    = red_;
    float* wsm   = sc + 3200;
    float* stats = wsm + 3200;
    float* ctx   = stats + 64;

    { int i = bk*512 + tid;
      if (i < Bn*Hn) {
          float h0 = g_h[i];
          int row = i >> 10, col = i & 1023;
          frag_store((u16*)g_dhf[0][0], (u16*)g_dhf[0][1], row, col, h0);
          frag_store((u16*)g_fdf[0][0], (u16*)g_fdf[0][1], row, col, h0);
      } }
    float cst = (tid < 256) ? g_c[(tid>>3)*Hn + bk*8 + (tid&7)] : 0.0f;
    gbar();

    for (int t = 0; t < Tn; t++) {
        const int rp = t & 1, wp2 = rp ^ 1;

        // P1: gates + cell (prefetched)
        {
            const uint4 *Ah, *Al, *Wf;
            int cb;
            if (wid < 8) { Ah = g_fdf[rp][0]; Al = g_fdf[rp][1]; Wf = w_ihDH_f; cb = wid*8; }
            else         { Ah = g_dhf[rp][0]; Al = g_dhf[rp][1]; Wf = w_hhD_f;  cb = (wid-8)*8; }

            float xg0, xg1, xg2, xg3;
            if (tid < 256) {
                const int bb = tid >> 3, jl = tid & 7;
                const size_t xw = ((size_t)(bb*Tn + t))*Gn + bk*8 + jl;
                xg0 = g_XWdec[xw]; xg1 = g_XWdec[xw+1024];
                xg2 = g_XWdec[xw+2048]; xg3 = g_XWdec[xw+3072];
            }

            float acc[2][4][4];
            #pragma unroll
            for (int a = 0; a < 2; a++)
                #pragma unroll
                for (int b = 0; b < 4; b++)
                    #pragma unroll
                    for (int q = 0; q < 4; q++) acc[a][b][q] = 0.0f;

            uint4 pfh0 = Ah[(cb*2)*32 + lane],   pfh1 = Ah[(cb*2+1)*32 + lane];
            uint4 pfl0 = Al[(cb*2)*32 + lane],   pfl1 = Al[(cb*2+1)*32 + lane];
            #pragma unroll
            for (int ks = 0; ks < 8; ks++) {
                const int c = cb + ks;
                uint4 fh0 = pfh0, fh1 = pfh1, fl0 = pfl0, fl1 = pfl1;
                if (ks < 7) {
                    const int c2 = c + 1;
                    pfh0 = Ah[(c2*2)*32 + lane]; pfh1 = Ah[(c2*2+1)*32 + lane];
                    pfl0 = Al[(c2*2)*32 + lane]; pfl1 = Al[(c2*2+1)*32 + lane];
                }
                #pragma unroll
                for (int nt = 0; nt < 4; nt++) {
                    uint4 wq = Wf[((size_t)(nt*128 + bk)*64 + c)*32 + lane];
                    mma16816(acc[0][nt], (u32*)&fh0, wq.x, wq.y);
                    mma16816(acc[0][nt], (u32*)&fh0, wq.z, wq.w);
                    mma16816(acc[0][nt], (u32*)&fl0, wq.x, wq.y);
                    mma16816(acc[1][nt], (u32*)&fh1, wq.x, wq.y);
                    mma16816(acc[1][nt], (u32*)&fh1, wq.z, wq.w);
                    mma16816(acc[1][nt], (u32*)&fl1, wq.x, wq.y);
                }
            }
            float* rw0 = &red_[wid*1056];
            #pragma unroll
            for (int mt = 0; mt < 2; mt++)
                #pragma unroll
                for (int nt = 0; nt < 4; nt++) {
                    int r0 = mt*16 + g, c0 = nt*8 + tg*2;
                    rw0[r0*33 + c0]       = acc[mt][nt][0];
                    rw0[r0*33 + c0 + 1]   = acc[mt][nt][1];
                    rw0[(r0+8)*33 + c0]   = acc[mt][nt][2];
                    rw0[(r0+8)*33 + c0+1] = acc[mt][nt][3];
                }
            __syncthreads();
            if (tid < 256) {
                const int bb = tid >> 3, jl = tid & 7, j = bk*8 + jl;
                float gi = xg0, gf = xg1, gg = xg2, go = xg3;
                #pragma unroll
                for (int w = 0; w < 16; w++) {
                    const float* rw = &red_[w*1056 + bb*33];
                    gi += rw[jl]; gf += rw[8+jl]; gg += rw[16+jl]; go += rw[24+jl];
                }
                cst = sigm(gf)*cst + sigm(gi)*tanhf(gg);
                float h = sigm(go)*tanhf(cst);
                g_hdf[bb*Hn + j] = h;
                frag_store((u16*)g_dhf[wp2][0], (u16*)g_dhf[wp2][1], bb, j, h);
            }
        }
        gbar();

        // P2: scores (float4 loads for MLP)
        #pragma unroll
        for (int r = 0; r < 2; r++) {
            int pair = bk*16 + wid + r*2048;
            if (pair < Bn*Sn) {
                int b = pair / Sn;
                const float4* ep4 = (const float4*)(g_enc_proj + (size_t)pair * Hn);
                const float4* hv4 = (const float4*)(g_hdf + b * Hn);
                float a = 0.f;
                #pragma unroll
                for (int it = 0; it < 8; it++) {
                    float4 e = ep4[lane + 32*it];
                    float4 h = hv4[lane + 32*it];
                    a += e.x*h.x + e.y*h.y + e.z*h.z + e.w*h.w;
                }
                #pragma unroll
                for (int o = 16; o; o >>= 1) a += __shfl_xor_sync(0xffffffffu, a, o);
                if (lane == 0) g_scores[pair] = a;
            }
        }
        gbar();

        // P3: softmax + context
        for (int i = tid; i < Bn*Sn; i += 512) sc[i] = g_scores[i];
        __syncthreads();
        #pragma unroll
        for (int q = 0; q < 2; q++) {
            int b = wid*2 + q;
            float m = -1e30f;
            for (int s = lane; s < Sn; s += 32) m = fmaxf(m, sc[b*Sn + s]);
            #pragma unroll
            for (int o = 16; o; o >>= 1) m = fmaxf(m, __shfl_xor_sync(0xffffffffu, m, o));
            float su = 0.f;
            for (int s = lane; s < Sn; s += 32) su += expf(sc[b*Sn + s] - m);
            #pragma unroll
            for (int o = 16; o; o >>= 1) su += __shfl_xor_sync(0xffffffffu, su, o);
            if (lane == 0) { stats[b] = m; stats[32 + b] = 1.0f / su; }
        }
        __syncthreads();
        for (int i = tid; i < Bn*Sn; i += 512) {
            int b = i / Sn;
            wsm[i] = expf(sc[i] - stats[b]) * stats[32 + b];
        }
        __syncthreads();
        {
            const int half = tid >> 8, ct = tid & 255;
            const int bb = ct >> 3, jl = ct & 7, j = bk*8 + jl;
            float a = 0.f;
            const float* eo = g_enc_out + ((size_t)bb*Sn) * Hn + j;
            const float* wv = wsm + bb*Sn;
            const int s0 = half*50;
            #pragma unroll 10
            for (int s = s0; s < s0 + 50; s++) a += wv[s] * eo[(size_t)s * Hn];
            ctx[tid] = a;
        }
        __syncthreads();
        if (tid < 256) {
            const int bb = tid >> 3, jl = tid & 7, j = bk*8 + jl;
            float a = ctx[tid] + ctx[256 + tid];
            frag_store((u16*)g_atf[0], (u16*)g_atf[1], bb, j, a);
        }
        gbar();

        // P4: feed = tanh([atten, hd] @ cls1 + b) (prefetched)
        {
            const uint4 *Ah, *Al;
            int cb, cw;
            if (wid < 8) { Ah = g_atf[0];      Al = g_atf[1];      cb = wid*8;     cw = 0; }
            else         { Ah = g_dhf[wp2][0]; Al = g_dhf[wp2][1]; cb = (wid-8)*8; cw = 64; }
            float fa[2][4];
            #pragma unroll
            for (int a = 0; a < 2; a++)
                #pragma unroll
                for (int q = 0; q < 4; q++) fa[a][q] = 0.0f;

            uint4 pfh0 = Ah[(cb*2)*32 + lane],   pfh1 = Ah[(cb*2+1)*32 + lane];
            uint4 pfl0 = Al[(cb*2)*32 + lane],   pfl1 = Al[(cb*2+1)*32 + lane];
            #pragma unroll
            for (int ks = 0; ks < 8; ks++) {
                const int c = cb + ks;
                uint4 fh0 = pfh0, fh1 = pfh1, fl0 = pfl0, fl1 = pfl1;
                if (ks < 7) {
                    const int c2 = c + 1;
                    pfh0 = Ah[(c2*2)*32 + lane]; pfh1 = Ah[(c2*2+1)*32 + lane];
                    pfl0 = Al[(c2*2)*32 + lane]; pfl1 = Al[(c2*2+1)*32 + lane];
                }
                uint4 wq = w_c1_f[((size_t)bk*128 + cw + c)*32 + lane];
                mma16816(fa[0], (u32*)&fh0, wq.x, wq.y);
                mma16816(fa[0], (u32*)&fh0, wq.z, wq.w);
                mma16816(fa[0], (u32*)&fl0, wq.x, wq.y);
                mma16816(fa[1], (u32*)&fh1, wq.x, wq.y);
                mma16816(fa[1], (u32*)&fh1, wq.z, wq.w);
                mma16816(fa[1], (u32*)&fl1, wq.x, wq.y);
            }
            float* rw0 = &red_[wid*1056];
            #pragma unroll
            for (int mt = 0; mt < 2; mt++) {
                int r0 = mt*16 + g, c0 = tg*2;
                rw0[r0*33 + c0]       = fa[mt][0];
                rw0[r0*33 + c0 + 1]   = fa[mt][1];
                rw0[(r0+8)*33 + c0]   = fa[mt][2];
                rw0[(r0+8)*33 + c0+1] = fa[mt][3];
            }
            __syncthreads();
            if (tid < 256) {
                const int bb = tid >> 3, jl = tid & 7, j = bk*8 + jl;
                float a = cls1_b[j];
                #pragma unroll
                for (int w = 0; w < 16; w++) a += red_[w*1056 + bb*33 + jl];
                float f = tanhf(a);
                frag_store((u16*)g_fdf[wp2][0], (u16*)g_fdf[wp2][1], bb, j, f);
                g_hidden[((size_t)(bb*Tn + t))*Hn + j] = f;
            }
        }
        gbar();
    }
}

extern "C" void kernel_launch(void* const* d_in, const int* in_sizes, int n_in,
                              void* d_out, int out_size)
{
    const int*   source_data = (const int*)  d_in[0];
    const int*   target_data = (const int*)  d_in[1];
    const float* src_emb  = (const float*)d_in[2];
    const float* tgt_emb  = (const float*)d_in[3];
    const float* enc_Wih  = (const float*)d_in[4];
    const float* enc_Whh  = (const float*)d_in[5];
    const float* enc_b    = (const float*)d_in[6];
    const float* dec_Wih  = (const float*)d_in[7];
    const float* dec_Whh  = (const float*)d_in[8];
    const float* dec_b    = (const float*)d_in[9];
    const float* att1_W   = (const float*)d_in[10];
    const float* att1_b   = (const float*)d_in[11];
    const float* cls1_W   = (const float*)d_in[12];
    const float* cls1_b   = (const float*)d_in[13];
    const float* cls2_W   = (const float*)d_in[14];
    const float* cls2_b   = (const float*)d_in[15];
    float* out = (float*)d_out;

    float *XWenc, *XWdec, *enc_out, *enc_proj, *hidden;
    void *ihE_h,*ihE_l,*ihD0_h,*ihD0_l,*att_h,*att_l,*c2_h,*c2_l;
    void *hhE_f,*ihDH_f,*hhD_f,*c1_f;
    cudaGetSymbolAddress((void**)&XWenc,   g_XWenc);
    cudaGetSymbolAddress((void**)&XWdec,   g_XWdec);
    cudaGetSymbolAddress((void**)&enc_out, g_enc_out);
    cudaGetSymbolAddress((void**)&enc_proj,g_enc_proj);
    cudaGetSymbolAddress((void**)&hidden,  g_hidden);
    cudaGetSymbolAddress(&ihE_h,  w_ihE_h);  cudaGetSymbolAddress(&ihE_l,  w_ihE_l);
    cudaGetSymbolAddress(&ihD0_h, w_ihD0_h); cudaGetSymbolAddress(&ihD0_l, w_ihD0_l);
    cudaGetSymbolAddress(&att_h,  w_att_h);  cudaGetSymbolAddress(&att_l,  w_att_l);
    cudaGetSymbolAddress(&c2_h,   w_c2_h);   cudaGetSymbolAddress(&c2_l,   w_c2_l);
    cudaGetSymbolAddress(&hhE_f,  w_hhE_f);  cudaGetSymbolAddress(&ihDH_f, w_ihDH_f);
    cudaGetSymbolAddress(&hhD_f,  w_hhD_f);  cudaGetSymbolAddress(&c1_f,   w_c1_f);

    cudaFuncSetAttribute(enc_persist, cudaFuncAttributeMaxDynamicSharedMemorySize, RED_F*4);
    cudaFuncSetAttribute(dec_persist, cudaFuncAttributeMaxDynamicSharedMemorySize, RED_F*4);

    CJobs jb;
    jb.j[0] = { enc_Wih,                    ihE_h,  ihE_l,   512, 4096, 0, 0     };
    jb.j[1] = { dec_Wih,                    ihD0_h, ihD0_l,  512, 4096, 0, 2048  };
    jb.j[2] = { att1_W,                     att_h,  att_l,  1024, 1024, 0, 4096  };
    jb.j[3] = { cls2_W,                     c2_h,   c2_l,   1024, Vn,   0, 5120  };
    jb.j[4] = { enc_Whh,                    hhE_f,  nullptr,1024, 4096, 1, 37120 };
    jb.j[5] = { dec_Wih + (size_t)512*4096, ihDH_f, nullptr,1024, 4096, 1, 41216 };
    jb.j[6] = { dec_Whh,                    hhD_f,  nullptr,1024, 4096, 1, 45312 };
    jb.j[7] = { cls1_W,                     c1_f,   nullptr,2048, 1024, 1, 49408 };
    conv_all<<<51456, 256>>>(jb);                                              // 1

    gemm_big<<<dim3(25, 32), 256>>>(src_emb, source_data,
        (u16*)ihE_h, (u16*)ihE_l, enc_b, XWenc, Gn, En);                       // 2
    gemm_big<<<dim3(25, 32), 256>>>(tgt_emb, target_data,
        (u16*)ihD0_h, (u16*)ihD0_l, dec_b, XWdec, Gn, En);                     // 3
    enc_persist<<<NBLK, 512, RED_F*4>>>();                                     // 4
    gemm_big<<<dim3(25, 8), 256>>>(enc_out, nullptr,
        (u16*)att_h, (u16*)att_l, att1_b, enc_proj, Hn, Hn);                   // 5
    dec_persist<<<NBLK, 512, RED_F*4>>>(cls1_b);                               // 6  <- ncu
    gemm_big<<<dim3(25, 250), 256>>>(hidden, nullptr,
        (u16*)c2_h, (u16*)c2_l, cls2_b, out, Vn, Hn);                          // 7
}

// round 10
// speedup vs baseline: 2.3667x; 1.1226x over previous
#include <cuda_runtime.h>
#include <cuda_bf16.h>
#include <cuda_fp16.h>
#include <math.h>
#include <stdint.h>

typedef unsigned short u16;
typedef unsigned int   u32;

#define Bn 32
#define Sn 100
#define Tn 100
#define En 512
#define Hn 1024
#define Vn 32000
#define Gn 4096
#define NBLK 128
#define RED_F (16*1056)   // dynamic smem floats for persistent kernels

// fp32 scratch
__device__ float g_XWenc[Bn*Sn*Gn];
__device__ float g_XWdec[Bn*Tn*Gn];
__device__ float g_enc_out[Bn*Sn*Hn];
__device__ float g_enc_proj[Bn*Sn*Hn];
__device__ float g_h[Bn*Hn];
__device__ float g_c[Bn*Hn];
__device__ float g_hdf[Bn*Hn];
__device__ float g_scores[Bn*Sn];

// fp16 hidden (classifier A operand)
__device__ u16 g_hid16[Bn*Tn*Hn];

// fragment-major state: uint4 idx = (chunk*2+mt)*32+lane, chunk=k16
__device__ uint4 g_ehf[2][2][4096];
__device__ uint4 g_dhf[2][2][4096];
__device__ uint4 g_fdf[2][2][4096];
__device__ uint4 g_atf[2][4096];

// plain transposed [n][k] bf16 weights (for gemm_big)
__device__ u16 w_ihE_h [(size_t)Gn*En],  w_ihE_l [(size_t)Gn*En];
__device__ u16 w_ihD0_h[(size_t)Gn*En],  w_ihD0_l[(size_t)Gn*En];
__device__ u16 w_att_h [(size_t)Hn*Hn],  w_att_l [(size_t)Hn*Hn];
// transposed fp16 hi/lo classifier weights
__device__ u16 w_c2_h  [(size_t)Vn*Hn],  w_c2_l  [(size_t)Vn*Hn];

// fragment-major weights: uint4 {b0h,b1h,b0l,b1l}, idx = (ng*nch + c)*32 + lane
__device__ uint4 w_hhE_f [512*64*32];
__device__ uint4 w_ihDH_f[512*64*32];
__device__ uint4 w_hhD_f [512*64*32];
__device__ uint4 w_c1_f  [128*128*32];

__device__ unsigned g_cnt, g_gen;
__device__ __forceinline__ void gbar() {
    __syncthreads();
    if (threadIdx.x == 0) {
        __threadfence();
        unsigned my = *((volatile unsigned*)&g_gen);
        unsigned a = atomicAdd(&g_cnt, 1u);
        if (a == NBLK - 1u) { g_cnt = 0u; __threadfence(); *((volatile unsigned*)&g_gen) = my + 1u; }
        else { while (*((volatile unsigned*)&g_gen) == my) {} }
        __threadfence();
    }
    __syncthreads();
}

__device__ __forceinline__ float sigm(float x){ return 1.0f/(1.0f + expf(-x)); }
__device__ __forceinline__ u16 bhi(float v){ return __bfloat16_as_ushort(__float2bfloat16(v)); }
__device__ __forceinline__ u16 blo(float v){
    __nv_bfloat16 h = __float2bfloat16(v);
    return __bfloat16_as_ushort(__float2bfloat16(v - __bfloat162float(h)));
}
__device__ __forceinline__ u32 pack2(u16 a, u16 b){ return (u32)a | ((u32)b << 16); }
__device__ __forceinline__ void split2(float x, float y, u32& hp, u32& lp) {
    hp = pack2(bhi(x), bhi(y)); lp = pack2(blo(x), blo(y));
}
__device__ __forceinline__ void mma16816(float* c, const u32* a, u32 b0, u32 b1) {
    asm volatile("mma.sync.aligned.m16n8k16.row.col.f32.bf16.bf16.f32 "
        "{%0,%1,%2,%3},{%4,%5,%6,%7},{%8,%9},{%0,%1,%2,%3};"
        : "+f"(c[0]), "+f"(c[1]), "+f"(c[2]), "+f"(c[3])
        : "r"(a[0]), "r"(a[1]), "r"(a[2]), "r"(a[3]), "r"(b0), "r"(b1));
}
__device__ __forceinline__ void mma16816h(float* c, const u32* a, u32 b0, u32 b1) {
    asm volatile("mma.sync.aligned.m16n8k16.row.col.f32.f16.f16.f32 "
        "{%0,%1,%2,%3},{%4,%5,%6,%7},{%8,%9},{%0,%1,%2,%3};"
        : "+f"(c[0]), "+f"(c[1]), "+f"(c[2]), "+f"(c[3])
        : "r"(a[0]), "r"(a[1]), "r"(a[2]), "r"(a[3]), "r"(b0), "r"(b1));
}
__device__ __forceinline__ void ldsm4(u32* r, u32 addr) {
    asm volatile("ldmatrix.sync.aligned.m8n8.x4.shared.b16 {%0,%1,%2,%3}, [%4];"
        : "=r"(r[0]), "=r"(r[1]), "=r"(r[2]), "=r"(r[3]) : "r"(addr));
}
__device__ __forceinline__ void frag_store(u16* Fh, u16* Fl, int row, int col, float v){
    int ch = col >> 4, kc = col & 15, mt = row >> 4, rg = row & 15;
    int lane = (rg & 7)*4 + ((kc >> 1) & 3);
    int w = ((kc >> 3) << 1) + (rg >> 3);
    size_t idx = ((size_t)(((ch*2 + mt)*32) + lane) << 3) + (w << 1) + (kc & 1);
    __nv_bfloat16 h = __float2bfloat16(v);
    Fh[idx] = __bfloat16_as_ushort(h);
    Fl[idx] = __bfloat16_as_ushort(__float2bfloat16(v - __bfloat162float(h)));
}

// ---------- merged conversion ----------
struct CJ { const float* W; void* Oh; void* Ol; int K, N, mode, boff; };
struct CJobs { CJ j[8]; };

__global__ void __launch_bounds__(256) conv_all(CJobs jb)
{
    __shared__ float tile[32][33];
    int blk = blockIdx.x, ji = 0;
    #pragma unroll
    for (int i = 7; i >= 0; i--) if (blk >= jb.j[i].boff) { ji = i; break; }
    const CJ& J = jb.j[ji];
    int local = blk - J.boff;
    const int tid = threadIdx.x, lane = tid & 31;
    if (J.mode == 0 || J.mode == 3) {
        int ntl = J.N >> 5;
        int tk = local / ntl, tn = local % ntl;
        int n0 = tn*32, k0 = tk*32;
        int tx = lane, ty = tid >> 5;
        #pragma unroll
        for (int i = 0; i < 4; i++)
            tile[ty + i*8][tx] = J.W[(size_t)(k0 + ty + i*8)*J.N + n0 + tx];
        __syncthreads();
        u16* Oh = (u16*)J.Oh; u16* Ol = (u16*)J.Ol;
        if (J.mode == 0) {
            #pragma unroll
            for (int i = 0; i < 4; i++) {
                int nn = ty + i*8;
                float v = tile[tx][nn];
                Oh[(size_t)(n0+nn)*J.K + k0 + tx] = bhi(v);
                Ol[(size_t)(n0+nn)*J.K + k0 + tx] = blo(v);
            }
        } else {
            #pragma unroll
            for (int i = 0; i < 4; i++) {
                int nn = ty + i*8;
                float v = tile[tx][nn];
                __half h = __float2half_rn(v);
                Oh[(size_t)(n0+nn)*J.K + k0 + tx] = __half_as_ushort(h);
                Ol[(size_t)(n0+nn)*J.K + k0 + tx] =
                    __half_as_ushort(__float2half_rn(v - __half2float(h)));
            }
        }
    } else {
        int nch = J.K >> 4;
        int pair = local*8 + (tid >> 5);
        int ng = pair / nch, c = pair % nch;
        int n = ng*8 + (lane >> 2), k = c*16 + (lane & 3)*2;
        const float* W = J.W;
        float v0 = W[(size_t)k*J.N + n],     v1 = W[(size_t)(k+1)*J.N + n];
        float v2 = W[(size_t)(k+8)*J.N + n], v3 = W[(size_t)(k+9)*J.N + n];
        ((uint4*)J.Oh)[(size_t)pair*32 + lane] =
            make_uint4(pack2(bhi(v0),bhi(v1)), pack2(bhi(v2),bhi(v3)),
                       pack2(blo(v0),blo(v1)), pack2(blo(v2),blo(v3)));
    }
}

// ---------- big GEMM with ldmatrix, DOUBLE-BUFFERED smem (bf16x3) ----------
__global__ void __launch_bounds__(256) gemm_big(
    const float* __restrict__ A, const int* __restrict__ gather,
    const u16* __restrict__ Bh, const u16* __restrict__ Bl,
    const float* __restrict__ bias, float* __restrict__ C, int N, int K)
{
    __shared__ __align__(16) u16 Ahs[2][128*24], Als[2][128*24];
    __shared__ __align__(16) u16 Bhs[2][128*24], Bls[2][128*24];
    const int t = threadIdx.x, lane = t & 31, wid = t >> 5;
    const int wr = wid & 3, wc = wid >> 2;
    const int g = lane >> 2, tg = lane & 3;
    const int m0 = blockIdx.x * 128, n0 = blockIdx.y * 128;

    const int srow = t >> 1, sseg = (t & 1) * 8;
    const int arow = gather ? gather[m0 + srow] : (m0 + srow);
    const float* Ap = A + (size_t)arow * K + sseg;
    const u16* Bph = Bh + (size_t)(n0 + srow) * K + sseg;
    const u16* Bpl = Bl + (size_t)(n0 + srow) * K + sseg;

    const int a_r = ((lane>>3)&1)*8 + (lane&7), a_c = (lane>>4)*8;
    const int b_r = (lane>>4)*8 + (lane&7),     b_c = ((lane>>3)&1)*8;
    u32 bAh[2], bAl[2], bBh[2], bBl[2];
    #pragma unroll
    for (int p = 0; p < 2; p++) {
        bAh[p] = (u32)__cvta_generic_to_shared(&Ahs[p][0]);
        bAl[p] = (u32)__cvta_generic_to_shared(&Als[p][0]);
        bBh[p] = (u32)__cvta_generic_to_shared(&Bhs[p][0]);
        bBl[p] = (u32)__cvta_generic_to_shared(&Bls[p][0]);
    }

    float acc[2][8][4];
    #pragma unroll
    for (int i = 0; i < 2; i++)
        #pragma unroll
        for (int j = 0; j < 8; j++)
            #pragma unroll
            for (int q = 0; q < 4; q++) acc[i][j][q] = 0.0f;

    const int iters = K >> 4;
    float4 a0R = *(const float4*)Ap, a1R = *(const float4*)(Ap + 4);
    uint4 bhR = *(const uint4*)Bph, blR = *(const uint4*)Bpl;

    {
        u32 h0,l0,h1,l1,h2,l2,h3,l3;
        split2(a0R.x,a0R.y,h0,l0); split2(a0R.z,a0R.w,h1,l1);
        split2(a1R.x,a1R.y,h2,l2); split2(a1R.z,a1R.w,h3,l3);
        *(uint4*)&Ahs[0][srow*24 + sseg] = make_uint4(h0,h1,h2,h3);
        *(uint4*)&Als[0][srow*24 + sseg] = make_uint4(l0,l1,l2,l3);
        *(uint4*)&Bhs[0][srow*24 + sseg] = bhR;
        *(uint4*)&Bls[0][srow*24 + sseg] = blR;
    }
    __syncthreads();

    for (int kt = 0; kt < iters; kt++) {
        const int p = kt & 1;
        if (kt + 1 < iters) {
            a0R = *(const float4*)(Ap + (kt+1)*16);
            a1R = *(const float4*)(Ap + (kt+1)*16 + 4);
            bhR = *(const uint4*)(Bph + (kt+1)*16);
            blR = *(const uint4*)(Bpl + (kt+1)*16);
        }
        u32 ah[2][4], al[2][4];
        #pragma unroll
        for (int mt = 0; mt < 2; mt++) {
            u32 off = (u32)(((wr*32 + mt*16 + a_r)*24 + a_c) * 2);
            ldsm4(ah[mt], bAh[p] + off);
            ldsm4(al[mt], bAl[p] + off);
        }
        #pragma unroll
        for (int ntp = 0; ntp < 4; ntp++) {
            u32 off = (u32)(((wc*64 + ntp*16 + b_r)*24 + b_c) * 2);
            u32 bh4[4], bl4[4];
            ldsm4(bh4, bBh[p] + off);
            ldsm4(bl4, bBl[p] + off);
            #pragma unroll
            for (int e = 0; e < 2; e++) {
                int nt = ntp*2 + e;
                #pragma unroll
                for (int mt = 0; mt < 2; mt++) {
                    mma16816(acc[mt][nt], ah[mt], bh4[e*2], bh4[e*2+1]);
                    mma16816(acc[mt][nt], ah[mt], bl4[e*2], bl4[e*2+1]);
                    mma16816(acc[mt][nt], al[mt], bh4[e*2], bh4[e*2+1]);
                }
            }
        }
        if (kt + 1 < iters) {
            const int q = p ^ 1;
            u32 h0,l0,h1,l1,h2,l2,h3,l3;
            split2(a0R.x,a0R.y,h0,l0); split2(a0R.z,a0R.w,h1,l1);
            split2(a1R.x,a1R.y,h2,l2); split2(a1R.z,a1R.w,h3,l3);
            *(uint4*)&Ahs[q][srow*24 + sseg] = make_uint4(h0,h1,h2,h3);
            *(uint4*)&Als[q][srow*24 + sseg] = make_uint4(l0,l1,l2,l3);
            *(uint4*)&Bhs[q][srow*24 + sseg] = bhR;
            *(uint4*)&Bls[q][srow*24 + sseg] = blR;
        }
        __syncthreads();
    }
    #pragma unroll
    for (int mt = 0; mt < 2; mt++)
        #pragma unroll
        for (int nt = 0; nt < 8; nt++) {
            int m = m0 + wr*32 + mt*16 + g;
            int n = n0 + wc*64 + nt*8 + tg*2;
            float b0v = bias[n], b1v = bias[n+1];
            float* p2 = C + (size_t)m * N + n;
            *(float2*)p2 = make_float2(acc[mt][nt][0] + b0v, acc[mt][nt][1] + b1v);
            *(float2*)(p2 + (size_t)8*N) = make_float2(acc[mt][nt][2] + b0v, acc[mt][nt][3] + b1v);
        }
}

// ---------- classifier GEMM: fp16 A (single) x fp16 B (hi/lo), 2-term ----------
__global__ void __launch_bounds__(256) gemm_cls(
    const u16* __restrict__ A,           // fp16 [M,K]
    const u16* __restrict__ Bh, const u16* __restrict__ Bl,   // fp16 [N,K]
    const float* __restrict__ bias, float* __restrict__ C, int N, int K)
{
    __shared__ __align__(16) u16 Ahs[2][128*24];
    __shared__ __align__(16) u16 Bhs[2][128*24], Bls[2][128*24];
    const int t = threadIdx.x, lane = t & 31, wid = t >> 5;
    const int wr = wid & 3, wc = wid >> 2;
    const int g = lane >> 2, tg = lane & 3;
    const int m0 = blockIdx.x * 128, n0 = blockIdx.y * 128;

    const int srow = t >> 1, sseg = (t & 1) * 8;
    const u16* Ap  = A  + (size_t)(m0 + srow) * K + sseg;
    const u16* Bph = Bh + (size_t)(n0 + srow) * K + sseg;
    const u16* Bpl = Bl + (size_t)(n0 + srow) * K + sseg;

    const int a_r = ((lane>>3)&1)*8 + (lane&7), a_c = (lane>>4)*8;
    const int b_r = (lane>>4)*8 + (lane&7),     b_c = ((lane>>3)&1)*8;
    u32 bAh[2], bBh[2], bBl[2];
    #pragma unroll
    for (int p = 0; p < 2; p++) {
        bAh[p] = (u32)__cvta_generic_to_shared(&Ahs[p][0]);
        bBh[p] = (u32)__cvta_generic_to_shared(&Bhs[p][0]);
        bBl[p] = (u32)__cvta_generic_to_shared(&Bls[p][0]);
    }

    float acc[2][8][4];
    #pragma unroll
    for (int i = 0; i < 2; i++)
        #pragma unroll
        for (int j = 0; j < 8; j++)
            #pragma unroll
            for (int q = 0; q < 4; q++) acc[i][j][q] = 0.0f;

    const int iters = K >> 4;
    uint4 aR = *(const uint4*)Ap;
    uint4 bhR = *(const uint4*)Bph, blR = *(const uint4*)Bpl;

    *(uint4*)&Ahs[0][srow*24 + sseg] = aR;
    *(uint4*)&Bhs[0][srow*24 + sseg] = bhR;
    *(uint4*)&Bls[0][srow*24 + sseg] = blR;
    __syncthreads();

    for (int kt = 0; kt < iters; kt++) {
        const int p = kt & 1;
        if (kt + 1 < iters) {
            aR  = *(const uint4*)(Ap + (kt+1)*16);
            bhR = *(const uint4*)(Bph + (kt+1)*16);
            blR = *(const uint4*)(Bpl + (kt+1)*16);
        }
        u32 ah[2][4];
        #pragma unroll
        for (int mt = 0; mt < 2; mt++) {
            u32 off = (u32)(((wr*32 + mt*16 + a_r)*24 + a_c) * 2);
            ldsm4(ah[mt], bAh[p] + off);
        }
        #pragma unroll
        for (int ntp = 0; ntp < 4; ntp++) {
            u32 off = (u32)(((wc*64 + ntp*16 + b_r)*24 + b_c) * 2);
            u32 bh4[4], bl4[4];
            ldsm4(bh4, bBh[p] + off);
            ldsm4(bl4, bBl[p] + off);
            #pragma unroll
            for (int e = 0; e < 2; e++) {
                int nt = ntp*2 + e;
                #pragma unroll
                for (int mt = 0; mt < 2; mt++) {
                    mma16816h(acc[mt][nt], ah[mt], bh4[e*2], bh4[e*2+1]);
                    mma16816h(acc[mt][nt], ah[mt], bl4[e*2], bl4[e*2+1]);
                }
            }
        }
        if (kt + 1 < iters) {
            const int q = p ^ 1;
            *(uint4*)&Ahs[q][srow*24 + sseg] = aR;
            *(uint4*)&Bhs[q][srow*24 + sseg] = bhR;
            *(uint4*)&Bls[q][srow*24 + sseg] = blR;
        }
        __syncthreads();
    }
    #pragma unroll
    for (int mt = 0; mt < 2; mt++)
        #pragma unroll
        for (int nt = 0; nt < 8; nt++) {
            int m = m0 + wr*32 + mt*16 + g;
            int n = n0 + wc*64 + nt*8 + tg*2;
            float b0v = bias[n], b1v = bias[n+1];
            float* p2 = C + (size_t)m * N + n;
            *(float2*)p2 = make_float2(acc[mt][nt][0] + b0v, acc[mt][nt][1] + b1v);
            *(float2*)(p2 + (size_t)8*N) = make_float2(acc[mt][nt][2] + b0v, acc[mt][nt][3] + b1v);
        }
}

// ---------- persistent encoder: 512 threads, prefetched ----------
__global__ void __launch_bounds__(512) enc_persist()
{
    extern __shared__ float red_[];
    const int bk = blockIdx.x, tid = threadIdx.x, lane = tid & 31, wid = tid >> 5;
    const int g = lane >> 2, tg = lane & 3;

    { int i = bk*512 + tid;
      if (i < 16384) { ((u32*)g_ehf[0][0])[i] = 0u; ((u32*)g_ehf[0][1])[i] = 0u; } }
    float cst = 0.0f;
    gbar();

    for (int t = 0; t < Sn; t++) {
        const int rp = t & 1, wp2 = rp ^ 1;
        const uint4* Ah = g_ehf[rp][0];
        const uint4* Al = g_ehf[rp][1];

        float xg0, xg1, xg2, xg3;
        if (tid < 256) {
            const int bb = tid >> 3, jl = tid & 7;
            const size_t xw = ((size_t)(bb*Sn + t))*Gn + bk*8 + jl;
            xg0 = g_XWenc[xw]; xg1 = g_XWenc[xw+1024];
            xg2 = g_XWenc[xw+2048]; xg3 = g_XWenc[xw+3072];
        }

        float acc[2][4][4];
        #pragma unroll
        for (int a = 0; a < 2; a++)
            #pragma unroll
            for (int b = 0; b < 4; b++)
                #pragma unroll
                for (int q = 0; q < 4; q++) acc[a][b][q] = 0.0f;

        const int cb = wid*4;
        uint4 pfh0 = Ah[(cb*2)*32 + lane],   pfh1 = Ah[(cb*2+1)*32 + lane];
        uint4 pfl0 = Al[(cb*2)*32 + lane],   pfl1 = Al[(cb*2+1)*32 + lane];
        #pragma unroll
        for (int ks = 0; ks < 4; ks++) {
            const int c = cb + ks;
            uint4 fh0 = pfh0, fh1 = pfh1, fl0 = pfl0, fl1 = pfl1;
            if (ks < 3) {
                const int c2 = c + 1;
                pfh0 = Ah[(c2*2)*32 + lane]; pfh1 = Ah[(c2*2+1)*32 + lane];
                pfl0 = Al[(c2*2)*32 + lane]; pfl1 = Al[(c2*2+1)*32 + lane];
            }
            #pragma unroll
            for (int nt = 0; nt < 4; nt++) {
                uint4 wq = w_hhE_f[((size_t)(nt*128 + bk)*64 + c)*32 + lane];
                mma16816(acc[0][nt], (u32*)&fh0, wq.x, wq.y);
                mma16816(acc[0][nt], (u32*)&fh0, wq.z, wq.w);
                mma16816(acc[0][nt], (u32*)&fl0, wq.x, wq.y);
                mma16816(acc[1][nt], (u32*)&fh1, wq.x, wq.y);
                mma16816(acc[1][nt], (u32*)&fh1, wq.z, wq.w);
                mma16816(acc[1][nt], (u32*)&fl1, wq.x, wq.y);
            }
        }
        float* rw0 = &red_[wid*1056];
        #pragma unroll
        for (int mt = 0; mt < 2; mt++)
            #pragma unroll
            for (int nt = 0; nt < 4; nt++) {
                int r0 = mt*16 + g, c0 = nt*8 + tg*2;
                rw0[r0*33 + c0]       = acc[mt][nt][0];
                rw0[r0*33 + c0 + 1]   = acc[mt][nt][1];
                rw0[(r0+8)*33 + c0]   = acc[mt][nt][2];
                rw0[(r0+8)*33 + c0+1] = acc[mt][nt][3];
            }
        __syncthreads();

        if (tid < 256) {
            const int bb = tid >> 3, jl = tid & 7, j = bk*8 + jl;
            float gi = xg0, gf = xg1, gg = xg2, go = xg3;
            #pragma unroll
            for (int w = 0; w < 16; w++) {
                const float* rw = &red_[w*1056 + bb*33];
                gi += rw[jl]; gf += rw[8+jl]; gg += rw[16+jl]; go += rw[24+jl];
            }
            cst = sigm(gf)*cst + sigm(gi)*tanhf(gg);
            float h = sigm(go)*tanhf(cst);
            g_enc_out[((size_t)(bb*Sn + t))*Hn + j] = h;
            frag_store((u16*)g_ehf[wp2][0], (u16*)g_ehf[wp2][1], bb, j, h);
            if (t == Sn-1) { g_h[bb*Hn + j] = h; g_c[bb*Hn + j] = cst; }
        }
        gbar();
    }
}

// ---------- persistent decoder: 512 threads, prefetched ----------
__global__ void __launch_bounds__(512) dec_persist(const float* __restrict__ cls1_b)
{
    extern __shared__ float red_[];
    const int bk = blockIdx.x, tid = threadIdx.x, lane = tid & 31, wid = tid >> 5;
    const int g = lane >> 2, tg = lane & 3;
    float* sc    = red_;
    float* wsm   = sc + 3200;
    float* stats = wsm + 3200;
    float* ctx   = stats + 64;

    { int i = bk*512 + tid;
      if (i < Bn*Hn) {
          float h0 = g_h[i];
          int row = i >> 10, col = i & 1023;
          frag_store((u16*)g_dhf[0][0], (u16*)g_dhf[0][1], row, col, h0);
          frag_store((u16*)g_fdf[0][0], (u16*)g_fdf[0][1], row, col, h0);
      } }
    float cst = (tid < 256) ? g_c[(tid>>3)*Hn + bk*8 + (tid&7)] : 0.0f;
    gbar();

    for (int t = 0; t < Tn; t++) {
        const int rp = t & 1, wp2 = rp ^ 1;

        // P1: gates + cell (prefetched)
        {
            const uint4 *Ah, *Al, *Wf;
            int cb;
            if (wid < 8) { Ah = g_fdf[rp][0]; Al = g_fdf[rp][1]; Wf = w_ihDH_f; cb = wid*8; }
            else         { Ah = g_dhf[rp][0]; Al = g_dhf[rp][1]; Wf = w_hhD_f;  cb = (wid-8)*8; }

            float xg0, xg1, xg2, xg3;
            if (tid < 256) {
                const int bb = tid >> 3, jl = tid & 7;
                const size_t xw = ((size_t)(bb*Tn + t))*Gn + bk*8 + jl;
                xg0 = g_XWdec[xw]; xg1 = g_XWdec[xw+1024];
                xg2 = g_XWdec[xw+2048]; xg3 = g_XWdec[xw+3072];
            }

            float acc[2][4][4];
            #pragma unroll
            for (int a = 0; a < 2; a++)
                #pragma unroll
                for (int b = 0; b < 4; b++)
                    #pragma unroll
                    for (int q = 0; q < 4; q++) acc[a][b][q] = 0.0f;

            uint4 pfh0 = Ah[(cb*2)*32 + lane],   pfh1 = Ah[(cb*2+1)*32 + lane];
            uint4 pfl0 = Al[(cb*2)*32 + lane],   pfl1 = Al[(cb*2+1)*32 + lane];
            #pragma unroll
            for (int ks = 0; ks < 8; ks++) {
                const int c = cb + ks;
                uint4 fh0 = pfh0, fh1 = pfh1, fl0 = pfl0, fl1 = pfl1;
                if (ks < 7) {
                    const int c2 = c + 1;
                    pfh0 = Ah[(c2*2)*32 + lane]; pfh1 = Ah[(c2*2+1)*32 + lane];
                    pfl0 = Al[(c2*2)*32 + lane]; pfl1 = Al[(c2*2+1)*32 + lane];
                }
                #pragma unroll
                for (int nt = 0; nt < 4; nt++) {
                    uint4 wq = Wf[((size_t)(nt*128 + bk)*64 + c)*32 + lane];
                    mma16816(acc[0][nt], (u32*)&fh0, wq.x, wq.y);
                    mma16816(acc[0][nt], (u32*)&fh0, wq.z, wq.w);
                    mma16816(acc[0][nt], (u32*)&fl0, wq.x, wq.y);
                    mma16816(acc[1][nt], (u32*)&fh1, wq.x, wq.y);
                    mma16816(acc[1][nt], (u32*)&fh1, wq.z, wq.w);
                    mma16816(acc[1][nt], (u32*)&fl1, wq.x, wq.y);
                }
            }
            float* rw0 = &red_[wid*1056];
            #pragma unroll
            for (int mt = 0; mt < 2; mt++)
                #pragma unroll
                for (int nt = 0; nt < 4; nt++) {
                    int r0 = mt*16 + g, c0 = nt*8 + tg*2;
                    rw0[r0*33 + c0]       = acc[mt][nt][0];
                    rw0[r0*33 + c0 + 1]   = acc[mt][nt][1];
                    rw0[(r0+8)*33 + c0]   = acc[mt][nt][2];
                    rw0[(r0+8)*33 + c0+1] = acc[mt][nt][3];
                }
            __syncthreads();
            if (tid < 256) {
                const int bb = tid >> 3, jl = tid & 7, j = bk*8 + jl;
                float gi = xg0, gf = xg1, gg = xg2, go = xg3;
                #pragma unroll
                for (int w = 0; w < 16; w++) {
                    const float* rw = &red_[w*1056 + bb*33];
                    gi += rw[jl]; gf += rw[8+jl]; gg += rw[16+jl]; go += rw[24+jl];
                }
                cst = sigm(gf)*cst + sigm(gi)*tanhf(gg);
                float h = sigm(go)*tanhf(cst);
                g_hdf[bb*Hn + j] = h;
                frag_store((u16*)g_dhf[wp2][0], (u16*)g_dhf[wp2][1], bb, j, h);
            }
        }
        gbar();

        // P2: scores (float4 loads for MLP)
        #pragma unroll
        for (int r = 0; r < 2; r++) {
            int pair = bk*16 + wid + r*2048;
            if (pair < Bn*Sn) {
                int b = pair / Sn;
                const float4* ep4 = (const float4*)(g_enc_proj + (size_t)pair * Hn);
                const float4* hv4 = (const float4*)(g_hdf + b * Hn);
                float a = 0.f;
                #pragma unroll
                for (int it = 0; it < 8; it++) {
                    float4 e = ep4[lane + 32*it];
                    float4 h = hv4[lane + 32*it];
                    a += e.x*h.x + e.y*h.y + e.z*h.z + e.w*h.w;
                }
                #pragma unroll
                for (int o = 16; o; o >>= 1) a += __shfl_xor_sync(0xffffffffu, a, o);
                if (lane == 0) g_scores[pair] = a;
            }
        }
        gbar();

        // P3: softmax + context
        for (int i = tid; i < Bn*Sn; i += 512) sc[i] = g_scores[i];
        __syncthreads();
        #pragma unroll
        for (int q = 0; q < 2; q++) {
            int b = wid*2 + q;
            float m = -1e30f;
            for (int s = lane; s < Sn; s += 32) m = fmaxf(m, sc[b*Sn + s]);
            #pragma unroll
            for (int o = 16; o; o >>= 1) m = fmaxf(m, __shfl_xor_sync(0xffffffffu, m, o));
            float su = 0.f;
            for (int s = lane; s < Sn; s += 32) su += expf(sc[b*Sn + s] - m);
            #pragma unroll
            for (int o = 16; o; o >>= 1) su += __shfl_xor_sync(0xffffffffu, su, o);
            if (lane == 0) { stats[b] = m; stats[32 + b] = 1.0f / su; }
        }
        __syncthreads();
        for (int i = tid; i < Bn*Sn; i += 512) {
            int b = i / Sn;
            wsm[i] = expf(sc[i] - stats[b]) * stats[32 + b];
        }
        __syncthreads();
        {
            const int half = tid >> 8, ct = tid & 255;
            const int bb = ct >> 3, jl = ct & 7, j = bk*8 + jl;
            float a = 0.f;
            const float* eo = g_enc_out + ((size_t)bb*Sn) * Hn + j;
            const float* wv = wsm + bb*Sn;
            const int s0 = half*50;
            #pragma unroll 10
            for (int s = s0; s < s0 + 50; s++) a += wv[s] * eo[(size_t)s * Hn];
            ctx[tid] = a;
        }
        __syncthreads();
        if (tid < 256) {
            const int bb = tid >> 3, jl = tid & 7, j = bk*8 + jl;
            float a = ctx[tid] + ctx[256 + tid];
            frag_store((u16*)g_atf[0], (u16*)g_atf[1], bb, j, a);
        }
        gbar();

        // P4: feed = tanh([atten, hd] @ cls1 + b) (prefetched)
        {
            const uint4 *Ah, *Al;
            int cb, cw;
            if (wid < 8) { Ah = g_atf[0];      Al = g_atf[1];      cb = wid*8;     cw = 0; }
            else         { Ah = g_dhf[wp2][0]; Al = g_dhf[wp2][1]; cb = (wid-8)*8; cw = 64; }
            float fa[2][4];
            #pragma unroll
            for (int a = 0; a < 2; a++)
                #pragma unroll
                for (int q = 0; q < 4; q++) fa[a][q] = 0.0f;

            uint4 pfh0 = Ah[(cb*2)*32 + lane],   pfh1 = Ah[(cb*2+1)*32 + lane];
            uint4 pfl0 = Al[(cb*2)*32 + lane],   pfl1 = Al[(cb*2+1)*32 + lane];
            #pragma unroll
            for (int ks = 0; ks < 8; ks++) {
                const int c = cb + ks;
                uint4 fh0 = pfh0, fh1 = pfh1, fl0 = pfl0, fl1 = pfl1;
                if (ks < 7) {
                    const int c2 = c + 1;
                    pfh0 = Ah[(c2*2)*32 + lane]; pfh1 = Ah[(c2*2+1)*32 + lane];
                    pfl0 = Al[(c2*2)*32 + lane]; pfl1 = Al[(c2*2+1)*32 + lane];
                }
                uint4 wq = w_c1_f[((size_t)bk*128 + cw + c)*32 + lane];
                mma16816(fa[0], (u32*)&fh0, wq.x, wq.y);
                mma16816(fa[0], (u32*)&fh0, wq.z, wq.w);
                mma16816(fa[0], (u32*)&fl0, wq.x, wq.y);
                mma16816(fa[1], (u32*)&fh1, wq.x, wq.y);
                mma16816(fa[1], (u32*)&fh1, wq.z, wq.w);
                mma16816(fa[1], (u32*)&fl1, wq.x, wq.y);
            }
            float* rw0 = &red_[wid*1056];
            #pragma unroll
            for (int mt = 0; mt < 2; mt++) {
                int r0 = mt*16 + g, c0 = tg*2;
                rw0[r0*33 + c0]       = fa[mt][0];
                rw0[r0*33 + c0 + 1]   = fa[mt][1];
                rw0[(r0+8)*33 + c0]   = fa[mt][2];
                rw0[(r0+8)*33 + c0+1] = fa[mt][3];
            }
            __syncthreads();
            if (tid < 256) {
                const int bb = tid >> 3, jl = tid & 7, j = bk*8 + jl;
                float a = cls1_b[j];
                #pragma unroll
                for (int w = 0; w < 16; w++) a += red_[w*1056 + bb*33 + jl];
                float f = tanhf(a);
                frag_store((u16*)g_fdf[wp2][0], (u16*)g_fdf[wp2][1], bb, j, f);
                g_hid16[((size_t)(bb*Tn + t))*Hn + j] =
                    __half_as_ushort(__float2half_rn(f));
            }
        }
        gbar();
    }
}

extern "C" void kernel_launch(void* const* d_in, const int* in_sizes, int n_in,
                              void* d_out, int out_size)
{
    const int*   source_data = (const int*)  d_in[0];
    const int*   target_data = (const int*)  d_in[1];
    const float* src_emb  = (const float*)d_in[2];
    const float* tgt_emb  = (const float*)d_in[3];
    const float* enc_Wih  = (const float*)d_in[4];
    const float* enc_Whh  = (const float*)d_in[5];
    const float* enc_b    = (const float*)d_in[6];
    const float* dec_Wih  = (const float*)d_in[7];
    const float* dec_Whh  = (const float*)d_in[8];
    const float* dec_b    = (const float*)d_in[9];
    const float* att1_W   = (const float*)d_in[10];
    const float* att1_b   = (const float*)d_in[11];
    const float* cls1_W   = (const float*)d_in[12];
    const float* cls1_b   = (const float*)d_in[13];
    const float* cls2_W   = (const float*)d_in[14];
    const float* cls2_b   = (const float*)d_in[15];
    float* out = (float*)d_out;

    float *XWenc, *XWdec, *enc_out, *enc_proj;
    void *ihE_h,*ihE_l,*ihD0_h,*ihD0_l,*att_h,*att_l,*c2_h,*c2_l;
    void *hhE_f,*ihDH_f,*hhD_f,*c1_f,*hid16;
    cudaGetSymbolAddress((void**)&XWenc,   g_XWenc);
    cudaGetSymbolAddress((void**)&XWdec,   g_XWdec);
    cudaGetSymbolAddress((void**)&enc_out, g_enc_out);
    cudaGetSymbolAddress((void**)&enc_proj,g_enc_proj);
    cudaGetSymbolAddress(&hid16,  g_hid16);
    cudaGetSymbolAddress(&ihE_h,  w_ihE_h);  cudaGetSymbolAddress(&ihE_l,  w_ihE_l);
    cudaGetSymbolAddress(&ihD0_h, w_ihD0_h); cudaGetSymbolAddress(&ihD0_l, w_ihD0_l);
    cudaGetSymbolAddress(&att_h,  w_att_h);  cudaGetSymbolAddress(&att_l,  w_att_l);
    cudaGetSymbolAddress(&c2_h,   w_c2_h);   cudaGetSymbolAddress(&c2_l,   w_c2_l);
    cudaGetSymbolAddress(&hhE_f,  w_hhE_f);  cudaGetSymbolAddress(&ihDH_f, w_ihDH_f);
    cudaGetSymbolAddress(&hhD_f,  w_hhD_f);  cudaGetSymbolAddress(&c1_f,   w_c1_f);

    cudaFuncSetAttribute(enc_persist, cudaFuncAttributeMaxDynamicSharedMemorySize, RED_F*4);
    cudaFuncSetAttribute(dec_persist, cudaFuncAttributeMaxDynamicSharedMemorySize, RED_F*4);

    CJobs jb;
    jb.j[0] = { enc_Wih,                    ihE_h,  ihE_l,   512, 4096, 0, 0     };
    jb.j[1] = { dec_Wih,                    ihD0_h, ihD0_l,  512, 4096, 0, 2048  };
    jb.j[2] = { att1_W,                     att_h,  att_l,  1024, 1024, 0, 4096  };
    jb.j[3] = { cls2_W,                     c2_h,   c2_l,   1024, Vn,   3, 5120  };
    jb.j[4] = { enc_Whh,                    hhE_f,  nullptr,1024, 4096, 1, 37120 };
    jb.j[5] = { dec_Wih + (size_t)512*4096, ihDH_f, nullptr,1024, 4096, 1, 41216 };
    jb.j[6] = { dec_Whh,                    hhD_f,  nullptr,1024, 4096, 1, 45312 };
    jb.j[7] = { cls1_W,                     c1_f,   nullptr,2048, 1024, 1, 49408 };
    conv_all<<<51456, 256>>>(jb);                                              // 1

    gemm_big<<<dim3(25, 32), 256>>>(src_emb, source_data,
        (u16*)ihE_h, (u16*)ihE_l, enc_b, XWenc, Gn, En);                       // 2
    gemm_big<<<dim3(25, 32), 256>>>(tgt_emb, target_data,
        (u16*)ihD0_h, (u16*)ihD0_l, dec_b, XWdec, Gn, En);                     // 3
    enc_persist<<<NBLK, 512, RED_F*4>>>();                                     // 4
    gemm_big<<<dim3(25, 8), 256>>>(enc_out, nullptr,
        (u16*)att_h, (u16*)att_l, att1_b, enc_proj, Hn, Hn);                   // 5
    dec_persist<<<NBLK, 512, RED_F*4>>>(cls1_b);                               // 6  <- ncu
    gemm_cls<<<dim3(25, 250), 256>>>((u16*)hid16,
        (u16*)c2_h, (u16*)c2_l, cls2_b, out, Vn, Hn);                          // 7
}

// round 11
// speedup vs baseline: 2.5317x; 1.0697x over previous
#include <cuda_runtime.h>
#include <cuda_fp16.h>
#include <math.h>
#include <stdint.h>

typedef unsigned short u16;
typedef unsigned int   u32;

#define Bn 32
#define Sn 100
#define Tn 100
#define En 512
#define Hn 1024
#define Vn 32000
#define Gn 4096
#define NBLK 128
#define RED_F (16*1056)

// fp32 scratch
__device__ float g_XWenc[Bn*Sn*Gn];
__device__ float g_XWdec[Bn*Tn*Gn];
__device__ float g_enc_out[Bn*Sn*Hn];
__device__ float g_enc_proj[Bn*Sn*Hn];
__device__ float g_h[Bn*Hn];
__device__ float g_c[Bn*Hn];
__device__ float g_hdf[Bn*Hn];
__device__ float g_scores[Bn*Sn];

// fp16 A operands for feed-forward GEMMs
__device__ u16 g_hid16[Bn*Tn*Hn];       // decoder hidden -> classifier
__device__ u16 g_eo16 [Bn*Sn*Hn];       // encoder out   -> att projection
__device__ u16 g_semb16[Bn*Sn*En];      // gathered src embeddings
__device__ u16 g_temb16[Bn*Tn*En];      // gathered tgt embeddings

// fragment-major fp16 state: uint4 idx = (chunk*2+mt)*32+lane, chunk = k16
__device__ uint4 g_ehf[2][4096];
__device__ uint4 g_dhf[2][4096];
__device__ uint4 g_fdf[2][4096];
__device__ uint4 g_atf[4096];

// transposed [n][k] fp16 hi/lo weights (feed-forward GEMMs)
__device__ u16 w_ihE_h [(size_t)Gn*En],  w_ihE_l [(size_t)Gn*En];
__device__ u16 w_ihD0_h[(size_t)Gn*En],  w_ihD0_l[(size_t)Gn*En];
__device__ u16 w_att_h [(size_t)Hn*Hn],  w_att_l [(size_t)Hn*Hn];
__device__ u16 w_c2_h  [(size_t)Vn*Hn],  w_c2_l  [(size_t)Vn*Hn];

// fragment-major fp16 weights: uint4 {b0h,b1h,b0l,b1l}, idx = (ng*nch+c)*32+lane
__device__ uint4 w_hhE_f [512*64*32];
__device__ uint4 w_ihDH_f[512*64*32];
__device__ uint4 w_hhD_f [512*64*32];
__device__ uint4 w_c1_f  [128*128*32];

__device__ unsigned g_cnt, g_gen;
__device__ __forceinline__ void gbar() {
    __syncthreads();
    if (threadIdx.x == 0) {
        __threadfence();
        unsigned my = *((volatile unsigned*)&g_gen);
        unsigned a = atomicAdd(&g_cnt, 1u);
        if (a == NBLK - 1u) { g_cnt = 0u; __threadfence(); *((volatile unsigned*)&g_gen) = my + 1u; }
        else { while (*((volatile unsigned*)&g_gen) == my) {} }
        __threadfence();
    }
    __syncthreads();
}

__device__ __forceinline__ float sigm(float x){ return 1.0f/(1.0f + expf(-x)); }
__device__ __forceinline__ u16 fhi(float v){ return __half_as_ushort(__float2half_rn(v)); }
__device__ __forceinline__ u16 flo(float v){
    __half h = __float2half_rn(v);
    return __half_as_ushort(__float2half_rn(v - __half2float(h)));
}
__device__ __forceinline__ u32 pack2(u16 a, u16 b){ return (u32)a | ((u32)b << 16); }
__device__ __forceinline__ void mma16816h(float* c, const u32* a, u32 b0, u32 b1) {
    asm volatile("mma.sync.aligned.m16n8k16.row.col.f32.f16.f16.f32 "
        "{%0,%1,%2,%3},{%4,%5,%6,%7},{%8,%9},{%0,%1,%2,%3};"
        : "+f"(c[0]), "+f"(c[1]), "+f"(c[2]), "+f"(c[3])
        : "r"(a[0]), "r"(a[1]), "r"(a[2]), "r"(a[3]), "r"(b0), "r"(b1));
}
__device__ __forceinline__ void ldsm4(u32* r, u32 addr) {
    asm volatile("ldmatrix.sync.aligned.m8n8.x4.shared.b16 {%0,%1,%2,%3}, [%4];"
        : "=r"(r[0]), "=r"(r[1]), "=r"(r[2]), "=r"(r[3]) : "r"(addr));
}
// scatter one fp16 state element into fragment-major array
__device__ __forceinline__ void frag_store16(u16* F, int row, int col, float v){
    int ch = col >> 4, kc = col & 15, mt = row >> 4, rg = row & 15;
    int lane = (rg & 7)*4 + ((kc >> 1) & 3);
    int w = ((kc >> 3) << 1) + (rg >> 3);
    size_t idx = ((size_t)(((ch*2 + mt)*32) + lane) << 3) + (w << 1) + (kc & 1);
    F[idx] = fhi(v);
}

// ---------- merged conversion / gather ----------
struct CJ { const float* W; void* Oh; void* Ol; int K, N, mode, boff; };
struct CJobs { CJ j[10]; };

__global__ void __launch_bounds__(256) conv_all(CJobs jb)
{
    __shared__ float tile[32][33];
    int blk = blockIdx.x, ji = 0;
    for (int i = 9; i >= 0; i--) if (blk >= jb.j[i].boff) { ji = i; break; }
    const CJ& J = jb.j[ji];
    int local = blk - J.boff;
    const int tid = threadIdx.x, lane = tid & 31;
    if (J.mode == 3) {
        // transposed fp16 hi/lo: W[K][N] -> Oh/Ol [N][K]
        int ntl = J.N >> 5;
        int tk = local / ntl, tn = local % ntl;
        int n0 = tn*32, k0 = tk*32;
        int tx = lane, ty = tid >> 5;
        #pragma unroll
        for (int i = 0; i < 4; i++)
            tile[ty + i*8][tx] = J.W[(size_t)(k0 + ty + i*8)*J.N + n0 + tx];
        __syncthreads();
        u16* Oh = (u16*)J.Oh; u16* Ol = (u16*)J.Ol;
        #pragma unroll
        for (int i = 0; i < 4; i++) {
            int nn = ty + i*8;
            float v = tile[tx][nn];
            Oh[(size_t)(n0+nn)*J.K + k0 + tx] = fhi(v);
            Ol[(size_t)(n0+nn)*J.K + k0 + tx] = flo(v);
        }
    } else if (J.mode == 1) {
        // fragment-major fp16 hi/lo: W[K][N] -> uint4 {b0h,b1h,b0l,b1l}
        int nch = J.K >> 4;
        int pair = local*8 + (tid >> 5);
        int ng = pair / nch, c = pair % nch;
        int n = ng*8 + (lane >> 2), k = c*16 + (lane & 3)*2;
        const float* W = J.W;
        float v0 = W[(size_t)k*J.N + n],     v1 = W[(size_t)(k+1)*J.N + n];
        float v2 = W[(size_t)(k+8)*J.N + n], v3 = W[(size_t)(k+9)*J.N + n];
        ((uint4*)J.Oh)[(size_t)pair*32 + lane] =
            make_uint4(pack2(fhi(v0),fhi(v1)), pack2(fhi(v2),fhi(v3)),
                       pack2(flo(v0),flo(v1)), pack2(flo(v2),flo(v3)));
    } else {
        // mode 5: embedding gather -> fp16 rows (idx ptr passed in Ol)
        const int* idxp = (const int*)J.Ol;
        size_t base = (size_t)idxp[local] * J.K;
        u16* Oh = (u16*)J.Oh;
        for (int k = tid; k < J.K; k += 256)
            Oh[(size_t)local*J.K + k] = fhi(J.W[base + k]);
    }
}

// ---------- GEMM: C[M,N] = A(fp16)[M,K] @ B(fp16 hi/lo)^T + bias, 2-term ----------
__global__ void __launch_bounds__(256) gemm_h16(
    const u16* __restrict__ A,
    const u16* __restrict__ Bh, const u16* __restrict__ Bl,
    const float* __restrict__ bias, float* __restrict__ C, int N, int K)
{
    __shared__ __align__(16) u16 Ahs[2][128*24];
    __shared__ __align__(16) u16 Bhs[2][128*24], Bls[2][128*24];
    const int t = threadIdx.x, lane = t & 31, wid = t >> 5;
    const int wr = wid & 3, wc = wid >> 2;
    const int g = lane >> 2, tg = lane & 3;
    const int m0 = blockIdx.x * 128, n0 = blockIdx.y * 128;

    const int srow = t >> 1, sseg = (t & 1) * 8;
    const u16* Ap  = A  + (size_t)(m0 + srow) * K + sseg;
    const u16* Bph = Bh + (size_t)(n0 + srow) * K + sseg;
    const u16* Bpl = Bl + (size_t)(n0 + srow) * K + sseg;

    const int a_r = ((lane>>3)&1)*8 + (lane&7), a_c = (lane>>4)*8;
    const int b_r = (lane>>4)*8 + (lane&7),     b_c = ((lane>>3)&1)*8;
    u32 bAh[2], bBh[2], bBl[2];
    #pragma unroll
    for (int p = 0; p < 2; p++) {
        bAh[p] = (u32)__cvta_generic_to_shared(&Ahs[p][0]);
        bBh[p] = (u32)__cvta_generic_to_shared(&Bhs[p][0]);
        bBl[p] = (u32)__cvta_generic_to_shared(&Bls[p][0]);
    }

    float acc[2][8][4];
    #pragma unroll
    for (int i = 0; i < 2; i++)
        #pragma unroll
        for (int j = 0; j < 8; j++)
            #pragma unroll
            for (int q = 0; q < 4; q++) acc[i][j][q] = 0.0f;

    const int iters = K >> 4;
    uint4 aR = *(const uint4*)Ap;
    uint4 bhR = *(const uint4*)Bph, blR = *(const uint4*)Bpl;

    *(uint4*)&Ahs[0][srow*24 + sseg] = aR;
    *(uint4*)&Bhs[0][srow*24 + sseg] = bhR;
    *(uint4*)&Bls[0][srow*24 + sseg] = blR;
    __syncthreads();

    for (int kt = 0; kt < iters; kt++) {
        const int p = kt & 1;
        if (kt + 1 < iters) {
            aR  = *(const uint4*)(Ap + (kt+1)*16);
            bhR = *(const uint4*)(Bph + (kt+1)*16);
            blR = *(const uint4*)(Bpl + (kt+1)*16);
        }
        u32 ah[2][4];
        #pragma unroll
        for (int mt = 0; mt < 2; mt++) {
            u32 off = (u32)(((wr*32 + mt*16 + a_r)*24 + a_c) * 2);
            ldsm4(ah[mt], bAh[p] + off);
        }
        #pragma unroll
        for (int ntp = 0; ntp < 4; ntp++) {
            u32 off = (u32)(((wc*64 + ntp*16 + b_r)*24 + b_c) * 2);
            u32 bh4[4], bl4[4];
            ldsm4(bh4, bBh[p] + off);
            ldsm4(bl4, bBl[p] + off);
            #pragma unroll
            for (int e = 0; e < 2; e++) {
                int nt = ntp*2 + e;
                #pragma unroll
                for (int mt = 0; mt < 2; mt++) {
                    mma16816h(acc[mt][nt], ah[mt], bh4[e*2], bh4[e*2+1]);
                    mma16816h(acc[mt][nt], ah[mt], bl4[e*2], bl4[e*2+1]);
                }
            }
        }
        if (kt + 1 < iters) {
            const int q = p ^ 1;
            *(uint4*)&Ahs[q][srow*24 + sseg] = aR;
            *(uint4*)&Bhs[q][srow*24 + sseg] = bhR;
            *(uint4*)&Bls[q][srow*24 + sseg] = blR;
        }
        __syncthreads();
    }
    #pragma unroll
    for (int mt = 0; mt < 2; mt++)
        #pragma unroll
        for (int nt = 0; nt < 8; nt++) {
            int m = m0 + wr*32 + mt*16 + g;
            int n = n0 + wc*64 + nt*8 + tg*2;
            float b0v = bias[n], b1v = bias[n+1];
            float* p2 = C + (size_t)m * N + n;
            *(float2*)p2 = make_float2(acc[mt][nt][0] + b0v, acc[mt][nt][1] + b1v);
            *(float2*)(p2 + (size_t)8*N) = make_float2(acc[mt][nt][2] + b0v, acc[mt][nt][3] + b1v);
        }
}

// ---------- persistent encoder: fp16 state, 2-term MMA ----------
__global__ void __launch_bounds__(512) enc_persist()
{
    extern __shared__ float red_[];
    const int bk = blockIdx.x, tid = threadIdx.x, lane = tid & 31, wid = tid >> 5;
    const int g = lane >> 2, tg = lane & 3;

    { int i = bk*512 + tid;
      if (i < 16384) ((u32*)g_ehf[0])[i] = 0u; }
    float cst = 0.0f;
    gbar();

    for (int t = 0; t < Sn; t++) {
        const int rp = t & 1, wp2 = rp ^ 1;
        const uint4* Af = g_ehf[rp];

        float xg0, xg1, xg2, xg3;
        if (tid < 256) {
            const int bb = tid >> 3, jl = tid & 7;
            const size_t xw = ((size_t)(bb*Sn + t))*Gn + bk*8 + jl;
            xg0 = g_XWenc[xw]; xg1 = g_XWenc[xw+1024];
            xg2 = g_XWenc[xw+2048]; xg3 = g_XWenc[xw+3072];
        }

        float acc[2][4][4];
        #pragma unroll
        for (int a = 0; a < 2; a++)
            #pragma unroll
            for (int b = 0; b < 4; b++)
                #pragma unroll
                for (int q = 0; q < 4; q++) acc[a][b][q] = 0.0f;

        const int cb = wid*4;
        uint4 pf0 = Af[(cb*2)*32 + lane], pf1 = Af[(cb*2+1)*32 + lane];
        #pragma unroll
        for (int ks = 0; ks < 4; ks++) {
            const int c = cb + ks;
            uint4 f0 = pf0, f1 = pf1;
            if (ks < 3) {
                pf0 = Af[((c+1)*2)*32 + lane];
                pf1 = Af[((c+1)*2+1)*32 + lane];
            }
            #pragma unroll
            for (int nt = 0; nt < 4; nt++) {
                uint4 wq = w_hhE_f[((size_t)(nt*128 + bk)*64 + c)*32 + lane];
                mma16816h(acc[0][nt], (u32*)&f0, wq.x, wq.y);
                mma16816h(acc[0][nt], (u32*)&f0, wq.z, wq.w);
                mma16816h(acc[1][nt], (u32*)&f1, wq.x, wq.y);
                mma16816h(acc[1][nt], (u32*)&f1, wq.z, wq.w);
            }
        }
        float* rw0 = &red_[wid*1056];
        #pragma unroll
        for (int mt = 0; mt < 2; mt++)
            #pragma unroll
            for (int nt = 0; nt < 4; nt++) {
                int r0 = mt*16 + g, c0 = nt*8 + tg*2;
                rw0[r0*33 + c0]       = acc[mt][nt][0];
                rw0[r0*33 + c0 + 1]   = acc[mt][nt][1];
                rw0[(r0+8)*33 + c0]   = acc[mt][nt][2];
                rw0[(r0+8)*33 + c0+1] = acc[mt][nt][3];
            }
        __syncthreads();

        if (tid < 256) {
            const int bb = tid >> 3, jl = tid & 7, j = bk*8 + jl;
            float gi = xg0, gf = xg1, gg = xg2, go = xg3;
            #pragma unroll
            for (int w = 0; w < 16; w++) {
                const float* rw = &red_[w*1056 + bb*33];
                gi += rw[jl]; gf += rw[8+jl]; gg += rw[16+jl]; go += rw[24+jl];
            }
            cst = sigm(gf)*cst + sigm(gi)*tanhf(gg);
            float h = sigm(go)*tanhf(cst);
            const size_t eo = ((size_t)(bb*Sn + t))*Hn + j;
            g_enc_out[eo] = h;
            g_eo16[eo] = fhi(h);
            frag_store16((u16*)g_ehf[wp2], bb, j, h);
            if (t == Sn-1) { g_h[bb*Hn + j] = h; g_c[bb*Hn + j] = cst; }
        }
        gbar();
    }
}

// ---------- persistent decoder: fp16 state, 2-term MMA ----------
__global__ void __launch_bounds__(512) dec_persist(const float* __restrict__ cls1_b)
{
    extern __shared__ float red_[];
    const int bk = blockIdx.x, tid = threadIdx.x, lane = tid & 31, wid = tid >> 5;
    const int g = lane >> 2, tg = lane & 3;
    float* sc    = red_;
    float* wsm   = sc + 3200;
    float* stats = wsm + 3200;
    float* ctx   = stats + 64;

    { int i = bk*512 + tid;
      if (i < Bn*Hn) {
          float h0 = g_h[i];
          int row = i >> 10, col = i & 1023;
          frag_store16((u16*)g_dhf[0], row, col, h0);
          frag_store16((u16*)g_fdf[0], row, col, h0);
      } }
    float cst = (tid < 256) ? g_c[(tid>>3)*Hn + bk*8 + (tid&7)] : 0.0f;
    gbar();

    for (int t = 0; t < Tn; t++) {
        const int rp = t & 1, wp2 = rp ^ 1;

        // P1: gates + cell
        {
            const uint4 *Af, *Wf;
            int cb;
            if (wid < 8) { Af = g_fdf[rp]; Wf = w_ihDH_f; cb = wid*8; }
            else         { Af = g_dhf[rp]; Wf = w_hhD_f;  cb = (wid-8)*8; }

            float xg0, xg1, xg2, xg3;
            if (tid < 256) {
                const int bb = tid >> 3, jl = tid & 7;
                const size_t xw = ((size_t)(bb*Tn + t))*Gn + bk*8 + jl;
                xg0 = g_XWdec[xw]; xg1 = g_XWdec[xw+1024];
                xg2 = g_XWdec[xw+2048]; xg3 = g_XWdec[xw+3072];
            }

            float acc[2][4][4];
            #pragma unroll
            for (int a = 0; a < 2; a++)
                #pragma unroll
                for (int b = 0; b < 4; b++)
                    #pragma unroll
                    for (int q = 0; q < 4; q++) acc[a][b][q] = 0.0f;

            uint4 pf0 = Af[(cb*2)*32 + lane], pf1 = Af[(cb*2+1)*32 + lane];
            #pragma unroll
            for (int ks = 0; ks < 8; ks++) {
                const int c = cb + ks;
                uint4 f0 = pf0, f1 = pf1;
                if (ks < 7) {
                    pf0 = Af[((c+1)*2)*32 + lane];
                    pf1 = Af[((c+1)*2+1)*32 + lane];
                }
                #pragma unroll
                for (int nt = 0; nt < 4; nt++) {
                    uint4 wq = Wf[((size_t)(nt*128 + bk)*64 + c)*32 + lane];
                    mma16816h(acc[0][nt], (u32*)&f0, wq.x, wq.y);
                    mma16816h(acc[0][nt], (u32*)&f0, wq.z, wq.w);
                    mma16816h(acc[1][nt], (u32*)&f1, wq.x, wq.y);
                    mma16816h(acc[1][nt], (u32*)&f1, wq.z, wq.w);
                }
            }
            float* rw0 = &red_[wid*1056];
            #pragma unroll
            for (int mt = 0; mt < 2; mt++)
                #pragma unroll
                for (int nt = 0; nt < 4; nt++) {
                    int r0 = mt*16 + g, c0 = nt*8 + tg*2;
                    rw0[r0*33 + c0]       = acc[mt][nt][0];
                    rw0[r0*33 + c0 + 1]   = acc[mt][nt][1];
                    rw0[(r0+8)*33 + c0]   = acc[mt][nt][2];
                    rw0[(r0+8)*33 + c0+1] = acc[mt][nt][3];
                }
            __syncthreads();
            if (tid < 256) {
                const int bb = tid >> 3, jl = tid & 7, j = bk*8 + jl;
                float gi = xg0, gf = xg1, gg = xg2, go = xg3;
                #pragma unroll
                for (int w = 0; w < 16; w++) {
                    const float* rw = &red_[w*1056 + bb*33];
                    gi += rw[jl]; gf += rw[8+jl]; gg += rw[16+jl]; go += rw[24+jl];
                }
                cst = sigm(gf)*cst + sigm(gi)*tanhf(gg);
                float h = sigm(go)*tanhf(cst);
                g_hdf[bb*Hn + j] = h;
                frag_store16((u16*)g_dhf[wp2], bb, j, h);
            }
        }
        gbar();

        // P2: attention scores
        #pragma unroll
        for (int r = 0; r < 2; r++) {
            int pair = bk*16 + wid + r*2048;
            if (pair < Bn*Sn) {
                int b = pair / Sn;
                const float4* ep4 = (const float4*)(g_enc_proj + (size_t)pair * Hn);
                const float4* hv4 = (const float4*)(g_hdf + b * Hn);
                float a = 0.f;
                #pragma unroll
                for (int it = 0; it < 8; it++) {
                    float4 e = ep4[lane + 32*it];
                    float4 h = hv4[lane + 32*it];
                    a += e.x*h.x + e.y*h.y + e.z*h.z + e.w*h.w;
                }
                #pragma unroll
                for (int o = 16; o; o >>= 1) a += __shfl_xor_sync(0xffffffffu, a, o);
                if (lane == 0) g_scores[pair] = a;
            }
        }
        gbar();

        // P3: softmax + context
        for (int i = tid; i < Bn*Sn; i += 512) sc[i] = g_scores[i];
        __syncthreads();
        #pragma unroll
        for (int q = 0; q < 2; q++) {
            int b = wid*2 + q;
            float m = -1e30f;
            for (int s = lane; s < Sn; s += 32) m = fmaxf(m, sc[b*Sn + s]);
            #pragma unroll
            for (int o = 16; o; o >>= 1) m = fmaxf(m, __shfl_xor_sync(0xffffffffu, m, o));
            float su = 0.f;
            for (int s = lane; s < Sn; s += 32) su += expf(sc[b*Sn + s] - m);
            #pragma unroll
            for (int o = 16; o; o >>= 1) su += __shfl_xor_sync(0xffffffffu, su, o);
            if (lane == 0) { stats[b] = m; stats[32 + b] = 1.0f / su; }
        }
        __syncthreads();
        for (int i = tid; i < Bn*Sn; i += 512) {
            int b = i / Sn;
            wsm[i] = expf(sc[i] - stats[b]) * stats[32 + b];
        }
        __syncthreads();
        {
            const int half = tid >> 8, ct = tid & 255;
            const int bb = ct >> 3, jl = ct & 7, j = bk*8 + jl;
            float a = 0.f;
            const float* eo = g_enc_out + ((size_t)bb*Sn) * Hn + j;
            const float* wv = wsm + bb*Sn;
            const int s0 = half*50;
            #pragma unroll 10
            for (int s = s0; s < s0 + 50; s++) a += wv[s] * eo[(size_t)s * Hn];
            ctx[tid] = a;
        }
        __syncthreads();
        if (tid < 256) {
            const int bb = tid >> 3, jl = tid & 7, j = bk*8 + jl;
            float a = ctx[tid] + ctx[256 + tid];
            frag_store16((u16*)g_atf, bb, j, a);
        }
        gbar();

        // P4: feed = tanh([atten, hd] @ cls1 + b)
        {
            const uint4 *Af;
            int cb, cw;
            if (wid < 8) { Af = g_atf;      cb = wid*8;     cw = 0; }
            else         { Af = g_dhf[wp2]; cb = (wid-8)*8; cw = 64; }
            float fa[2][4];
            #pragma unroll
            for (int a = 0; a < 2; a++)
                #pragma unroll
                for (int q = 0; q < 4; q++) fa[a][q] = 0.0f;

            uint4 pf0 = Af[(cb*2)*32 + lane], pf1 = Af[(cb*2+1)*32 + lane];
            #pragma unroll
            for (int ks = 0; ks < 8; ks++) {
                const int c = cb + ks;
                uint4 f0 = pf0, f1 = pf1;
                if (ks < 7) {
                    pf0 = Af[((c+1)*2)*32 + lane];
                    pf1 = Af[((c+1)*2+1)*32 + lane];
                }
                uint4 wq = w_c1_f[((size_t)bk*128 + cw + c)*32 + lane];
                mma16816h(fa[0], (u32*)&f0, wq.x, wq.y);
                mma16816h(fa[0], (u32*)&f0, wq.z, wq.w);
                mma16816h(fa[1], (u32*)&f1, wq.x, wq.y);
                mma16816h(fa[1], (u32*)&f1, wq.z, wq.w);
            }
            float* rw0 = &red_[wid*1056];
            #pragma unroll
            for (int mt = 0; mt < 2; mt++) {
                int r0 = mt*16 + g, c0 = tg*2;
                rw0[r0*33 + c0]       = fa[mt][0];
                rw0[r0*33 + c0 + 1]   = fa[mt][1];
                rw0[(r0+8)*33 + c0]   = fa[mt][2];
                rw0[(r0+8)*33 + c0+1] = fa[mt][3];
            }
            __syncthreads();
            if (tid < 256) {
                const int bb = tid >> 3, jl = tid & 7, j = bk*8 + jl;
                float a = cls1_b[j];
                #pragma unroll
                for (int w = 0; w < 16; w++) a += red_[w*1056 + bb*33 + jl];
                float f = tanhf(a);
                frag_store16((u16*)g_fdf[wp2], bb, j, f);
                g_hid16[((size_t)(bb*Tn + t))*Hn + j] = fhi(f);
            }
        }
        gbar();
    }
}

extern "C" void kernel_launch(void* const* d_in, const int* in_sizes, int n_in,
                              void* d_out, int out_size)
{
    const int*   source_data = (const int*)  d_in[0];
    const int*   target_data = (const int*)  d_in[1];
    const float* src_emb  = (const float*)d_in[2];
    const float* tgt_emb  = (const float*)d_in[3];
    const float* enc_Wih  = (const float*)d_in[4];
    const float* enc_Whh  = (const float*)d_in[5];
    const float* enc_b    = (const float*)d_in[6];
    const float* dec_Wih  = (const float*)d_in[7];
    const float* dec_Whh  = (const float*)d_in[8];
    const float* dec_b    = (const float*)d_in[9];
    const float* att1_W   = (const float*)d_in[10];
    const float* att1_b   = (const float*)d_in[11];
    const float* cls1_W   = (const float*)d_in[12];
    const float* cls1_b   = (const float*)d_in[13];
    const float* cls2_W   = (const float*)d_in[14];
    const float* cls2_b   = (const float*)d_in[15];
    float* out = (float*)d_out;

    float *XWenc, *XWdec, *enc_proj;
    void *ihE_h,*ihE_l,*ihD0_h,*ihD0_l,*att_h,*att_l,*c2_h,*c2_l;
    void *hhE_f,*ihDH_f,*hhD_f,*c1_f;
    void *hid16,*eo16,*semb16,*temb16;
    cudaGetSymbolAddress((void**)&XWenc,   g_XWenc);
    cudaGetSymbolAddress((void**)&XWdec,   g_XWdec);
    cudaGetSymbolAddress((void**)&enc_proj,g_enc_proj);
    cudaGetSymbolAddress(&hid16,  g_hid16);  cudaGetSymbolAddress(&eo16, g_eo16);
    cudaGetSymbolAddress(&semb16, g_semb16); cudaGetSymbolAddress(&temb16, g_temb16);
    cudaGetSymbolAddress(&ihE_h,  w_ihE_h);  cudaGetSymbolAddress(&ihE_l,  w_ihE_l);
    cudaGetSymbolAddress(&ihD0_h, w_ihD0_h); cudaGetSymbolAddress(&ihD0_l, w_ihD0_l);
    cudaGetSymbolAddress(&att_h,  w_att_h);  cudaGetSymbolAddress(&att_l,  w_att_l);
    cudaGetSymbolAddress(&c2_h,   w_c2_h);   cudaGetSymbolAddress(&c2_l,   w_c2_l);
    cudaGetSymbolAddress(&hhE_f,  w_hhE_f);  cudaGetSymbolAddress(&ihDH_f, w_ihDH_f);
    cudaGetSymbolAddress(&hhD_f,  w_hhD_f);  cudaGetSymbolAddress(&c1_f,   w_c1_f);

    cudaFuncSetAttribute(enc_persist, cudaFuncAttributeMaxDynamicSharedMemorySize, RED_F*4);
    cudaFuncSetAttribute(dec_persist, cudaFuncAttributeMaxDynamicSharedMemorySize, RED_F*4);

    CJobs jb;
    jb.j[0] = { enc_Wih,                    ihE_h,  ihE_l,   512, 4096, 3, 0     };
    jb.j[1] = { dec_Wih,                    ihD0_h, ihD0_l,  512, 4096, 3, 2048  };
    jb.j[2] = { att1_W,                     att_h,  att_l,  1024, 1024, 3, 4096  };
    jb.j[3] = { cls2_W,                     c2_h,   c2_l,   1024, Vn,   3, 5120  };
    jb.j[4] = { enc_Whh,                    hhE_f,  nullptr,1024, 4096, 1, 37120 };
    jb.j[5] = { dec_Wih + (size_t)512*4096, ihDH_f, nullptr,1024, 4096, 1, 41216 };
    jb.j[6] = { dec_Whh,                    hhD_f,  nullptr,1024, 4096, 1, 45312 };
    jb.j[7] = { cls1_W,                     c1_f,   nullptr,2048, 1024, 1, 49408 };
    jb.j[8] = { src_emb, semb16, (void*)source_data,  512, 0, 5, 51456 };
    jb.j[9] = { tgt_emb, temb16, (void*)target_data,  512, 0, 5, 54656 };
    conv_all<<<57856, 256>>>(jb);                                              // 1

    gemm_h16<<<dim3(25, 32), 256>>>((u16*)semb16,
        (u16*)ihE_h, (u16*)ihE_l, enc_b, XWenc, Gn, En);                       // 2
    gemm_h16<<<dim3(25, 32), 256>>>((u16*)temb16,
        (u16*)ihD0_h, (u16*)ihD0_l, dec_b, XWdec, Gn, En);                     // 3
    enc_persist<<<NBLK, 512, RED_F*4>>>();                                     // 4
    gemm_h16<<<dim3(25, 8), 256>>>((u16*)eo16,
        (u16*)att_h, (u16*)att_l, att1_b, enc_proj, Hn, Hn);                   // 5
    dec_persist<<<NBLK, 512, RED_F*4>>>(cls1_b);                               // 6  <- ncu
    gemm_h16<<<dim3(25, 250), 256>>>((u16*)hid16,
        (u16*)c2_h, (u16*)c2_l, cls2_b, out, Vn, Hn);                          // 7
}

// round 12
// speedup vs baseline: 2.6235x; 1.0363x over previous
#include <cuda_runtime.h>
#include <cuda_fp16.h>
#include <math.h>
#include <stdint.h>

typedef unsigned short u16;
typedef unsigned int   u32;

#define Bn 32
#define Sn 100
#define Tn 100
#define En 512
#define Hn 1024
#define Vn 32000
#define Gn 4096
#define NBLK 128
#define RED_F (16*1056)
#define PB_OFF 8192    // MMA-partial region offset in red_ (floats)

// fp32 scratch
__device__ float g_XWenc[Bn*Sn*Gn];
__device__ float g_XWdec[Bn*Tn*Gn];
__device__ float g_enc_out[Bn*Sn*Hn];
__device__ float g_enc_proj[Bn*Sn*Hn];
__device__ float g_h[Bn*Hn];
__device__ float g_c[Bn*Hn];
__device__ float g_hdf[Bn*Hn];
__device__ float g_scores[Bn*Sn];
__device__ float g_zbias[1024];          // zero-initialized

// fp16 operands
__device__ u16 g_hid16[Bn*Tn*Hn];
__device__ u16 g_eo16 [Bn*Sn*Hn];
__device__ u16 g_EP2h [Bn*Sn*Hn];        // enc_out @ cls1_W[0:H]  (fp16)
__device__ u16 g_semb16[Bn*Sn*En];
__device__ u16 g_temb16[Bn*Tn*En];

// fragment-major fp16 state
__device__ uint4 g_ehf[2][4096];
__device__ uint4 g_dhf[2][4096];
__device__ uint4 g_fdf[2][4096];

// transposed [n][k] fp16 hi/lo weights (feed-forward GEMMs)
__device__ u16 w_ihE_h [(size_t)Gn*En],  w_ihE_l [(size_t)Gn*En];
__device__ u16 w_ihD0_h[(size_t)Gn*En],  w_ihD0_l[(size_t)Gn*En];
__device__ u16 w_att_h [(size_t)Hn*Hn],  w_att_l [(size_t)Hn*Hn];
__device__ u16 w_c1a_h [(size_t)Hn*Hn],  w_c1a_l [(size_t)Hn*Hn];
__device__ u16 w_c2_h  [(size_t)Vn*Hn],  w_c2_l  [(size_t)Vn*Hn];

// fragment-major fp16 weights: uint4 {b0h,b1h,b0l,b1l}
__device__ uint4 w_hhE_f [512*64*32];
__device__ uint4 w_ihDH_f[512*64*32];
__device__ uint4 w_hhD_f [512*64*32];
__device__ uint4 w_c1b_f [128*64*32];    // cls1_W rows H..2H

__device__ unsigned g_cnt, g_gen;
__device__ __forceinline__ void gbar() {
    __syncthreads();
    if (threadIdx.x == 0) {
        __threadfence();
        unsigned my = *((volatile unsigned*)&g_gen);
        unsigned a = atomicAdd(&g_cnt, 1u);
        if (a == NBLK - 1u) { g_cnt = 0u; __threadfence(); *((volatile unsigned*)&g_gen) = my + 1u; }
        else { while (*((volatile unsigned*)&g_gen) == my) {} }
        __threadfence();
    }
    __syncthreads();
}

__device__ __forceinline__ float sigm(float x){ return 1.0f/(1.0f + expf(-x)); }
__device__ __forceinline__ u16 fhi(float v){ return __half_as_ushort(__float2half_rn(v)); }
__device__ __forceinline__ u16 flo(float v){
    __half h = __float2half_rn(v);
    return __half_as_ushort(__float2half_rn(v - __half2float(h)));
}
__device__ __forceinline__ u32 pack2(u16 a, u16 b){ return (u32)a | ((u32)b << 16); }
__device__ __forceinline__ void mma16816h(float* c, const u32* a, u32 b0, u32 b1) {
    asm volatile("mma.sync.aligned.m16n8k16.row.col.f32.f16.f16.f32 "
        "{%0,%1,%2,%3},{%4,%5,%6,%7},{%8,%9},{%0,%1,%2,%3};"
        : "+f"(c[0]), "+f"(c[1]), "+f"(c[2]), "+f"(c[3])
        : "r"(a[0]), "r"(a[1]), "r"(a[2]), "r"(a[3]), "r"(b0), "r"(b1));
}
__device__ __forceinline__ void ldsm4(u32* r, u32 addr) {
    asm volatile("ldmatrix.sync.aligned.m8n8.x4.shared.b16 {%0,%1,%2,%3}, [%4];"
        : "=r"(r[0]), "=r"(r[1]), "=r"(r[2]), "=r"(r[3]) : "r"(addr));
}
__device__ __forceinline__ void frag_store16(u16* F, int row, int col, float v){
    int ch = col >> 4, kc = col & 15, mt = row >> 4, rg = row & 15;
    int lane = (rg & 7)*4 + ((kc >> 1) & 3);
    int w = ((kc >> 3) << 1) + (rg >> 3);
    size_t idx = ((size_t)(((ch*2 + mt)*32) + lane) << 3) + (w << 1) + (kc & 1);
    F[idx] = fhi(v);
}

// ---------- merged conversion / gather ----------
struct CJ { const float* W; void* Oh; void* Ol; int K, N, mode, boff; };
struct CJobs { CJ j[11]; };

__global__ void __launch_bounds__(256) conv_all(CJobs jb)
{
    __shared__ float tile[32][33];
    int blk = blockIdx.x, ji = 0;
    for (int i = 10; i >= 0; i--) if (blk >= jb.j[i].boff) { ji = i; break; }
    const CJ& J = jb.j[ji];
    int local = blk - J.boff;
    const int tid = threadIdx.x, lane = tid & 31;
    if (J.mode == 3) {
        int ntl = J.N >> 5;
        int tk = local / ntl, tn = local % ntl;
        int n0 = tn*32, k0 = tk*32;
        int tx = lane, ty = tid >> 5;
        #pragma unroll
        for (int i = 0; i < 4; i++)
            tile[ty + i*8][tx] = J.W[(size_t)(k0 + ty + i*8)*J.N + n0 + tx];
        __syncthreads();
        u16* Oh = (u16*)J.Oh; u16* Ol = (u16*)J.Ol;
        #pragma unroll
        for (int i = 0; i < 4; i++) {
            int nn = ty + i*8;
            float v = tile[tx][nn];
            Oh[(size_t)(n0+nn)*J.K + k0 + tx] = fhi(v);
            Ol[(size_t)(n0+nn)*J.K + k0 + tx] = flo(v);
        }
    } else if (J.mode == 1) {
        int nch = J.K >> 4;
        int pair = local*8 + (tid >> 5);
        int ng = pair / nch, c = pair % nch;
        int n = ng*8 + (lane >> 2), k = c*16 + (lane & 3)*2;
        const float* W = J.W;
        float v0 = W[(size_t)k*J.N + n],     v1 = W[(size_t)(k+1)*J.N + n];
        float v2 = W[(size_t)(k+8)*J.N + n], v3 = W[(size_t)(k+9)*J.N + n];
        ((uint4*)J.Oh)[(size_t)pair*32 + lane] =
            make_uint4(pack2(fhi(v0),fhi(v1)), pack2(fhi(v2),fhi(v3)),
                       pack2(flo(v0),flo(v1)), pack2(flo(v2),flo(v3)));
    } else {
        // mode 5: embedding gather -> fp16 rows (idx ptr passed in Ol)
        const int* idxp = (const int*)J.Ol;
        size_t base = (size_t)idxp[local] * J.K;
        u16* Oh = (u16*)J.Oh;
        for (int k = tid; k < J.K; k += 256)
            Oh[(size_t)local*J.K + k] = fhi(J.W[base + k]);
    }
}

// ---------- GEMM: C = A(fp16) @ B(fp16 hi/lo)^T + bias; fp32 and/or fp16 out ----------
__global__ void __launch_bounds__(256) gemm_h16(
    const u16* __restrict__ A,
    const u16* __restrict__ Bh, const u16* __restrict__ Bl,
    const float* __restrict__ bias, float* __restrict__ C, u16* __restrict__ C16,
    int N, int K)
{
    __shared__ __align__(16) u16 Ahs[2][128*24];
    __shared__ __align__(16) u16 Bhs[2][128*24], Bls[2][128*24];
    const int t = threadIdx.x, lane = t & 31, wid = t >> 5;
    const int wr = wid & 3, wc = wid >> 2;
    const int g = lane >> 2, tg = lane & 3;
    const int m0 = blockIdx.x * 128, n0 = blockIdx.y * 128;

    const int srow = t >> 1, sseg = (t & 1) * 8;
    const u16* Ap  = A  + (size_t)(m0 + srow) * K + sseg;
    const u16* Bph = Bh + (size_t)(n0 + srow) * K + sseg;
    const u16* Bpl = Bl + (size_t)(n0 + srow) * K + sseg;

    const int a_r = ((lane>>3)&1)*8 + (lane&7), a_c = (lane>>4)*8;
    const int b_r = (lane>>4)*8 + (lane&7),     b_c = ((lane>>3)&1)*8;
    u32 bAh[2], bBh[2], bBl[2];
    #pragma unroll
    for (int p = 0; p < 2; p++) {
        bAh[p] = (u32)__cvta_generic_to_shared(&Ahs[p][0]);
        bBh[p] = (u32)__cvta_generic_to_shared(&Bhs[p][0]);
        bBl[p] = (u32)__cvta_generic_to_shared(&Bls[p][0]);
    }

    float acc[2][8][4];
    #pragma unroll
    for (int i = 0; i < 2; i++)
        #pragma unroll
        for (int j = 0; j < 8; j++)
            #pragma unroll
            for (int q = 0; q < 4; q++) acc[i][j][q] = 0.0f;

    const int iters = K >> 4;
    uint4 aR = *(const uint4*)Ap;
    uint4 bhR = *(const uint4*)Bph, blR = *(const uint4*)Bpl;

    *(uint4*)&Ahs[0][srow*24 + sseg] = aR;
    *(uint4*)&Bhs[0][srow*24 + sseg] = bhR;
    *(uint4*)&Bls[0][srow*24 + sseg] = blR;
    __syncthreads();

    for (int kt = 0; kt < iters; kt++) {
        const int p = kt & 1;
        if (kt + 1 < iters) {
            aR  = *(const uint4*)(Ap + (kt+1)*16);
            bhR = *(const uint4*)(Bph + (kt+1)*16);
            blR = *(const uint4*)(Bpl + (kt+1)*16);
        }
        u32 ah[2][4];
        #pragma unroll
        for (int mt = 0; mt < 2; mt++) {
            u32 off = (u32)(((wr*32 + mt*16 + a_r)*24 + a_c) * 2);
            ldsm4(ah[mt], bAh[p] + off);
        }
        #pragma unroll
        for (int ntp = 0; ntp < 4; ntp++) {
            u32 off = (u32)(((wc*64 + ntp*16 + b_r)*24 + b_c) * 2);
            u32 bh4[4], bl4[4];
            ldsm4(bh4, bBh[p] + off);
            ldsm4(bl4, bBl[p] + off);
            #pragma unroll
            for (int e = 0; e < 2; e++) {
                int nt = ntp*2 + e;
                #pragma unroll
                for (int mt = 0; mt < 2; mt++) {
                    mma16816h(acc[mt][nt], ah[mt], bh4[e*2], bh4[e*2+1]);
                    mma16816h(acc[mt][nt], ah[mt], bl4[e*2], bl4[e*2+1]);
                }
            }
        }
        if (kt + 1 < iters) {
            const int q = p ^ 1;
            *(uint4*)&Ahs[q][srow*24 + sseg] = aR;
            *(uint4*)&Bhs[q][srow*24 + sseg] = bhR;
            *(uint4*)&Bls[q][srow*24 + sseg] = blR;
        }
        __syncthreads();
    }
    #pragma unroll
    for (int mt = 0; mt < 2; mt++)
        #pragma unroll
        for (int nt = 0; nt < 8; nt++) {
            int m = m0 + wr*32 + mt*16 + g;
            int n = n0 + wc*64 + nt*8 + tg*2;
            float b0v = bias[n], b1v = bias[n+1];
            float v00 = acc[mt][nt][0] + b0v, v01 = acc[mt][nt][1] + b1v;
            float v10 = acc[mt][nt][2] + b0v, v11 = acc[mt][nt][3] + b1v;
            if (C) {
                float* p2 = C + (size_t)m * N + n;
                *(float2*)p2 = make_float2(v00, v01);
                *(float2*)(p2 + (size_t)8*N) = make_float2(v10, v11);
            }
            if (C16) {
                u16* p3 = C16 + (size_t)m * N + n;
                *(u32*)p3 = pack2(fhi(v00), fhi(v01));
                *(u32*)(p3 + (size_t)8*N) = pack2(fhi(v10), fhi(v11));
            }
        }
}

// ---------- persistent encoder ----------
__global__ void __launch_bounds__(512) enc_persist()
{
    extern __shared__ float red_[];
    const int bk = blockIdx.x, tid = threadIdx.x, lane = tid & 31, wid = tid >> 5;
    const int g = lane >> 2, tg = lane & 3;

    { int i = bk*512 + tid;
      if (i < 16384) ((u32*)g_ehf[0])[i] = 0u; }
    float cst = 0.0f;
    gbar();

    for (int t = 0; t < Sn; t++) {
        const int rp = t & 1, wp2 = rp ^ 1;
        const uint4* Af = g_ehf[rp];

        float xg0, xg1, xg2, xg3;
        if (tid < 256) {
            const int bb = tid >> 3, jl = tid & 7;
            const size_t xw = ((size_t)(bb*Sn + t))*Gn + bk*8 + jl;
            xg0 = g_XWenc[xw]; xg1 = g_XWenc[xw+1024];
            xg2 = g_XWenc[xw+2048]; xg3 = g_XWenc[xw+3072];
        }

        float acc[2][4][4];
        #pragma unroll
        for (int a = 0; a < 2; a++)
            #pragma unroll
            for (int b = 0; b < 4; b++)
                #pragma unroll
                for (int q = 0; q < 4; q++) acc[a][b][q] = 0.0f;

        const int cb = wid*4;
        uint4 pf0 = Af[(cb*2)*32 + lane], pf1 = Af[(cb*2+1)*32 + lane];
        #pragma unroll
        for (int ks = 0; ks < 4; ks++) {
            const int c = cb + ks;
            uint4 f0 = pf0, f1 = pf1;
            if (ks < 3) {
                pf0 = Af[((c+1)*2)*32 + lane];
                pf1 = Af[((c+1)*2+1)*32 + lane];
            }
            #pragma unroll
            for (int nt = 0; nt < 4; nt++) {
                uint4 wq = w_hhE_f[((size_t)(nt*128 + bk)*64 + c)*32 + lane];
                mma16816h(acc[0][nt], (u32*)&f0, wq.x, wq.y);
                mma16816h(acc[0][nt], (u32*)&f0, wq.z, wq.w);
                mma16816h(acc[1][nt], (u32*)&f1, wq.x, wq.y);
                mma16816h(acc[1][nt], (u32*)&f1, wq.z, wq.w);
            }
        }
        float* rw0 = &red_[wid*1056];
        #pragma unroll
        for (int mt = 0; mt < 2; mt++)
            #pragma unroll
            for (int nt = 0; nt < 4; nt++) {
                int r0 = mt*16 + g, c0 = nt*8 + tg*2;
                rw0[r0*33 + c0]       = acc[mt][nt][0];
                rw0[r0*33 + c0 + 1]   = acc[mt][nt][1];
                rw0[(r0+8)*33 + c0]   = acc[mt][nt][2];
                rw0[(r0+8)*33 + c0+1] = acc[mt][nt][3];
            }
        __syncthreads();

        if (tid < 256) {
            const int bb = tid >> 3, jl = tid & 7, j = bk*8 + jl;
            float gi = xg0, gf = xg1, gg = xg2, go = xg3;
            #pragma unroll
            for (int w = 0; w < 16; w++) {
                const float* rw = &red_[w*1056 + bb*33];
                gi += rw[jl]; gf += rw[8+jl]; gg += rw[16+jl]; go += rw[24+jl];
            }
            cst = sigm(gf)*cst + sigm(gi)*tanhf(gg);
            float h = sigm(go)*tanhf(cst);
            const size_t eo = ((size_t)(bb*Sn + t))*Hn + j;
            g_enc_out[eo] = h;
            g_eo16[eo] = fhi(h);
            frag_store16((u16*)g_ehf[wp2], bb, j, h);
            if (t == Sn-1) { g_h[bb*Hn + j] = h; g_c[bb*Hn + j] = cst; }
        }
        gbar();
    }
}

// ---------- persistent decoder: 3 phases/step ----------
__global__ void __launch_bounds__(512) dec_persist(const float* __restrict__ cls1_b)
{
    extern __shared__ float red_[];
    const int bk = blockIdx.x, tid = threadIdx.x, lane = tid & 31, wid = tid >> 5;
    const int g = lane >> 2, tg = lane & 3;
    float* sc    = red_;
    float* wsm   = sc + 3200;
    float* stats = wsm + 3200;
    float* ctx   = stats + 64;

    { int i = bk*512 + tid;
      if (i < Bn*Hn) {
          float h0 = g_h[i];
          int row = i >> 10, col = i & 1023;
          frag_store16((u16*)g_dhf[0], row, col, h0);
          frag_store16((u16*)g_fdf[0], row, col, h0);
      } }
    float cst = (tid < 256) ? g_c[(tid>>3)*Hn + bk*8 + (tid&7)] : 0.0f;
    gbar();

    for (int t = 0; t < Tn; t++) {
        const int rp = t & 1, wp2 = rp ^ 1;

        // ---- P1: gates + LSTM cell ----
        {
            const uint4 *Af, *Wf;
            int cb;
            if (wid < 8) { Af = g_fdf[rp]; Wf = w_ihDH_f; cb = wid*8; }
            else         { Af = g_dhf[rp]; Wf = w_hhD_f;  cb = (wid-8)*8; }

            float xg0, xg1, xg2, xg3;
            if (tid < 256) {
                const int bb = tid >> 3, jl = tid & 7;
                const size_t xw = ((size_t)(bb*Tn + t))*Gn + bk*8 + jl;
                xg0 = g_XWdec[xw]; xg1 = g_XWdec[xw+1024];
                xg2 = g_XWdec[xw+2048]; xg3 = g_XWdec[xw+3072];
            }

            float acc[2][4][4];
            #pragma unroll
            for (int a = 0; a < 2; a++)
                #pragma unroll
                for (int b = 0; b < 4; b++)
                    #pragma unroll
                    for (int q = 0; q < 4; q++) acc[a][b][q] = 0.0f;

            uint4 pf0 = Af[(cb*2)*32 + lane], pf1 = Af[(cb*2+1)*32 + lane];
            #pragma unroll
            for (int ks = 0; ks < 8; ks++) {
                const int c = cb + ks;
                uint4 f0 = pf0, f1 = pf1;
                if (ks < 7) {
                    pf0 = Af[((c+1)*2)*32 + lane];
                    pf1 = Af[((c+1)*2+1)*32 + lane];
                }
                #pragma unroll
                for (int nt = 0; nt < 4; nt++) {
                    uint4 wq = Wf[((size_t)(nt*128 + bk)*64 + c)*32 + lane];
                    mma16816h(acc[0][nt], (u32*)&f0, wq.x, wq.y);
                    mma16816h(acc[0][nt], (u32*)&f0, wq.z, wq.w);
                    mma16816h(acc[1][nt], (u32*)&f1, wq.x, wq.y);
                    mma16816h(acc[1][nt], (u32*)&f1, wq.z, wq.w);
                }
            }
            float* rw0 = &red_[wid*1056];
            #pragma unroll
            for (int mt = 0; mt < 2; mt++)
                #pragma unroll
                for (int nt = 0; nt < 4; nt++) {
                    int r0 = mt*16 + g, c0 = nt*8 + tg*2;
                    rw0[r0*33 + c0]       = acc[mt][nt][0];
                    rw0[r0*33 + c0 + 1]   = acc[mt][nt][1];
                    rw0[(r0+8)*33 + c0]   = acc[mt][nt][2];
                    rw0[(r0+8)*33 + c0+1] = acc[mt][nt][3];
                }
            __syncthreads();
            if (tid < 256) {
                const int bb = tid >> 3, jl = tid & 7, j = bk*8 + jl;
                float gi = xg0, gf = xg1, gg = xg2, go = xg3;
                #pragma unroll
                for (int w = 0; w < 16; w++) {
                    const float* rw = &red_[w*1056 + bb*33];
                    gi += rw[jl]; gf += rw[8+jl]; gg += rw[16+jl]; go += rw[24+jl];
                }
                cst = sigm(gf)*cst + sigm(gi)*tanhf(gg);
                float h = sigm(go)*tanhf(cst);
                g_hdf[bb*Hn + j] = h;
                frag_store16((u16*)g_dhf[wp2], bb, j, h);
            }
        }
        gbar();

        // ---- P2: h@W1b partial MMA + attention scores ----
        {
            // (a) feed partial: hd @ cls1_W[H:2H]
            const uint4* Af = g_dhf[wp2];
            const int cb = wid*4;
            float fa[2][4];
            #pragma unroll
            for (int a = 0; a < 2; a++)
                #pragma unroll
                for (int q = 0; q < 4; q++) fa[a][q] = 0.0f;
            uint4 pf0 = Af[(cb*2)*32 + lane], pf1 = Af[(cb*2+1)*32 + lane];
            #pragma unroll
            for (int ks = 0; ks < 4; ks++) {
                const int c = cb + ks;
                uint4 f0 = pf0, f1 = pf1;
                if (ks < 3) {
                    pf0 = Af[((c+1)*2)*32 + lane];
                    pf1 = Af[((c+1)*2+1)*32 + lane];
                }
                uint4 wq = w_c1b_f[((size_t)bk*64 + c)*32 + lane];
                mma16816h(fa[0], (u32*)&f0, wq.x, wq.y);
                mma16816h(fa[0], (u32*)&f0, wq.z, wq.w);
                mma16816h(fa[1], (u32*)&f1, wq.x, wq.y);
                mma16816h(fa[1], (u32*)&f1, wq.z, wq.w);
            }
            float* pb = red_ + PB_OFF + wid*256;
            #pragma unroll
            for (int mt = 0; mt < 2; mt++) {
                int r0 = mt*16 + g;
                pb[r0*8 + tg*2]       = fa[mt][0];
                pb[r0*8 + tg*2 + 1]   = fa[mt][1];
                pb[(r0+8)*8 + tg*2]   = fa[mt][2];
                pb[(r0+8)*8 + tg*2+1] = fa[mt][3];
            }
            // (b) scores
            #pragma unroll
            for (int r = 0; r < 2; r++) {
                int pair = bk*16 + wid + r*2048;
                if (pair < Bn*Sn) {
                    int b = pair / Sn;
                    const float4* ep4 = (const float4*)(g_enc_proj + (size_t)pair * Hn);
                    const float4* hv4 = (const float4*)(g_hdf + b * Hn);
                    float a = 0.f;
                    #pragma unroll
                    for (int it = 0; it < 8; it++) {
                        float4 e = ep4[lane + 32*it];
                        float4 h = hv4[lane + 32*it];
                        a += e.x*h.x + e.y*h.y + e.z*h.z + e.w*h.w;
                    }
                    #pragma unroll
                    for (int o = 16; o; o >>= 1) a += __shfl_xor_sync(0xffffffffu, a, o);
                    if (lane == 0) g_scores[pair] = a;
                }
            }
        }
        gbar();

        // ---- P3: softmax + context-over-EP2 + feed ----
        for (int i = tid; i < Bn*Sn; i += 512) sc[i] = g_scores[i];
        __syncthreads();
        #pragma unroll
        for (int q = 0; q < 2; q++) {
            int b = wid*2 + q;
            float m = -1e30f;
            for (int s = lane; s < Sn; s += 32) m = fmaxf(m, sc[b*Sn + s]);
            #pragma unroll
            for (int o = 16; o; o >>= 1) m = fmaxf(m, __shfl_xor_sync(0xffffffffu, m, o));
            float su = 0.f;
            for (int s = lane; s < Sn; s += 32) su += expf(sc[b*Sn + s] - m);
            #pragma unroll
            for (int o = 16; o; o >>= 1) su += __shfl_xor_sync(0xffffffffu, su, o);
            if (lane == 0) { stats[b] = m; stats[32 + b] = 1.0f / su; }
        }
        __syncthreads();
        for (int i = tid; i < Bn*Sn; i += 512) {
            int b = i / Sn;
            wsm[i] = expf(sc[i] - stats[b]) * stats[32 + b];
        }
        __syncthreads();
        {
            const int half = tid >> 8, ct = tid & 255;
            const int bb = ct >> 3, jl = ct & 7, j = bk*8 + jl;
            const __half* e2 = (const __half*)(g_EP2h + ((size_t)(bb*Sn + half*50))*Hn + j);
            const float* wv = wsm + bb*Sn + half*50;
            float a = 0.f;
            #pragma unroll 10
            for (int s = 0; s < 50; s++) a += wv[s] * __half2float(e2[(size_t)s * Hn]);
            ctx[tid] = a;
        }
        __syncthreads();
        if (tid < 256) {
            const int bb = tid >> 3, jl = tid & 7, j = bk*8 + jl;
            float a = ctx[tid] + ctx[256 + tid] + cls1_b[j];
            #pragma unroll
            for (int w = 0; w < 16; w++) a += red_[PB_OFF + w*256 + bb*8 + jl];
            float f = tanhf(a);
            frag_store16((u16*)g_fdf[wp2], bb, j, f);
            g_hid16[((size_t)(bb*Tn + t))*Hn + j] = fhi(f);
        }
        gbar();
    }
}

extern "C" void kernel_launch(void* const* d_in, const int* in_sizes, int n_in,
                              void* d_out, int out_size)
{
    const int*   source_data = (const int*)  d_in[0];
    const int*   target_data = (const int*)  d_in[1];
    const float* src_emb  = (const float*)d_in[2];
    const float* tgt_emb  = (const float*)d_in[3];
    const float* enc_Wih  = (const float*)d_in[4];
    const float* enc_Whh  = (const float*)d_in[5];
    const float* enc_b    = (const float*)d_in[6];
    const float* dec_Wih  = (const float*)d_in[7];
    const float* dec_Whh  = (const float*)d_in[8];
    const float* dec_b    = (const float*)d_in[9];
    const float* att1_W   = (const float*)d_in[10];
    const float* att1_b   = (const float*)d_in[11];
    const float* cls1_W   = (const float*)d_in[12];
    const float* cls1_b   = (const float*)d_in[13];
    const float* cls2_W   = (const float*)d_in[14];
    const float* cls2_b   = (const float*)d_in[15];
    float* out = (float*)d_out;

    float *XWenc, *XWdec, *enc_proj, *zbias;
    void *ihE_h,*ihE_l,*ihD0_h,*ihD0_l,*att_h,*att_l,*c1a_h,*c1a_l,*c2_h,*c2_l;
    void *hhE_f,*ihDH_f,*hhD_f,*c1b_f;
    void *hid16,*eo16,*ep2h,*semb16,*temb16;
    cudaGetSymbolAddress((void**)&XWenc,   g_XWenc);
    cudaGetSymbolAddress((void**)&XWdec,   g_XWdec);
    cudaGetSymbolAddress((void**)&enc_proj,g_enc_proj);
    cudaGetSymbolAddress((void**)&zbias,   g_zbias);
    cudaGetSymbolAddress(&hid16,  g_hid16);  cudaGetSymbolAddress(&eo16, g_eo16);
    cudaGetSymbolAddress(&ep2h,   g_EP2h);
    cudaGetSymbolAddress(&semb16, g_semb16); cudaGetSymbolAddress(&temb16, g_temb16);
    cudaGetSymbolAddress(&ihE_h,  w_ihE_h);  cudaGetSymbolAddress(&ihE_l,  w_ihE_l);
    cudaGetSymbolAddress(&ihD0_h, w_ihD0_h); cudaGetSymbolAddress(&ihD0_l, w_ihD0_l);
    cudaGetSymbolAddress(&att_h,  w_att_h);  cudaGetSymbolAddress(&att_l,  w_att_l);
    cudaGetSymbolAddress(&c1a_h,  w_c1a_h);  cudaGetSymbolAddress(&c1a_l,  w_c1a_l);
    cudaGetSymbolAddress(&c2_h,   w_c2_h);   cudaGetSymbolAddress(&c2_l,   w_c2_l);
    cudaGetSymbolAddress(&hhE_f,  w_hhE_f);  cudaGetSymbolAddress(&ihDH_f, w_ihDH_f);
    cudaGetSymbolAddress(&hhD_f,  w_hhD_f);  cudaGetSymbolAddress(&c1b_f,  w_c1b_f);

    cudaFuncSetAttribute(enc_persist, cudaFuncAttributeMaxDynamicSharedMemorySize, RED_F*4);
    cudaFuncSetAttribute(dec_persist, cudaFuncAttributeMaxDynamicSharedMemorySize, RED_F*4);

    CJobs jb;
    jb.j[0]  = { enc_Wih,                     ihE_h,  ihE_l,   512, 4096, 3, 0     };
    jb.j[1]  = { dec_Wih,                     ihD0_h, ihD0_l,  512, 4096, 3, 2048  };
    jb.j[2]  = { att1_W,                      att_h,  att_l,  1024, 1024, 3, 4096  };
    jb.j[3]  = { cls2_W,                      c2_h,   c2_l,   1024, Vn,   3, 5120  };
    jb.j[4]  = { cls1_W,                      c1a_h,  c1a_l,  1024, 1024, 3, 37120 };
    jb.j[5]  = { enc_Whh,                     hhE_f,  nullptr,1024, 4096, 1, 38144 };
    jb.j[6]  = { dec_Wih + (size_t)512*4096,  ihDH_f, nullptr,1024, 4096, 1, 42240 };
    jb.j[7]  = { dec_Whh,                     hhD_f,  nullptr,1024, 4096, 1, 46336 };
    jb.j[8]  = { cls1_W + (size_t)1024*1024,  c1b_f,  nullptr,1024, 1024, 1, 50432 };
    jb.j[9]  = { src_emb, semb16, (void*)source_data,  512, 0, 5, 51456 };
    jb.j[10] = { tgt_emb, temb16, (void*)target_data,  512, 0, 5, 54656 };
    conv_all<<<57856, 256>>>(jb);                                              // 1

    gemm_h16<<<dim3(25, 32), 256>>>((u16*)semb16,
        (u16*)ihE_h, (u16*)ihE_l, enc_b, XWenc, nullptr, Gn, En);              // 2
    gemm_h16<<<dim3(25, 32), 256>>>((u16*)temb16,
        (u16*)ihD0_h, (u16*)ihD0_l, dec_b, XWdec, nullptr, Gn, En);            // 3
    enc_persist<<<NBLK, 512, RED_F*4>>>();                                     // 4
    gemm_h16<<<dim3(25, 8), 256>>>((u16*)eo16,
        (u16*)att_h, (u16*)att_l, att1_b, enc_proj, nullptr, Hn, Hn);          // 5
    gemm_h16<<<dim3(25, 8), 256>>>((u16*)eo16,
        (u16*)c1a_h, (u16*)c1a_l, zbias, nullptr, (u16*)ep2h, Hn, Hn);         // 6
    dec_persist<<<NBLK, 512, RED_F*4>>>(cls1_b);                               // 7
    gemm_h16<<<dim3(25, 250), 256>>>((u16*)hid16,
        (u16*)c2_h, (u16*)c2_l, cls2_b, out, nullptr, Vn, Hn);                 // 8
}